// round 10
// baseline (speedup 1.0000x reference)
#include <cuda_runtime.h>
#include <cuda_fp16.h>
#include <cstdint>
#include <cstdio>
#include <cstring>
#include <cmath>
#include <dlfcn.h>

#define IN_F   4096
#define OUT_F  4096
#define M_ROWS 8192

// Host-module fp16 scratch (used by the fallback path).
__device__ __half g_Xh[(size_t)M_ROWS * IN_F];
__device__ __half g_Wh[(size_t)OUT_F * IN_F];

__constant__ float NF4[16] = {
    -1.0f, -0.6961928009986877f, -0.5250730514526367f, -0.39491748809814453f,
    -0.28444138169288635f, -0.18477343022823334f, -0.09105003625154495f, 0.0f,
    0.07958029955625534f, 0.16093020141124725f, 0.24611230194568634f,
    0.33791524171829224f, 0.4407098889350891f, 0.5626170039176941f,
    0.7229568362236023f, 1.0f
};

static const float NF4H[16] = {
    -1.0f, -0.6961928009986877f, -0.5250730514526367f, -0.39491748809814453f,
    -0.28444138169288635f, -0.18477343022823334f, -0.09105003625154495f, 0.0f,
    0.07958029955625534f, 0.16093020141124725f, 0.24611230194568634f,
    0.33791524171829224f, 0.4407098889350891f, 0.5626170039176941f,
    0.7229568362236023f, 1.0f
};

__device__ __forceinline__ uint32_t smem_u32(const void* p) {
    uint32_t a;
    asm("{ .reg .u64 t; cvta.to.shared.u64 t, %1; cvt.u32.u64 %0, t; }" : "=r"(a) : "l"(p));
    return a;
}

// ---------------------------------------------------------------------------
// Kernel A: convert x (fp32) -> dst (fp16). 8 elems/thread.
// ---------------------------------------------------------------------------
__global__ void convert_x_kernel(const float* __restrict__ x, __half* __restrict__ dst) {
    size_t i = ((size_t)blockIdx.x * 256 + threadIdx.x) * 8;
    float4 v0 = *(const float4*)(x + i);
    float4 v1 = *(const float4*)(x + i + 4);
    __half2 h0 = __floats2half2_rn(v0.x, v0.y);
    __half2 h1 = __floats2half2_rn(v0.z, v0.w);
    __half2 h2 = __floats2half2_rn(v1.x, v1.y);
    __half2 h3 = __floats2half2_rn(v1.z, v1.w);
    uint4 o;
    o.x = *(uint32_t*)&h0; o.y = *(uint32_t*)&h1;
    o.z = *(uint32_t*)&h2; o.w = *(uint32_t*)&h3;
    *(uint4*)&dst[i] = o;
}

// lora_B [4096][64] fp32 -> fp16 same layout
__global__ void cvt_lb_kernel(const float* __restrict__ lB, __half* __restrict__ lb) {
    size_t i = ((size_t)blockIdx.x * 256 + threadIdx.x) * 4;
    float4 v = *(const float4*)(lB + i);
    __half h[4] = {__float2half_rn(v.x), __float2half_rn(v.y),
                   __float2half_rn(v.z), __float2half_rn(v.w)};
    *(uint2*)&lb[i] = *(uint2*)h;
}

// lora_A [64][4096] fp32 -> lat [4096][64] fp16 (transpose)
__global__ void cvt_lat_kernel(const float* __restrict__ lA, __half* __restrict__ lat) {
    __shared__ float s[64][65];
    const int tid = threadIdx.x;
    const int i0 = blockIdx.x * 64;
    for (int idx = tid; idx < 4096; idx += 256) {
        int r = idx >> 6, ii = idx & 63;
        s[r][ii] = lA[r * IN_F + i0 + ii];
    }
    __syncthreads();
    int ii = tid >> 2, rs = (tid & 3) * 16;
    __half h[16];
#pragma unroll
    for (int j = 0; j < 16; j++) h[j] = __float2half_rn(s[rs + j][ii]);
    uint4* dst = (uint4*)&lat[(size_t)(i0 + ii) * 64 + rs];
    dst[0] = *(uint4*)&h[0];
    dst[1] = *(uint4*)&h[8];
}

// ---------------------------------------------------------------------------
// Host fallback: W_eff = NF4 dequant * absmax + lora_B @ lora_A  (fp16 out)
// ---------------------------------------------------------------------------
__global__ void build_weff_kernel(const int* __restrict__ qweight,
                                  const float* __restrict__ absmax,
                                  const float* __restrict__ lA,
                                  const float* __restrict__ lB,
                                  __half* __restrict__ dst) {
    __shared__ float Bsh[64][64];
    __shared__ float Ash[64][128];

    const int tid = threadIdx.x;
    const int o0 = blockIdx.y * 64;
    const int i0 = blockIdx.x * 128;

    for (int t = tid; t < 64 * 64; t += 256) {
        int o = t >> 6, r = t & 63;
        Bsh[r][o] = lB[(o0 + o) * 64 + r];
    }
    for (int t = tid; t < 64 * 128; t += 256) {
        int r = t >> 7, c = t & 127;
        Ash[r][c] = lA[r * IN_F + i0 + c];
    }
    __syncthreads();

    const int oo0 = (tid >> 4) * 4;
    const int ii0 = (tid & 15) * 8;

    float acc[4][8];
#pragma unroll
    for (int a = 0; a < 4; a++)
#pragma unroll
        for (int b = 0; b < 8; b++) acc[a][b] = 0.0f;

#pragma unroll 4
    for (int r = 0; r < 64; r++) {
        float4 a0 = *(const float4*)&Ash[r][ii0];
        float4 a1 = *(const float4*)&Ash[r][ii0 + 4];
#pragma unroll
        for (int oo = 0; oo < 4; oo++) {
            float bv = Bsh[r][oo0 + oo];
            acc[oo][0] += bv * a0.x; acc[oo][1] += bv * a0.y;
            acc[oo][2] += bv * a0.z; acc[oo][3] += bv * a0.w;
            acc[oo][4] += bv * a1.x; acc[oo][5] += bv * a1.y;
            acc[oo][6] += bv * a1.z; acc[oo][7] += bv * a1.w;
        }
    }

#pragma unroll
    for (int oo = 0; oo < 4; oo++) {
        const int o = o0 + oo0 + oo;
        const size_t k = (size_t)o * IN_F + i0 + ii0;
        const int4 qv = ((const int4*)qweight)[k >> 3];
        const float am = absmax[k >> 6];

        float w[8];
        w[0] = NF4[qv.x & 15];  w[1] = NF4[(qv.x >> 4) & 15];
        w[2] = NF4[qv.y & 15];  w[3] = NF4[(qv.y >> 4) & 15];
        w[4] = NF4[qv.z & 15];  w[5] = NF4[(qv.z >> 4) & 15];
        w[6] = NF4[qv.w & 15];  w[7] = NF4[(qv.w >> 4) & 15];

        __half2 h0 = __floats2half2_rn(w[0] * am + acc[oo][0], w[1] * am + acc[oo][1]);
        __half2 h1 = __floats2half2_rn(w[2] * am + acc[oo][2], w[3] * am + acc[oo][3]);
        __half2 h2 = __floats2half2_rn(w[4] * am + acc[oo][4], w[5] * am + acc[oo][5]);
        __half2 h3 = __floats2half2_rn(w[6] * am + acc[oo][6], w[7] * am + acc[oo][7]);
        uint4 pk;
        pk.x = *(uint32_t*)&h0; pk.y = *(uint32_t*)&h1;
        pk.z = *(uint32_t*)&h2; pk.w = *(uint32_t*)&h3;
        *(uint4*)&dst[k] = pk;
    }
}

// ---------------------------------------------------------------------------
// Fallback GEMM (proven 778us): fp16 mma.sync, 512 thr, 4-stage.
// ---------------------------------------------------------------------------
constexpr int BM = 128, BN = 256, BK = 64, S = 4;
constexpr int NT = IN_F / BK;
constexpr int A_BYTES = BM * 128;
constexpr int B_BYTES = BN * 128;
constexpr int STAGE = A_BYTES + B_BYTES;
constexpr int SMEM_TOTAL = 1024 + S * STAGE;
constexpr int TOTAL_TILES = (M_ROWS / BM) * (OUT_F / BN);

__device__ __forceinline__ void mma_f16(float c[4], const uint32_t a[4],
                                        uint32_t b0, uint32_t b1) {
    asm volatile(
        "mma.sync.aligned.m16n8k16.row.col.f32.f16.f16.f32 "
        "{%0,%1,%2,%3}, {%4,%5,%6,%7}, {%8,%9}, {%0,%1,%2,%3};"
        : "+f"(c[0]), "+f"(c[1]), "+f"(c[2]), "+f"(c[3])
        : "r"(a[0]), "r"(a[1]), "r"(a[2]), "r"(a[3]), "r"(b0), "r"(b1));
}

__device__ __forceinline__ void ldsm4(uint32_t& r0, uint32_t& r1,
                                      uint32_t& r2, uint32_t& r3, uint32_t addr) {
    asm volatile("ldmatrix.sync.aligned.m8n8.x4.shared.b16 {%0,%1,%2,%3}, [%4];"
                 : "=r"(r0), "=r"(r1), "=r"(r2), "=r"(r3) : "r"(addr));
}

__device__ __forceinline__ void st_cs_f2(float* p, float a, float b) {
    asm volatile("st.global.cs.v2.f32 [%0], {%1,%2};" :: "l"(p), "f"(a), "f"(b)
                 : "memory");
}

__device__ __forceinline__ void issue_stage(uint32_t sA, uint32_t sB,
                                            const __half* xb, const __half* wb,
                                            int tid) {
#pragma unroll
    for (int r = 0; r < 2; r++) {
        int i = tid + r * 512;
        int row = i >> 3, c = i & 7;
        uint32_t off = (uint32_t)(row * 128 + ((c * 16) ^ ((row & 7) << 4)));
        const __half* src = xb + (size_t)row * IN_F + c * 8;
        asm volatile("cp.async.cg.shared.global.L2::256B [%0], [%1], 16;\n"
                     :: "r"(sA + off), "l"(src));
    }
#pragma unroll
    for (int r = 0; r < 4; r++) {
        int i = tid + r * 512;
        int row = i >> 3, c = i & 7;
        uint32_t off = (uint32_t)(row * 128 + ((c * 16) ^ ((row & 7) << 4)));
        const __half* src = wb + (size_t)row * IN_F + c * 8;
        asm volatile("cp.async.cg.shared.global.L2::256B [%0], [%1], 16;\n"
                     :: "r"(sB + off), "l"(src));
    }
}

__global__ void __launch_bounds__(512, 1)
gemm_f16_kernel(const __half* __restrict__ Xh, const __half* __restrict__ Wh,
                float* __restrict__ out) {
    extern __shared__ char sm[];
    const uint32_t stage0 = (smem_u32(sm) + 1023) & ~1023u;

    const int tid = threadIdx.x;
    const int wid = tid >> 5;
    const int lane = tid & 31;
    const int warp_m = wid & 3;
    const int warp_n = wid >> 2;
    const int g = lane >> 3;
    const int r = lane & 7;

    uint32_t a_rowoff[2], a_xr[2];
    const uint32_t a_kc = (uint32_t)((g >> 1) * 16);
#pragma unroll
    for (int mf = 0; mf < 2; mf++) {
        int row = warp_m * 32 + mf * 16 + (g & 1) * 8 + r;
        a_rowoff[mf] = row * 128;
        a_xr[mf] = (row & 7) << 4;
    }
    uint32_t b_rowoff[4], b_xr[4];
    const uint32_t b_kc = (uint32_t)((g & 1) * 16);
#pragma unroll
    for (int p = 0; p < 4; p++) {
        int row = warp_n * 64 + p * 16 + (g >> 1) * 8 + r;
        b_rowoff[p] = row * 128;
        b_xr[p] = (row & 7) << 4;
    }

    for (int t = blockIdx.x; t < TOTAL_TILES; t += gridDim.x) {
        const int mBase = (t >> 4) * BM;
        const int nBase = (t & 15) * BN;
        const __half* xt = Xh + (size_t)mBase * IN_F;
        const __half* wt = Wh + (size_t)nBase * IN_F;

        float acc[2][8][4];
#pragma unroll
        for (int i = 0; i < 2; i++)
#pragma unroll
            for (int j = 0; j < 8; j++)
#pragma unroll
                for (int l = 0; l < 4; l++) acc[i][j][l] = 0.0f;

#pragma unroll
        for (int p = 0; p < S - 1; p++) {
            uint32_t sA = stage0 + p * STAGE;
            issue_stage(sA, sA + A_BYTES, xt + p * BK, wt + p * BK, tid);
            asm volatile("cp.async.commit_group;\n" ::: "memory");
        }

        for (int kt = 0; kt < NT; kt++) {
            asm volatile("cp.async.wait_group %0;\n" :: "n"(S - 2) : "memory");
            __syncthreads();

            if (kt + S - 1 < NT) {
                const int s2 = (kt + S - 1) % S;
                uint32_t sA = stage0 + s2 * STAGE;
                issue_stage(sA, sA + A_BYTES,
                            xt + (kt + S - 1) * BK, wt + (kt + S - 1) * BK, tid);
            }
            asm volatile("cp.async.commit_group;\n" ::: "memory");

            const uint32_t sA = stage0 + (kt % S) * STAGE;
            const uint32_t sB = sA + A_BYTES;

#pragma unroll
            for (int q = 0; q < 4; q++) {
                uint32_t a[2][4];
#pragma unroll
                for (int mf = 0; mf < 2; mf++)
                    ldsm4(a[mf][0], a[mf][1], a[mf][2], a[mf][3],
                          sA + a_rowoff[mf] + (((q * 32) + a_kc) ^ a_xr[mf]));
                uint32_t b[8][2];
#pragma unroll
                for (int p = 0; p < 4; p++)
                    ldsm4(b[2 * p][0], b[2 * p][1], b[2 * p + 1][0], b[2 * p + 1][1],
                          sB + b_rowoff[p] + (((q * 32) + b_kc) ^ b_xr[p]));
#pragma unroll
                for (int mf = 0; mf < 2; mf++)
#pragma unroll
                    for (int nf = 0; nf < 8; nf++)
                        mma_f16(acc[mf][nf], a[mf], b[nf][0], b[nf][1]);
            }
        }
        asm volatile("cp.async.wait_group 0;\n" ::: "memory");

#pragma unroll
        for (int mf = 0; mf < 2; mf++) {
#pragma unroll
            for (int nf = 0; nf < 8; nf++) {
                const int row = mBase + warp_m * 32 + mf * 16 + (lane >> 2);
                const int col = nBase + warp_n * 64 + nf * 8 + (lane & 3) * 2;
                st_cs_f2(&out[(size_t)row * OUT_F + col],
                         acc[mf][nf][0], acc[mf][nf][1]);
                st_cs_f2(&out[(size_t)(row + 8) * OUT_F + col],
                         acc[mf][nf][2], acc[mf][nf][3]);
            }
        }
        __syncthreads();
    }
}

// ===========================================================================
// NVRTC tcgen05 module: gemm5 (backstop), gemm5c (proven), gemm5d (TMA),
// wbuild, init kernels.
// ===========================================================================
static const char* NVRTC_SRC = R"NVSRC(
typedef unsigned int u32;
typedef unsigned long long u64;
typedef unsigned short u16;

__device__ u16 GX[33554432];     // 8192*4096 fp16
__device__ u16 GW[16777216];     // 4096*4096 fp16
__device__ float GOUT[33554432]; // gemm self-test output
__device__ u16 GLB[262144];      // lora_B fp16 [4096][64]
__device__ u16 GLAT[262144];     // lora_A^T fp16 [4096][64]
__device__ int GTQW[8388608];    // wbuild self-test qweight
__device__ float GTAM[262144];   // wbuild self-test absmax
__device__ __align__(128) unsigned char TMXD[128];  // tensormap for GX
__device__ __align__(128) unsigned char TMWD[128];  // tensormap for GW

__constant__ float NF4D[16] = {
    -1.0f, -0.6961928009986877f, -0.5250730514526367f, -0.39491748809814453f,
    -0.28444138169288635f, -0.18477343022823334f, -0.09105003625154495f, 0.0f,
    0.07958029955625534f, 0.16093020141124725f, 0.24611230194568634f,
    0.33791524171829224f, 0.4407098889350891f, 0.5626170039176941f,
    0.7229568362236023f, 1.0f
};

#define MWAIT(ba, ph) do { u32 _d; \
    asm volatile("{ .reg .pred p; mbarrier.try_wait.parity.acquire.cta.shared::cta.b64 p, [%1], %2; selp.b32 %0,1,0,p; }" \
                 : "=r"(_d) : "r"(ba), "r"(ph) : "memory"); \
    if (!_d) { \
        asm volatile("{ .reg .pred P1; WL%=: mbarrier.try_wait.parity.acquire.cta.shared::cta.b64 P1, [%0], %1, 0x989680; @P1 bra.uni WD%=; bra.uni WL%=; WD%=: }" \
                     :: "r"(ba), "r"(ph) : "memory"); } } while(0)

#define LDTM32(rr, addr) \
    asm volatile("tcgen05.ld.sync.aligned.32x32b.x32.b32 " \
        "{%0,%1,%2,%3,%4,%5,%6,%7,%8,%9,%10,%11,%12,%13,%14,%15," \
        "%16,%17,%18,%19,%20,%21,%22,%23,%24,%25,%26,%27,%28,%29,%30,%31}, [%32];" \
        : "=r"(rr[0]), "=r"(rr[1]), "=r"(rr[2]), "=r"(rr[3]), \
          "=r"(rr[4]), "=r"(rr[5]), "=r"(rr[6]), "=r"(rr[7]), \
          "=r"(rr[8]), "=r"(rr[9]), "=r"(rr[10]), "=r"(rr[11]), \
          "=r"(rr[12]), "=r"(rr[13]), "=r"(rr[14]), "=r"(rr[15]), \
          "=r"(rr[16]), "=r"(rr[17]), "=r"(rr[18]), "=r"(rr[19]), \
          "=r"(rr[20]), "=r"(rr[21]), "=r"(rr[22]), "=r"(rr[23]), \
          "=r"(rr[24]), "=r"(rr[25]), "=r"(rr[26]), "=r"(rr[27]), \
          "=r"(rr[28]), "=r"(rr[29]), "=r"(rr[30]), "=r"(rr[31]) \
        : "r"(addr))

#define TMA2D(dst, tmap, cx, cy, mbar) \
    asm volatile("cp.async.bulk.tensor.2d.shared::cta.global.tile.mbarrier::complete_tx::bytes " \
                 "[%0], [%1, {%2, %3}], [%4];" \
                 :: "r"(dst), "l"(tmap), "r"(cx), "r"(cy), "r"(mbar) : "memory")

#define EXPECT_TX(mbar, n) \
    asm volatile("mbarrier.arrive.expect_tx.shared.b64 _, [%0], %1;" \
                 :: "r"(mbar), "r"(n) : "memory")

__device__ __forceinline__ u32 sm2u32(const void* p) {
    u32 a;
    asm("{ .reg .u64 t; cvta.to.shared.u64 t, %1; cvt.u32.u64 %0, t; }" : "=r"(a) : "l"(p));
    return a;
}

extern "C" __global__ void initt() {
    u64 i = (u64)blockIdx.x * 256 + threadIdx.x;
    const u16 T[9] = {0xBC00,0xBA00,0xB800,0xB400,0,0x3400,0x3800,0x3A00,0x3C00};
    if (i < 33554432ull) {
        u32 m = (u32)(i >> 12), k = (u32)(i & 4095);
        GX[i] = T[(k*131u + m*7u) % 9u];
    }
    if (i < 16777216ull) {
        u32 n = (u32)(i >> 12), k = (u32)(i & 4095);
        GW[i] = T[(k*17u + n*3u) % 7u + 1u];
    }
}

extern "C" __global__ void wtinit() {
    u64 i = (u64)blockIdx.x * 256 + threadIdx.x;
    if (i < 8388608ull) GTQW[i] = (int)((i * 37ull) & 255ull);
    if (i < 262144ull) {
        GTAM[i] = (float)((u32)(i * 13ull) % 31u + 1u) * 0.03125f;
        u32 o = (u32)(i >> 6), r = (u32)(i & 63);
        float lb = (float)((int)((o*3u + r*7u) % 17u) - 8) * 0.015625f;
        float la = (float)((int)((o*5u + r*11u) % 19u) - 9) * 0.015625f;
        u16 hb, ha;
        asm("cvt.rn.f16.f32 %0, %1;" : "=h"(hb) : "f"(lb));
        asm("cvt.rn.f16.f32 %0, %1;" : "=h"(ha) : "f"(la));
        GLB[i] = hb;
        GLAT[i] = ha;
    }
}

__device__ __forceinline__ void ld_sub(u32 dst, const char* src, int tid, int iters) {
#pragma unroll
    for (int r = 0; r < 8; r++) {
        if (r >= iters) break;
        int i = tid + r * 256; int row = i >> 3, c = i & 7;
        u32 off = (u32)(row * 128 + ((c * 16) ^ ((row & 7) << 4)));
        asm volatile("cp.async.cg.shared.global.L2::256B [%0], [%1], 16;"
                     :: "r"(dst + off), "l"(src + (u64)row * 8192 + c * 16));
    }
}

// ---------------- gemm5 (R7 proven, single M-tile, backstop) ----------------
__device__ __forceinline__ void ld_stage(u32 sA, u32 sB, const char* xb,
                                         const char* wb, int tid) {
#pragma unroll
    for (int r = 0; r < 4; r++) {
        int i = tid + r * 256; int row = i >> 3, c = i & 7;
        u32 off = (u32)(row * 128 + ((c * 16) ^ ((row & 7) << 4)));
        asm volatile("cp.async.cg.shared.global.L2::256B [%0], [%1], 16;"
                     :: "r"(sA + off), "l"(xb + (u64)row * 8192 + c * 16));
    }
#pragma unroll
    for (int r = 0; r < 8; r++) {
        int i = tid + r * 256; int row = i >> 3, c = i & 7;
        u32 off = (u32)(row * 128 + ((c * 16) ^ ((row & 7) << 4)));
        asm volatile("cp.async.cg.shared.global.L2::256B [%0], [%1], 16;"
                     :: "r"(sB + off), "l"(wb + (u64)row * 8192 + c * 16));
    }
}

extern "C" __global__ void __launch_bounds__(256, 1)
gemm5(const char* __restrict__ X, const char* __restrict__ W,
      float* __restrict__ out) {
    extern __shared__ char sm[];
    u32 base = (sm2u32(sm) + 1023) & ~1023u;
    const u32 tptr = base;
    const u32 mb = base + 16;
    const u32 st0 = base + 1024;
    const int tid = threadIdx.x, wid = tid >> 5, lid = tid & 31;

    if (wid == 0)
        asm volatile("tcgen05.alloc.cta_group::1.sync.aligned.shared::cta.b32 [%0], %1;"
                     :: "r"(tptr), "r"(256u) : "memory");
    if (tid == 0) {
#pragma unroll
        for (int s = 0; s < 4; s++)
            asm volatile("mbarrier.init.shared.b64 [%0], %1;"
                         :: "r"(mb + s * 8), "r"(1u) : "memory");
    }
    __syncthreads();
    u32 tmem; asm volatile("ld.shared.b32 %0,[%1];" : "=r"(tmem) : "r"(tptr));

    const u64 DBASE = (2ull << 61) | (1ull << 46) | (64ull << 32) | (1ull << 16);
    const u32 IDESC = (1u << 4) | (32u << 17) | (8u << 24);

#pragma unroll 1
    for (int t = blockIdx.x; t < 1024; t += gridDim.x) {
        const int mBase = (t >> 4) * 128, nBase = (t & 15) * 256;
        const char* xt = X + (u64)mBase * 8192;
        const char* wt = W + (u64)nBase * 8192;

#pragma unroll
        for (int p = 0; p < 4; p++) {
            u32 sA = st0 + p * 49152;
            ld_stage(sA, sA + 16384, xt + p * 128, wt + p * 128, tid);
            asm volatile("cp.async.commit_group;" ::: "memory");
        }

#pragma unroll 1
        for (int kt = 0; kt < 64; kt++) {
            const int s = kt & 3;
            const u32 sA = st0 + s * 49152, sB = sA + 16384;
            asm volatile("cp.async.wait_group 3;" ::: "memory");
            __syncthreads();

            if (wid == 0) {
                u32 ep;
                asm volatile("{ .reg .pred p; elect.sync _|p, 0xFFFFFFFF; selp.b32 %0,1,0,p; }"
                             : "=r"(ep));
                if (ep) {
                    asm volatile("fence.proxy.async.shared::cta;" ::: "memory");
                    u64 ad = DBASE | ((u64)(sA >> 4) & 0x3FFF);
                    u64 bd = DBASE | ((u64)(sB >> 4) & 0x3FFF);
#pragma unroll
                    for (int q = 0; q < 4; q++) {
                        u32 en = (kt > 0 || q > 0) ? 1u : 0u;
                        asm volatile("{ .reg .pred p; setp.ne.u32 p, %5, 0; "
                            "tcgen05.mma.cta_group::1.kind::f16 [%0], %1, %2, %3, {%4,%4,%4,%4}, p; }"
                            :: "r"(tmem), "l"(ad + q * 2), "l"(bd + q * 2),
                               "r"(IDESC), "r"(0u), "r"(en) : "memory");
                    }
                    asm volatile("tcgen05.commit.cta_group::1.mbarrier::arrive::one.shared::cluster.b64 [%0];"
                                 :: "r"(mb + s * 8) : "memory");
                }
            }

            if (kt + 4 < 64) {
                u32 ph = (u32)((kt >> 2) & 1);
                MWAIT(mb + s * 8, ph);
                ld_stage(sA, sB, xt + (kt + 4) * 128, wt + (kt + 4) * 128, tid);
            }
            asm volatile("cp.async.commit_group;" ::: "memory");
        }

        MWAIT(mb + 24, 1u);
        asm volatile("tcgen05.fence::after_thread_sync;" ::: "memory");

        if (wid < 4) {
            float* dst = out + (u64)(mBase + wid * 32 + lid) * 4096 + nBase;
#pragma unroll
            for (int ch = 0; ch < 8; ch++) {
                u32 rr[32];
                LDTM32(rr, tmem + ch * 32);
                asm volatile("tcgen05.wait::ld.sync.aligned;" ::: "memory");
#pragma unroll
                for (int j = 0; j < 8; j++)
                    asm volatile("st.global.cs.v4.b32 [%0], {%1,%2,%3,%4};"
                                 :: "l"(dst + ch * 32 + j * 4),
                                    "r"(rr[4 * j]), "r"(rr[4 * j + 1]),
                                    "r"(rr[4 * j + 2]), "r"(rr[4 * j + 3]) : "memory");
            }
            asm volatile("tcgen05.fence::before_thread_sync;" ::: "memory");
        }
        __syncthreads();
    }

    __syncthreads();
    if (wid == 0) {
        asm volatile("tcgen05.relinquish_alloc_permit.cta_group::1.sync.aligned;");
        asm volatile("tcgen05.dealloc.cta_group::1.sync.aligned.b32 %0, %1;"
                     :: "r"(tmem), "r"(256u));
    }
}

// ---------------- gemm5c: 2 M-tiles, decoupled cp.async pipeline ----------------
extern "C" __global__ void __launch_bounds__(256, 1)
gemm5c(const char* __restrict__ X, const char* __restrict__ W,
       float* __restrict__ out) {
    extern __shared__ char sm[];
    u32 base = (sm2u32(sm) + 1023) & ~1023u;
    const u32 tptr = base;
    const u32 mb = base + 16;
    const u32 st0 = base + 1024;
    const int tid = threadIdx.x, wid = tid >> 5, lid = tid & 31;

    if (wid == 0)
        asm volatile("tcgen05.alloc.cta_group::1.sync.aligned.shared::cta.b32 [%0], %1;"
                     :: "r"(tptr), "r"(512u) : "memory");
    if (tid == 0) {
#pragma unroll
        for (int s = 0; s < 3; s++)
            asm volatile("mbarrier.init.shared.b64 [%0], %1;"
                         :: "r"(mb + s * 8), "r"(1u) : "memory");
    }
    __syncthreads();
    u32 tmem; asm volatile("ld.shared.b32 %0,[%1];" : "=r"(tmem) : "r"(tptr));

    const u64 DBASE = (2ull << 61) | (1ull << 46) | (64ull << 32) | (1ull << 16);
    const u32 IDESC = (1u << 4) | (32u << 17) | (8u << 24);

    int bp1 = 0, bp2 = 0;

#pragma unroll 1
    for (int t = blockIdx.x; t < 512; t += gridDim.x) {
        const int mBase = (t >> 4) * 256, nBase = (t & 15) * 256;
        const char* x0 = X + (u64)mBase * 8192;
        const char* x1 = x0 + 1048576;
        const char* wt = W + (u64)nBase * 8192;

#pragma unroll
        for (int p = 0; p < 2; p++) {
            u32 sA0 = st0 + p * 65536;
            ld_sub(sA0,         x0 + p * 128, tid, 4);
            ld_sub(sA0 + 16384, x1 + p * 128, tid, 4);
            ld_sub(sA0 + 32768, wt + p * 128, tid, 8);
            asm volatile("cp.async.commit_group;" ::: "memory");
        }

#pragma unroll 1
        for (int kt = 0; kt < 64; kt++) {
            const int kdiv = kt / 3;
            const int s = kt - kdiv * 3;
            const u32 sA0 = st0 + s * 65536, sA1 = sA0 + 16384, sB = sA0 + 32768;
            asm volatile("cp.async.wait_group 1;" ::: "memory");
            __syncthreads();

            if (wid == 0) {
                u32 ep;
                asm volatile("{ .reg .pred p; elect.sync _|p, 0xFFFFFFFF; selp.b32 %0,1,0,p; }"
                             : "=r"(ep));
                if (ep) {
                    asm volatile("fence.proxy.async.shared::cta;" ::: "memory");
                    u64 a0 = DBASE | ((u64)(sA0 >> 4) & 0x3FFF);
                    u64 a1 = DBASE | ((u64)(sA1 >> 4) & 0x3FFF);
                    u64 bd = DBASE | ((u64)(sB >> 4) & 0x3FFF);
#pragma unroll
                    for (int q = 0; q < 4; q++) {
                        u32 en = (kt > 0 || q > 0) ? 1u : 0u;
                        asm volatile("{ .reg .pred p; setp.ne.u32 p, %5, 0; "
                            "tcgen05.mma.cta_group::1.kind::f16 [%0], %1, %2, %3, {%4,%4,%4,%4}, p; }"
                            :: "r"(tmem), "l"(a0 + q * 2), "l"(bd + q * 2),
                               "r"(IDESC), "r"(0u), "r"(en) : "memory");
                        asm volatile("{ .reg .pred p; setp.ne.u32 p, %5, 0; "
                            "tcgen05.mma.cta_group::1.kind::f16 [%0], %1, %2, %3, {%4,%4,%4,%4}, p; }"
                            :: "r"(tmem + 256), "l"(a1 + q * 2), "l"(bd + q * 2),
                               "r"(IDESC), "r"(0u), "r"(en) : "memory");
                    }
                    asm volatile("tcgen05.commit.cta_group::1.mbarrier::arrive::one.shared::cluster.b64 [%0];"
                                 :: "r"(mb + s * 8) : "memory");
                }
            }

            if (kt + 2 < 64) {
                const int sd = (kt + 2) - ((kt + 2) / 3) * 3;
                const u32 dA0 = st0 + sd * 65536;
                if (kt >= 1) {
                    const int kp = kt - 1;
                    const int kdv = kp / 3;
                    const int sp = kp - kdv * 3;
                    int bps = (sp == 0) ? 0 : ((sp == 1) ? bp1 : bp2);
                    u32 ph = (u32)(bps ^ (kdv & 1));
                    MWAIT(mb + sp * 8, ph);
                }
                ld_sub(dA0,         x0 + (kt + 2) * 128, tid, 4);
                ld_sub(dA0 + 16384, x1 + (kt + 2) * 128, tid, 4);
                ld_sub(dA0 + 32768, wt + (kt + 2) * 128, tid, 8);
            }
            asm volatile("cp.async.commit_group;" ::: "memory");
        }

        MWAIT(mb, 1u);
        asm volatile("tcgen05.fence::after_thread_sync;" ::: "memory");

        {
            const int half = wid >> 2, wr = wid & 3;
            float* dst = out + (u64)(mBase + half * 128 + wr * 32 + lid) * 4096 + nBase;
            const u32 tm = tmem + half * 256;
#pragma unroll
            for (int ch = 0; ch < 8; ch++) {
                u32 rr[32];
                LDTM32(rr, tm + ch * 32);
                asm volatile("tcgen05.wait::ld.sync.aligned;" ::: "memory");
#pragma unroll
                for (int j = 0; j < 8; j++)
                    asm volatile("st.global.cs.v4.b32 [%0], {%1,%2,%3,%4};"
                                 :: "l"(dst + ch * 32 + j * 4),
                                    "r"(rr[4 * j]), "r"(rr[4 * j + 1]),
                                    "r"(rr[4 * j + 2]), "r"(rr[4 * j + 3]) : "memory");
            }
            asm volatile("tcgen05.fence::before_thread_sync;" ::: "memory");
        }
        __syncthreads();
        bp1 ^= 1; bp2 ^= 1;
    }

    __syncthreads();
    if (wid == 0) {
        asm volatile("tcgen05.relinquish_alloc_permit.cta_group::1.sync.aligned;");
        asm volatile("tcgen05.dealloc.cta_group::1.sync.aligned.b32 %0, %1;"
                     :: "r"(tmem), "r"(512u));
    }
}

// ---------------- gemm5d: TMA + single-thread producer/consumer ----------------
// Same tiling/parity as gemm5c, but the whole k-loop runs in ONE elected
// thread: full-mbarrier (TMA complete_tx) -> MMA -> commit -> TMA for kt+2.
// No per-iter __syncthreads / wait_group / proxy fences.
extern "C" __global__ void __launch_bounds__(256, 1)
gemm5d(const void* __restrict__ tmx, const void* __restrict__ tmw,
       float* __restrict__ out) {
    extern __shared__ char sm[];
    u32 base = (sm2u32(sm) + 1023) & ~1023u;
    const u32 tptr = base;
    const u32 mbc = base + 16;    // commit barriers x3
    const u32 mbf = base + 48;    // TMA full barriers x3
    const u32 st0 = base + 1024;
    const int tid = threadIdx.x, wid = tid >> 5, lid = tid & 31;

    if (wid == 0)
        asm volatile("tcgen05.alloc.cta_group::1.sync.aligned.shared::cta.b32 [%0], %1;"
                     :: "r"(tptr), "r"(512u) : "memory");
    if (tid == 0) {
#pragma unroll
        for (int s = 0; s < 3; s++) {
            asm volatile("mbarrier.init.shared.b64 [%0], %1;"
                         :: "r"(mbc + s * 8), "r"(1u) : "memory");
            asm volatile("mbarrier.init.shared.b64 [%0], %1;"
                         :: "r"(mbf + s * 8), "r"(1u) : "memory");
        }
        asm volatile("prefetch.tensormap [%0];" :: "l"(tmx));
        asm volatile("prefetch.tensormap [%0];" :: "l"(tmw));
    }
    __syncthreads();
    u32 tmem; asm volatile("ld.shared.b32 %0,[%1];" : "=r"(tmem) : "r"(tptr));

    const u64 DBASE = (2ull << 61) | (1ull << 46) | (64ull << 32) | (1ull << 16);
    const u32 IDESC = (1u << 4) | (32u << 17) | (8u << 24);

    int bp1 = 0, bp2 = 0;          // commit-barrier base parities (all threads)
    int pf0 = 0, pf1 = 0, pf2 = 0; // full-barrier parities (thread0 only)

#pragma unroll 1
    for (int t = blockIdx.x; t < 512; t += gridDim.x) {
        const int mBase = (t >> 4) * 256, nBase = (t & 15) * 256;

        if (wid == 0) {
            u32 ep;
            asm volatile("{ .reg .pred p; elect.sync _|p, 0xFFFFFFFF; selp.b32 %0,1,0,p; }"
                         : "=r"(ep));
            if (ep) {
                // prologue: ktiles 0,1
#pragma unroll
                for (int p = 0; p < 2; p++) {
                    u32 sl = st0 + p * 65536;
                    EXPECT_TX(mbf + p * 8, 65536u);
                    TMA2D(sl,         tmx, p * 128, mBase,       mbf + p * 8);
                    TMA2D(sl + 16384, tmx, p * 128, mBase + 128, mbf + p * 8);
                    TMA2D(sl + 32768, tmw, p * 128, nBase,       mbf + p * 8);
                }
#pragma unroll 1
                for (int kt = 0; kt < 64; kt++) {
                    const int kdiv = kt / 3;
                    const int s = kt - kdiv * 3;
                    const u32 sA0 = st0 + s * 65536, sA1 = sA0 + 16384, sB = sA0 + 32768;
                    u32 ph;
                    if (s == 0) { ph = (u32)pf0; pf0 ^= 1; }
                    else if (s == 1) { ph = (u32)pf1; pf1 ^= 1; }
                    else { ph = (u32)pf2; pf2 ^= 1; }
                    MWAIT(mbf + s * 8, ph);

                    u64 a0 = DBASE | ((u64)(sA0 >> 4) & 0x3FFF);
                    u64 a1 = DBASE | ((u64)(sA1 >> 4) & 0x3FFF);
                    u64 bd = DBASE | ((u64)(sB >> 4) & 0x3FFF);
#pragma unroll
                    for (int q = 0; q < 4; q++) {
                        u32 en = (kt > 0 || q > 0) ? 1u : 0u;
                        asm volatile("{ .reg .pred p; setp.ne.u32 p, %5, 0; "
                            "tcgen05.mma.cta_group::1.kind::f16 [%0], %1, %2, %3, {%4,%4,%4,%4}, p; }"
                            :: "r"(tmem), "l"(a0 + q * 2), "l"(bd + q * 2),
                               "r"(IDESC), "r"(0u), "r"(en) : "memory");
                        asm volatile("{ .reg .pred p; setp.ne.u32 p, %5, 0; "
                            "tcgen05.mma.cta_group::1.kind::f16 [%0], %1, %2, %3, {%4,%4,%4,%4}, p; }"
                            :: "r"(tmem + 256), "l"(a1 + q * 2), "l"(bd + q * 2),
                               "r"(IDESC), "r"(0u), "r"(en) : "memory");
                    }
                    asm volatile("tcgen05.commit.cta_group::1.mbarrier::arrive::one.shared::cluster.b64 [%0];"
                                 :: "r"(mbc + s * 8) : "memory");

                    if (kt + 2 < 64) {
                        const int sd = (kt + 2) - ((kt + 2) / 3) * 3;
                        const u32 dA0 = st0 + sd * 65536;
                        if (kt >= 1) {
                            const int kp = kt - 1;
                            const int kdv = kp / 3;
                            const int sp = kp - kdv * 3;   // == sd
                            int bps = (sp == 0) ? 0 : ((sp == 1) ? bp1 : bp2);
                            u32 p2 = (u32)(bps ^ (kdv & 1));
                            MWAIT(mbc + sp * 8, p2);
                        }
                        EXPECT_TX(mbf + sd * 8, 65536u);
                        TMA2D(dA0,         tmx, (kt + 2) * 128, mBase,       mbf + sd * 8);
                        TMA2D(dA0 + 16384, tmx, (kt + 2) * 128, mBase + 128, mbf + sd * 8);
                        TMA2D(dA0 + 32768, tmw, (kt + 2) * 128, nBase,       mbf + sd * 8);
                    }
                }
            }
        }

        // drain: commit of kt=63 (slot 0, 22nd this tile -> parity 1)
        MWAIT(mbc, 1u);
        asm volatile("tcgen05.fence::after_thread_sync;" ::: "memory");

        {
            const int half = wid >> 2, wr = wid & 3;
            float* dst = out + (u64)(mBase + half * 128 + wr * 32 + lid) * 4096 + nBase;
            const u32 tm = tmem + half * 256;
#pragma unroll
            for (int ch = 0; ch < 8; ch++) {
                u32 rr[32];
                LDTM32(rr, tm + ch * 32);
                asm volatile("tcgen05.wait::ld.sync.aligned;" ::: "memory");
#pragma unroll
                for (int j = 0; j < 8; j++)
                    asm volatile("st.global.cs.v4.b32 [%0], {%1,%2,%3,%4};"
                                 :: "l"(dst + ch * 32 + j * 4),
                                    "r"(rr[4 * j]), "r"(rr[4 * j + 1]),
                                    "r"(rr[4 * j + 2]), "r"(rr[4 * j + 3]) : "memory");
            }
            asm volatile("tcgen05.fence::before_thread_sync;" ::: "memory");
        }
        __syncthreads();
        bp1 ^= 1; bp2 ^= 1;
    }

    __syncthreads();
    if (wid == 0) {
        asm volatile("tcgen05.relinquish_alloc_permit.cta_group::1.sync.aligned;");
        asm volatile("tcgen05.dealloc.cta_group::1.sync.aligned.b32 %0, %1;"
                     :: "r"(tmem), "r"(512u));
    }
}

// ---------------- wbuild: fused LoRA GEMM + NF4 dequant ----------------
extern "C" __global__ void __launch_bounds__(256, 1)
wbuild(const int* __restrict__ qw, const float* __restrict__ am,
       const u16* __restrict__ lb, const u16* __restrict__ lat,
       u16* __restrict__ w) {
    extern __shared__ char sm[];
    u32 base = (sm2u32(sm) + 1023) & ~1023u;
    const u32 tptr = base;
    const u32 mb = base + 16;
    const u32 sa = base + 1024;
    const u32 sb = sa + 16384;
    const int tid = threadIdx.x, wid = tid >> 5, lid = tid & 31;
    const int ti = blockIdx.x;
    const int o0 = (ti >> 4) * 128, i0 = (ti & 15) * 256;

    if (wid == 0)
        asm volatile("tcgen05.alloc.cta_group::1.sync.aligned.shared::cta.b32 [%0], %1;"
                     :: "r"(tptr), "r"(256u) : "memory");
    if (tid == 0)
        asm volatile("mbarrier.init.shared.b64 [%0], %1;" :: "r"(mb), "r"(1u) : "memory");
    __syncthreads();
    u32 tmem; asm volatile("ld.shared.b32 %0,[%1];" : "=r"(tmem) : "r"(tptr));

#pragma unroll
    for (int r = 0; r < 4; r++) {
        int i = tid + r * 256; int row = i >> 3, c = i & 7;
        u32 off = (u32)(row * 128 + ((c * 16) ^ ((row & 7) << 4)));
        asm volatile("cp.async.cg.shared.global [%0], [%1], 16;"
                     :: "r"(sa + off), "l"((const char*)lb + (u64)(o0 + row) * 128 + c * 16));
    }
#pragma unroll
    for (int r = 0; r < 8; r++) {
        int i = tid + r * 256; int row = i >> 3, c = i & 7;
        u32 off = (u32)(row * 128 + ((c * 16) ^ ((row & 7) << 4)));
        asm volatile("cp.async.cg.shared.global [%0], [%1], 16;"
                     :: "r"(sb + off), "l"((const char*)lat + (u64)(i0 + row) * 128 + c * 16));
    }
    asm volatile("cp.async.commit_group;" ::: "memory");
    asm volatile("cp.async.wait_group 0;" ::: "memory");
    __syncthreads();

    const u64 DBASE = (2ull << 61) | (1ull << 46) | (64ull << 32) | (1ull << 16);
    const u32 IDESC = (1u << 4) | (32u << 17) | (8u << 24);

    if (wid == 0) {
        u32 ep;
        asm volatile("{ .reg .pred p; elect.sync _|p, 0xFFFFFFFF; selp.b32 %0,1,0,p; }"
                     : "=r"(ep));
        if (ep) {
            asm volatile("fence.proxy.async.shared::cta;" ::: "memory");
            u64 ad = DBASE | ((u64)(sa >> 4) & 0x3FFF);
            u64 bd = DBASE | ((u64)(sb >> 4) & 0x3FFF);
#pragma unroll
            for (int q = 0; q < 4; q++) {
                u32 en = (q > 0) ? 1u : 0u;
                asm volatile("{ .reg .pred p; setp.ne.u32 p, %5, 0; "
                    "tcgen05.mma.cta_group::1.kind::f16 [%0], %1, %2, %3, {%4,%4,%4,%4}, p; }"
                    :: "r"(tmem), "l"(ad + q * 2), "l"(bd + q * 2),
                       "r"(IDESC), "r"(0u), "r"(en) : "memory");
            }
            asm volatile("tcgen05.commit.cta_group::1.mbarrier::arrive::one.shared::cluster.b64 [%0];"
                         :: "r"(mb) : "memory");
        }
    }
    __syncthreads();
    MWAIT(mb, 0u);
    asm volatile("tcgen05.fence::after_thread_sync;" ::: "memory");

    const int half = wid >> 2, wr = wid & 3;
    const int o = o0 + wr * 32 + lid;
#pragma unroll
    for (int c4 = 0; c4 < 4; c4++) {
        u32 rr[32];
        LDTM32(rr, tmem + half * 128 + c4 * 32);
        asm volatile("tcgen05.wait::ld.sync.aligned;" ::: "memory");
        const u64 k = (u64)o * 4096 + (u64)(i0 + half * 128 + c4 * 32);
        const float a = am[k >> 6];
        const int4* qp = (const int4*)qw + (k >> 3);
        u32 ov[16];
#pragma unroll
        for (int u = 0; u < 4; u++) {
            int4 qv = qp[u];
            int e[8] = {qv.x & 15, (qv.x >> 4) & 15, qv.y & 15, (qv.y >> 4) & 15,
                        qv.z & 15, (qv.z >> 4) & 15, qv.w & 15, (qv.w >> 4) & 15};
#pragma unroll
            for (int j = 0; j < 4; j++) {
                union { u32 u_; float f_; } c0, c1;
                c0.u_ = rr[u * 8 + 2 * j];
                c1.u_ = rr[u * 8 + 2 * j + 1];
                float w0 = NF4D[e[2 * j]] * a + c0.f_;
                float w1 = NF4D[e[2 * j + 1]] * a + c1.f_;
                asm("cvt.rn.f16x2.f32 %0, %1, %2;" : "=r"(ov[u * 4 + j]) : "f"(w1), "f"(w0));
            }
        }
        char* wp = (char*)w + k * 2;
#pragma unroll
        for (int j = 0; j < 4; j++)
            asm volatile("st.global.cs.v4.b32 [%0], {%1,%2,%3,%4};"
                         :: "l"(wp + j * 16), "r"(ov[4 * j]), "r"(ov[4 * j + 1]),
                            "r"(ov[4 * j + 2]), "r"(ov[4 * j + 3]) : "memory");
    }
    asm volatile("tcgen05.fence::before_thread_sync;" ::: "memory");
    __syncthreads();
    if (wid == 0) {
        asm volatile("tcgen05.relinquish_alloc_permit.cta_group::1.sync.aligned;");
        asm volatile("tcgen05.dealloc.cta_group::1.sync.aligned.b32 %0, %1;"
                     :: "r"(tmem), "r"(256u));
    }
}
)NVSRC";

// --- driver/nvrtc plumbing ---
typedef int (*nvrtcCreateProgram_t)(void**, const char*, const char*, int,
                                    const char* const*, const char* const*);
typedef int (*nvrtcCompileProgram_t)(void*, int, const char* const*);
typedef int (*nvrtcGetCUBINSize_t)(void*, size_t*);
typedef int (*nvrtcGetCUBIN_t)(void*, char*);
typedef int (*cuInit_t)(unsigned);
typedef int (*cuDevicePrimaryCtxRetain_t)(void**, int);
typedef int (*cuCtxSetCurrent_t)(void*);
typedef int (*cuModuleLoadDataEx_t)(void**, const void*, unsigned, int*, void**);
typedef int (*cuModuleGetFunction_t)(void**, void*, const char*);
typedef int (*cuModuleGetGlobal_t)(unsigned long long*, size_t*, void*, const char*);
typedef int (*cuFuncSetAttribute_t)(void*, int, int);
typedef int (*cuLaunchKernel_t)(void*, unsigned, unsigned, unsigned,
                                unsigned, unsigned, unsigned,
                                unsigned, void*, void**, void**);
typedef int (*cuCtxSynchronize_t)(void);
typedef int (*cuMemcpyDtoH_t)(void*, unsigned long long, size_t);
typedef int (*cuMemcpyHtoD_t)(unsigned long long, const void*, size_t);
typedef int (*cuTensorMapEncodeTiled_t)(void*, int, unsigned, void*,
                                        const unsigned long long*,
                                        const unsigned long long*,
                                        const unsigned*, const unsigned*,
                                        int, int, int, int);

#if defined(CUDA_API_PER_THREAD_DEFAULT_STREAM) || defined(__CUDA_API_PER_THREAD_DEFAULT_STREAM)
#define DRV_STREAM ((void*)0x2)
#else
#define DRV_STREAM ((void*)0x1)
#endif

static bool g_ok_gemm = false, g_ok_wb = false, g_tma = false;
static cuLaunchKernel_t p_cuLaunchKernel = nullptr;
static void* g_fn_gemm = nullptr;
static void* g_fn_wbuild = nullptr;
static unsigned long long g_gx = 0, g_gw = 0, g_glb = 0, g_glat = 0;
static unsigned long long g_tmx = 0, g_tmw = 0;
constexpr int SMEM5 = 198656;
constexpr int SMEMW = 51200;

static float h2f(uint16_t h) {
    uint32_t s = (h >> 15) & 1, e = (h >> 10) & 31, m = h & 1023;
    uint32_t f;
    if (e == 0) {
        if (m == 0) f = s << 31;
        else {
            e = 127 - 15 + 1;
            while (!(m & 1024)) { m <<= 1; e--; }
            m &= 1023;
            f = (s << 31) | (e << 23) | (m << 13);
        }
    } else if (e == 31) f = (s << 31) | 0x7F800000 | (m << 13);
    else f = (s << 31) | ((e - 15 + 127) << 23) | (m << 13);
    float r; memcpy(&r, &f, 4); return r;
}

static bool try_init_tcgen05() {
    void* hcu = dlopen("libcuda.so.1", RTLD_NOW | RTLD_GLOBAL);
    if (!hcu) hcu = dlopen("libcuda.so", RTLD_NOW | RTLD_GLOBAL);
    if (!hcu) return false;
    void* hnv = dlopen("libnvrtc.so.13", RTLD_NOW | RTLD_GLOBAL);
    if (!hnv) hnv = dlopen("libnvrtc.so", RTLD_NOW | RTLD_GLOBAL);
    if (!hnv) hnv = dlopen("libnvrtc.so.12", RTLD_NOW | RTLD_GLOBAL);
    if (!hnv) return false;

    auto nCreate  = (nvrtcCreateProgram_t)dlsym(hnv, "nvrtcCreateProgram");
    auto nCompile = (nvrtcCompileProgram_t)dlsym(hnv, "nvrtcCompileProgram");
    auto nCbSize  = (nvrtcGetCUBINSize_t)dlsym(hnv, "nvrtcGetCUBINSize");
    auto nCb      = (nvrtcGetCUBIN_t)dlsym(hnv, "nvrtcGetCUBIN");
    auto cInit    = (cuInit_t)dlsym(hcu, "cuInit");
    auto cRetain  = (cuDevicePrimaryCtxRetain_t)dlsym(hcu, "cuDevicePrimaryCtxRetain");
    auto cSetCur  = (cuCtxSetCurrent_t)dlsym(hcu, "cuCtxSetCurrent");
    auto cModLoad = (cuModuleLoadDataEx_t)dlsym(hcu, "cuModuleLoadDataEx");
    auto cGetFn   = (cuModuleGetFunction_t)dlsym(hcu, "cuModuleGetFunction");
    auto cGetGlb  = (cuModuleGetGlobal_t)dlsym(hcu, "cuModuleGetGlobal_v2");
    auto cSetAttr = (cuFuncSetAttribute_t)dlsym(hcu, "cuFuncSetAttribute");
    auto cLaunch  = (cuLaunchKernel_t)dlsym(hcu, "cuLaunchKernel");
    auto cSync    = (cuCtxSynchronize_t)dlsym(hcu, "cuCtxSynchronize");
    auto cD2H     = (cuMemcpyDtoH_t)dlsym(hcu, "cuMemcpyDtoH_v2");
    auto cH2D     = (cuMemcpyHtoD_t)dlsym(hcu, "cuMemcpyHtoD_v2");
    auto cTmEnc   = (cuTensorMapEncodeTiled_t)dlsym(hcu, "cuTensorMapEncodeTiled");
    if (!nCreate || !nCompile || !nCbSize || !nCb || !cInit || !cRetain ||
        !cSetCur || !cModLoad || !cGetFn || !cGetGlb || !cSetAttr ||
        !cLaunch || !cSync || !cD2H)
        return false;

    if (cInit(0)) return false;
    void* ctx = nullptr;
    if (cRetain(&ctx, 0)) return false;
    if (cSetCur(ctx)) return false;

    void* prog = nullptr;
    if (nCreate(&prog, NVRTC_SRC, "gemm5.cu", 0, nullptr, nullptr)) return false;
    const char* opts[] = {"--gpu-architecture=sm_103a"};
    if (nCompile(prog, 1, opts)) return false;
    size_t cbsz = 0;
    if (nCbSize(prog, &cbsz) || cbsz == 0) return false;
    static char* cubin = new char[cbsz];
    if (nCb(prog, cubin)) return false;

    void* mod = nullptr;
    if (cModLoad(&mod, cubin, 0, nullptr, nullptr)) return false;
    void *fG5 = nullptr, *fG5c = nullptr, *fG5d = nullptr;
    void *fInit = nullptr, *fWb = nullptr, *fWti = nullptr;
    if (cGetFn(&fG5, mod, "gemm5")) return false;
    if (cGetFn(&fG5c, mod, "gemm5c")) return false;
    if (cGetFn(&fG5d, mod, "gemm5d")) return false;
    if (cGetFn(&fInit, mod, "initt")) return false;
    if (cGetFn(&fWb, mod, "wbuild")) return false;
    if (cGetFn(&fWti, mod, "wtinit")) return false;
    unsigned long long gx = 0, gw = 0, gout = 0, glb = 0, glat = 0,
                       gtqw = 0, gtam = 0, tmxd = 0, tmwd = 0;
    size_t sz;
    if (cGetGlb(&gx, &sz, mod, "GX")) return false;
    if (cGetGlb(&gw, &sz, mod, "GW")) return false;
    if (cGetGlb(&gout, &sz, mod, "GOUT")) return false;
    if (cGetGlb(&glb, &sz, mod, "GLB")) return false;
    if (cGetGlb(&glat, &sz, mod, "GLAT")) return false;
    if (cGetGlb(&gtqw, &sz, mod, "GTQW")) return false;
    if (cGetGlb(&gtam, &sz, mod, "GTAM")) return false;
    if (cGetGlb(&tmxd, &sz, mod, "TMXD")) return false;
    if (cGetGlb(&tmwd, &sz, mod, "TMWD")) return false;
    if (cSetAttr(fG5, 8, SMEM5)) return false;
    if (cSetAttr(fG5c, 8, SMEM5)) return false;
    if (cSetAttr(fG5d, 8, SMEM5)) return false;
    if (cSetAttr(fWb, 8, SMEMW)) return false;

    p_cuLaunchKernel = cLaunch;
    g_gx = gx; g_gw = gw; g_glb = glb; g_glat = glat;
    g_tmx = tmxd; g_tmw = tmwd;

    // ---- encode tensormaps (uint8, SW128) ----
    bool tma_ready = false;
    if (cTmEnc && cH2D) {
        struct { alignas(64) unsigned char b[128]; } tm;
        unsigned long long dimsX[2] = {8192ull, 8192ull};   // bytes/row, rows
        unsigned long long dimsW[2] = {8192ull, 4096ull};
        unsigned long long strides[1] = {8192ull};
        unsigned boxA[2] = {128u, 128u};
        unsigned boxB[2] = {128u, 256u};
        unsigned es[2] = {1u, 1u};
        // dtype UINT8=0, interleave NONE=0, swizzle 128B=3, L2 promo 128B=2, oob NONE=0
        do {
            memset(&tm, 0, sizeof(tm));
            if (cTmEnc(&tm, 0, 2, (void*)(uintptr_t)gx, dimsX, strides, boxA, es,
                       0, 3, 2, 0)) break;
            if (cH2D(tmxd, &tm, 128)) break;
            memset(&tm, 0, sizeof(tm));
            if (cTmEnc(&tm, 0, 2, (void*)(uintptr_t)gw, dimsW, strides, boxB, es,
                       0, 3, 2, 0)) break;
            if (cH2D(tmwd, &tm, 128)) break;
            tma_ready = true;
        } while (0);
    }

    // ---- gemm self-test (exact integer grid) ----
    if (cLaunch(fInit, 131072, 1, 1, 256, 1, 1, 0, DRV_STREAM, nullptr, nullptr))
        return false;
    static float row[OUT_F];
    const int ms[4] = {0, 97, 4095, 8191};
    auto check_out = [&](unsigned long long gout_) -> bool {
        for (int ri = 0; ri < 4; ri++) {
            int m = ms[ri];
            if (cD2H(row, gout_ + (unsigned long long)m * OUT_F * 4, OUT_F * 4))
                return false;
            for (int n = 0; n < OUT_F; n++) {
                float ref = 0.0f;
                for (int k = 0; k < IN_F; k++) {
                    int av = (k * 131 + m * 7) % 9 - 4;
                    int bv = (k * 17 + n * 3) % 7 - 3;
                    ref += (av * 0.25f) * (bv * 0.25f);
                }
                if (fabsf(row[n] - ref) > 0.01f) return false;
            }
        }
        return true;
    };
    auto test_gemm = [&](void* fn) -> bool {
        unsigned long long px = gx, pw = gw, po = gout;
        void* args[3] = {&px, &pw, &po};
        if (cLaunch(fn, 148, 1, 1, 256, 1, 1, SMEM5, DRV_STREAM, args, nullptr))
            return false;
        if (cSync()) return false;
        return check_out(gout);
    };
    auto test_gemm_tma = [&](void* fn) -> bool {
        unsigned long long px = tmxd, pw = tmwd, po = gout;
        void* args[3] = {&px, &pw, &po};
        if (cLaunch(fn, 148, 1, 1, 256, 1, 1, SMEM5, DRV_STREAM, args, nullptr))
            return false;
        if (cSync()) return false;
        return check_out(gout);
    };
    if (tma_ready && test_gemm_tma(fG5d)) { g_fn_gemm = fG5d; g_ok_gemm = true; g_tma = true; }
    else if (test_gemm(fG5c)) { g_fn_gemm = fG5c; g_ok_gemm = true; }
    else if (test_gemm(fG5)) { g_fn_gemm = fG5; g_ok_gemm = true; }
    if (!g_ok_gemm) return false;

    // ---- wbuild self-test ----
    do {
        if (cLaunch(fWti, 32768, 1, 1, 256, 1, 1, 0, DRV_STREAM, nullptr, nullptr))
            break;
        unsigned long long pq = gtqw, pa = gtam, pl = glb, pt = glat, pw2 = gw;
        void* args[5] = {&pq, &pa, &pl, &pt, &pw2};
        if (cLaunch(fWb, 512, 1, 1, 256, 1, 1, SMEMW, DRV_STREAM, args, nullptr))
            break;
        if (cSync()) break;
        static uint16_t wrow[IN_F];
        const int os[4] = {0, 1, 255, 4095};
        bool ok = true;
        for (int oi = 0; oi < 4 && ok; oi++) {
            int o = os[oi];
            if (cD2H(wrow, gw + (unsigned long long)o * IN_F * 2, IN_F * 2)) { ok = false; break; }
            for (int i = 0; i < IN_F; i++) {
                uint64_t k = (uint64_t)o * 4096 + i;
                uint64_t t = k >> 1;
                int qv = (int)((t * 37ull) & 255ull);
                int nib = (k & 1) ? (qv >> 4) & 15 : qv & 15;
                float a = (float)(((uint32_t)((k >> 6) * 13ull)) % 31u + 1u) * 0.03125f;
                float lora = 0.0f;
                for (int r = 0; r < 64; r++) {
                    float lb = (float)((int)(((uint32_t)o * 3u + r * 7u) % 17u) - 8) * 0.015625f;
                    float la = (float)((int)(((uint32_t)i * 5u + r * 11u) % 19u) - 9) * 0.015625f;
                    lora += lb * la;
                }
                float ref = NF4H[nib] * a + lora;
                if (fabsf(h2f(wrow[i]) - ref) > 0.01f) { ok = false; break; }
            }
        }
        if (ok) { g_fn_wbuild = fWb; g_ok_wb = true; }
    } while (0);

    return true;
}

__attribute__((constructor))
static void _init_drv() {
    try_init_tcgen05();
}

// ---------------------------------------------------------------------------
extern "C" void kernel_launch(void* const* d_in, const int* in_sizes, int n_in,
                              void* d_out, int out_size) {
    const float* x  = (const float*)d_in[0];
    const int*   qw = (const int*)d_in[1];
    const float* am = (const float*)d_in[2];
    const float* lA = (const float*)d_in[3];
    const float* lB = (const float*)d_in[4];
    float*       out = (float*)d_out;

    (void)in_sizes; (void)n_in; (void)out_size;

    if (g_ok_gemm) {
        __half* xh = (__half*)(uintptr_t)g_gx;
        __half* wh = (__half*)(uintptr_t)g_gw;

        convert_x_kernel<<<(M_ROWS * IN_F / 8) / 256, 256>>>(x, xh);

        if (g_ok_wb) {
            cvt_lb_kernel<<<256, 256>>>(lB, (__half*)(uintptr_t)g_glb);
            cvt_lat_kernel<<<64, 256>>>(lA, (__half*)(uintptr_t)g_glat);
            unsigned long long pq = (unsigned long long)(uintptr_t)qw;
            unsigned long long pa = (unsigned long long)(uintptr_t)am;
            unsigned long long pl = g_glb, pt = g_glat, pw = g_gw;
            void* args[5] = {&pq, &pa, &pl, &pt, &pw};
            p_cuLaunchKernel(g_fn_wbuild, 512, 1, 1, 256, 1, 1, SMEMW,
                             DRV_STREAM, args, nullptr);
        } else {
            build_weff_kernel<<<dim3(IN_F / 128, OUT_F / 64), 256>>>(qw, am, lA, lB, wh);
        }

        void* po = (void*)out;
        if (g_tma) {
            unsigned long long ptx = g_tmx, ptw = g_tmw;
            void* args[3] = {&ptx, &ptw, &po};
            p_cuLaunchKernel(g_fn_gemm, 148, 1, 1, 256, 1, 1, SMEM5,
                             DRV_STREAM, args, nullptr);
        } else {
            unsigned long long px = g_gx, pw2 = g_gw;
            void* args[3] = {&px, &pw2, &po};
            p_cuLaunchKernel(g_fn_gemm, 148, 1, 1, 256, 1, 1, SMEM5,
                             DRV_STREAM, args, nullptr);
        }
    } else {
        __half* xh; __half* wh;
        cudaGetSymbolAddress((void**)&xh, g_Xh);
        cudaGetSymbolAddress((void**)&wh, g_Wh);
        convert_x_kernel<<<(M_ROWS * IN_F / 8) / 256, 256>>>(x, xh);
        build_weff_kernel<<<dim3(IN_F / 128, OUT_F / 64), 256>>>(qw, am, lA, lB, wh);
        cudaFuncSetAttribute(gemm_f16_kernel,
                             cudaFuncAttributeMaxDynamicSharedMemorySize, SMEM_TOTAL);
        gemm_f16_kernel<<<148, 512, SMEM_TOTAL>>>(xh, wh, out);
    }
}

// round 11
// speedup vs baseline: 1.0060x; 1.0060x over previous
#include <cuda_runtime.h>
#include <cuda_fp16.h>
#include <cstdint>
#include <cstdio>
#include <cstring>
#include <cmath>
#include <dlfcn.h>

#define IN_F   4096
#define OUT_F  4096
#define M_ROWS 8192

// Host-module fp16 scratch (used by the fallback path).
__device__ __half g_Xh[(size_t)M_ROWS * IN_F];
__device__ __half g_Wh[(size_t)OUT_F * IN_F];

__constant__ float NF4[16] = {
    -1.0f, -0.6961928009986877f, -0.5250730514526367f, -0.39491748809814453f,
    -0.28444138169288635f, -0.18477343022823334f, -0.09105003625154495f, 0.0f,
    0.07958029955625534f, 0.16093020141124725f, 0.24611230194568634f,
    0.33791524171829224f, 0.4407098889350891f, 0.5626170039176941f,
    0.7229568362236023f, 1.0f
};

static const float NF4H[16] = {
    -1.0f, -0.6961928009986877f, -0.5250730514526367f, -0.39491748809814453f,
    -0.28444138169288635f, -0.18477343022823334f, -0.09105003625154495f, 0.0f,
    0.07958029955625534f, 0.16093020141124725f, 0.24611230194568634f,
    0.33791524171829224f, 0.4407098889350891f, 0.5626170039176941f,
    0.7229568362236023f, 1.0f
};

__device__ __forceinline__ uint32_t smem_u32(const void* p) {
    uint32_t a;
    asm("{ .reg .u64 t; cvta.to.shared.u64 t, %1; cvt.u32.u64 %0, t; }" : "=r"(a) : "l"(p));
    return a;
}

// ---------------------------------------------------------------------------
// Kernel A: convert x (fp32) -> dst (fp16). 8 elems/thread.
// ---------------------------------------------------------------------------
__global__ void convert_x_kernel(const float* __restrict__ x, __half* __restrict__ dst) {
    size_t i = ((size_t)blockIdx.x * 256 + threadIdx.x) * 8;
    float4 v0 = *(const float4*)(x + i);
    float4 v1 = *(const float4*)(x + i + 4);
    __half2 h0 = __floats2half2_rn(v0.x, v0.y);
    __half2 h1 = __floats2half2_rn(v0.z, v0.w);
    __half2 h2 = __floats2half2_rn(v1.x, v1.y);
    __half2 h3 = __floats2half2_rn(v1.z, v1.w);
    uint4 o;
    o.x = *(uint32_t*)&h0; o.y = *(uint32_t*)&h1;
    o.z = *(uint32_t*)&h2; o.w = *(uint32_t*)&h3;
    *(uint4*)&dst[i] = o;
}

// lora_B [4096][64] fp32 -> fp16 same layout
__global__ void cvt_lb_kernel(const float* __restrict__ lB, __half* __restrict__ lb) {
    size_t i = ((size_t)blockIdx.x * 256 + threadIdx.x) * 4;
    float4 v = *(const float4*)(lB + i);
    __half h[4] = {__float2half_rn(v.x), __float2half_rn(v.y),
                   __float2half_rn(v.z), __float2half_rn(v.w)};
    *(uint2*)&lb[i] = *(uint2*)h;
}

// lora_A [64][4096] fp32 -> lat [4096][64] fp16 (transpose)
__global__ void cvt_lat_kernel(const float* __restrict__ lA, __half* __restrict__ lat) {
    __shared__ float s[64][65];
    const int tid = threadIdx.x;
    const int i0 = blockIdx.x * 64;
    for (int idx = tid; idx < 4096; idx += 256) {
        int r = idx >> 6, ii = idx & 63;
        s[r][ii] = lA[r * IN_F + i0 + ii];
    }
    __syncthreads();
    int ii = tid >> 2, rs = (tid & 3) * 16;
    __half h[16];
#pragma unroll
    for (int j = 0; j < 16; j++) h[j] = __float2half_rn(s[rs + j][ii]);
    uint4* dst = (uint4*)&lat[(size_t)(i0 + ii) * 64 + rs];
    dst[0] = *(uint4*)&h[0];
    dst[1] = *(uint4*)&h[8];
}

// ---------------------------------------------------------------------------
// Host fallback: W_eff = NF4 dequant * absmax + lora_B @ lora_A  (fp16 out)
// ---------------------------------------------------------------------------
__global__ void build_weff_kernel(const int* __restrict__ qweight,
                                  const float* __restrict__ absmax,
                                  const float* __restrict__ lA,
                                  const float* __restrict__ lB,
                                  __half* __restrict__ dst) {
    __shared__ float Bsh[64][64];
    __shared__ float Ash[64][128];

    const int tid = threadIdx.x;
    const int o0 = blockIdx.y * 64;
    const int i0 = blockIdx.x * 128;

    for (int t = tid; t < 64 * 64; t += 256) {
        int o = t >> 6, r = t & 63;
        Bsh[r][o] = lB[(o0 + o) * 64 + r];
    }
    for (int t = tid; t < 64 * 128; t += 256) {
        int r = t >> 7, c = t & 127;
        Ash[r][c] = lA[r * IN_F + i0 + c];
    }
    __syncthreads();

    const int oo0 = (tid >> 4) * 4;
    const int ii0 = (tid & 15) * 8;

    float acc[4][8];
#pragma unroll
    for (int a = 0; a < 4; a++)
#pragma unroll
        for (int b = 0; b < 8; b++) acc[a][b] = 0.0f;

#pragma unroll 4
    for (int r = 0; r < 64; r++) {
        float4 a0 = *(const float4*)&Ash[r][ii0];
        float4 a1 = *(const float4*)&Ash[r][ii0 + 4];
#pragma unroll
        for (int oo = 0; oo < 4; oo++) {
            float bv = Bsh[r][oo0 + oo];
            acc[oo][0] += bv * a0.x; acc[oo][1] += bv * a0.y;
            acc[oo][2] += bv * a0.z; acc[oo][3] += bv * a0.w;
            acc[oo][4] += bv * a1.x; acc[oo][5] += bv * a1.y;
            acc[oo][6] += bv * a1.z; acc[oo][7] += bv * a1.w;
        }
    }

#pragma unroll
    for (int oo = 0; oo < 4; oo++) {
        const int o = o0 + oo0 + oo;
        const size_t k = (size_t)o * IN_F + i0 + ii0;
        const int4 qv = ((const int4*)qweight)[k >> 3];
        const float am = absmax[k >> 6];

        float w[8];
        w[0] = NF4[qv.x & 15];  w[1] = NF4[(qv.x >> 4) & 15];
        w[2] = NF4[qv.y & 15];  w[3] = NF4[(qv.y >> 4) & 15];
        w[4] = NF4[qv.z & 15];  w[5] = NF4[(qv.z >> 4) & 15];
        w[6] = NF4[qv.w & 15];  w[7] = NF4[(qv.w >> 4) & 15];

        __half2 h0 = __floats2half2_rn(w[0] * am + acc[oo][0], w[1] * am + acc[oo][1]);
        __half2 h1 = __floats2half2_rn(w[2] * am + acc[oo][2], w[3] * am + acc[oo][3]);
        __half2 h2 = __floats2half2_rn(w[4] * am + acc[oo][4], w[5] * am + acc[oo][5]);
        __half2 h3 = __floats2half2_rn(w[6] * am + acc[oo][6], w[7] * am + acc[oo][7]);
        uint4 pk;
        pk.x = *(uint32_t*)&h0; pk.y = *(uint32_t*)&h1;
        pk.z = *(uint32_t*)&h2; pk.w = *(uint32_t*)&h3;
        *(uint4*)&dst[k] = pk;
    }
}

// ---------------------------------------------------------------------------
// Fallback GEMM (proven 778us): fp16 mma.sync, 512 thr, 4-stage.
// ---------------------------------------------------------------------------
constexpr int BM = 128, BN = 256, BK = 64, S = 4;
constexpr int NT = IN_F / BK;
constexpr int A_BYTES = BM * 128;
constexpr int B_BYTES = BN * 128;
constexpr int STAGE = A_BYTES + B_BYTES;
constexpr int SMEM_TOTAL = 1024 + S * STAGE;
constexpr int TOTAL_TILES = (M_ROWS / BM) * (OUT_F / BN);

__device__ __forceinline__ void mma_f16(float c[4], const uint32_t a[4],
                                        uint32_t b0, uint32_t b1) {
    asm volatile(
        "mma.sync.aligned.m16n8k16.row.col.f32.f16.f16.f32 "
        "{%0,%1,%2,%3}, {%4,%5,%6,%7}, {%8,%9}, {%0,%1,%2,%3};"
        : "+f"(c[0]), "+f"(c[1]), "+f"(c[2]), "+f"(c[3])
        : "r"(a[0]), "r"(a[1]), "r"(a[2]), "r"(a[3]), "r"(b0), "r"(b1));
}

__device__ __forceinline__ void ldsm4(uint32_t& r0, uint32_t& r1,
                                      uint32_t& r2, uint32_t& r3, uint32_t addr) {
    asm volatile("ldmatrix.sync.aligned.m8n8.x4.shared.b16 {%0,%1,%2,%3}, [%4];"
                 : "=r"(r0), "=r"(r1), "=r"(r2), "=r"(r3) : "r"(addr));
}

__device__ __forceinline__ void st_cs_f2(float* p, float a, float b) {
    asm volatile("st.global.cs.v2.f32 [%0], {%1,%2};" :: "l"(p), "f"(a), "f"(b)
                 : "memory");
}

__device__ __forceinline__ void issue_stage(uint32_t sA, uint32_t sB,
                                            const __half* xb, const __half* wb,
                                            int tid) {
#pragma unroll
    for (int r = 0; r < 2; r++) {
        int i = tid + r * 512;
        int row = i >> 3, c = i & 7;
        uint32_t off = (uint32_t)(row * 128 + ((c * 16) ^ ((row & 7) << 4)));
        const __half* src = xb + (size_t)row * IN_F + c * 8;
        asm volatile("cp.async.cg.shared.global.L2::256B [%0], [%1], 16;\n"
                     :: "r"(sA + off), "l"(src));
    }
#pragma unroll
    for (int r = 0; r < 4; r++) {
        int i = tid + r * 512;
        int row = i >> 3, c = i & 7;
        uint32_t off = (uint32_t)(row * 128 + ((c * 16) ^ ((row & 7) << 4)));
        const __half* src = wb + (size_t)row * IN_F + c * 8;
        asm volatile("cp.async.cg.shared.global.L2::256B [%0], [%1], 16;\n"
                     :: "r"(sB + off), "l"(src));
    }
}

__global__ void __launch_bounds__(512, 1)
gemm_f16_kernel(const __half* __restrict__ Xh, const __half* __restrict__ Wh,
                float* __restrict__ out) {
    extern __shared__ char sm[];
    const uint32_t stage0 = (smem_u32(sm) + 1023) & ~1023u;

    const int tid = threadIdx.x;
    const int wid = tid >> 5;
    const int lane = tid & 31;
    const int warp_m = wid & 3;
    const int warp_n = wid >> 2;
    const int g = lane >> 3;
    const int r = lane & 7;

    uint32_t a_rowoff[2], a_xr[2];
    const uint32_t a_kc = (uint32_t)((g >> 1) * 16);
#pragma unroll
    for (int mf = 0; mf < 2; mf++) {
        int row = warp_m * 32 + mf * 16 + (g & 1) * 8 + r;
        a_rowoff[mf] = row * 128;
        a_xr[mf] = (row & 7) << 4;
    }
    uint32_t b_rowoff[4], b_xr[4];
    const uint32_t b_kc = (uint32_t)((g & 1) * 16);
#pragma unroll
    for (int p = 0; p < 4; p++) {
        int row = warp_n * 64 + p * 16 + (g >> 1) * 8 + r;
        b_rowoff[p] = row * 128;
        b_xr[p] = (row & 7) << 4;
    }

    for (int t = blockIdx.x; t < TOTAL_TILES; t += gridDim.x) {
        const int mBase = (t >> 4) * BM;
        const int nBase = (t & 15) * BN;
        const __half* xt = Xh + (size_t)mBase * IN_F;
        const __half* wt = Wh + (size_t)nBase * IN_F;

        float acc[2][8][4];
#pragma unroll
        for (int i = 0; i < 2; i++)
#pragma unroll
            for (int j = 0; j < 8; j++)
#pragma unroll
                for (int l = 0; l < 4; l++) acc[i][j][l] = 0.0f;

#pragma unroll
        for (int p = 0; p < S - 1; p++) {
            uint32_t sA = stage0 + p * STAGE;
            issue_stage(sA, sA + A_BYTES, xt + p * BK, wt + p * BK, tid);
            asm volatile("cp.async.commit_group;\n" ::: "memory");
        }

        for (int kt = 0; kt < NT; kt++) {
            asm volatile("cp.async.wait_group %0;\n" :: "n"(S - 2) : "memory");
            __syncthreads();

            if (kt + S - 1 < NT) {
                const int s2 = (kt + S - 1) % S;
                uint32_t sA = stage0 + s2 * STAGE;
                issue_stage(sA, sA + A_BYTES,
                            xt + (kt + S - 1) * BK, wt + (kt + S - 1) * BK, tid);
            }
            asm volatile("cp.async.commit_group;\n" ::: "memory");

            const uint32_t sA = stage0 + (kt % S) * STAGE;
            const uint32_t sB = sA + A_BYTES;

#pragma unroll
            for (int q = 0; q < 4; q++) {
                uint32_t a[2][4];
#pragma unroll
                for (int mf = 0; mf < 2; mf++)
                    ldsm4(a[mf][0], a[mf][1], a[mf][2], a[mf][3],
                          sA + a_rowoff[mf] + (((q * 32) + a_kc) ^ a_xr[mf]));
                uint32_t b[8][2];
#pragma unroll
                for (int p = 0; p < 4; p++)
                    ldsm4(b[2 * p][0], b[2 * p][1], b[2 * p + 1][0], b[2 * p + 1][1],
                          sB + b_rowoff[p] + (((q * 32) + b_kc) ^ b_xr[p]));
#pragma unroll
                for (int mf = 0; mf < 2; mf++)
#pragma unroll
                    for (int nf = 0; nf < 8; nf++)
                        mma_f16(acc[mf][nf], a[mf], b[nf][0], b[nf][1]);
            }
        }
        asm volatile("cp.async.wait_group 0;\n" ::: "memory");

#pragma unroll
        for (int mf = 0; mf < 2; mf++) {
#pragma unroll
            for (int nf = 0; nf < 8; nf++) {
                const int row = mBase + warp_m * 32 + mf * 16 + (lane >> 2);
                const int col = nBase + warp_n * 64 + nf * 8 + (lane & 3) * 2;
                st_cs_f2(&out[(size_t)row * OUT_F + col],
                         acc[mf][nf][0], acc[mf][nf][1]);
                st_cs_f2(&out[(size_t)(row + 8) * OUT_F + col],
                         acc[mf][nf][2], acc[mf][nf][3]);
            }
        }
        __syncthreads();
    }
}

// ===========================================================================
// NVRTC tcgen05 module: gemm5/5c (cp.async backstops), gemm5d (TMA),
// gemm6 (cluster B-multicast TMA), wbuild, init kernels.
// ===========================================================================
static const char* NVRTC_SRC = R"NVSRC(
typedef unsigned int u32;
typedef unsigned long long u64;
typedef unsigned short u16;

__device__ u16 GX[33554432];     // 8192*4096 fp16
__device__ u16 GW[16777216];     // 4096*4096 fp16
__device__ float GOUT[33554432]; // gemm self-test output
__device__ u16 GLB[262144];      // lora_B fp16 [4096][64]
__device__ u16 GLAT[262144];     // lora_A^T fp16 [4096][64]
__device__ int GTQW[8388608];    // wbuild self-test qweight
__device__ float GTAM[262144];   // wbuild self-test absmax
__device__ __align__(128) unsigned char TMXD[128];   // tensormap GX  box 128x128
__device__ __align__(128) unsigned char TMWD[128];   // tensormap GW  box 128x256
__device__ __align__(128) unsigned char TMW2D[128];  // tensormap GW  box 128x128

__constant__ float NF4D[16] = {
    -1.0f, -0.6961928009986877f, -0.5250730514526367f, -0.39491748809814453f,
    -0.28444138169288635f, -0.18477343022823334f, -0.09105003625154495f, 0.0f,
    0.07958029955625534f, 0.16093020141124725f, 0.24611230194568634f,
    0.33791524171829224f, 0.4407098889350891f, 0.5626170039176941f,
    0.7229568362236023f, 1.0f
};

#define MWAIT(ba, ph) do { u32 _d; \
    asm volatile("{ .reg .pred p; mbarrier.try_wait.parity.acquire.cta.shared::cta.b64 p, [%1], %2; selp.b32 %0,1,0,p; }" \
                 : "=r"(_d) : "r"(ba), "r"(ph) : "memory"); \
    if (!_d) { \
        asm volatile("{ .reg .pred P1; WL%=: mbarrier.try_wait.parity.acquire.cta.shared::cta.b64 P1, [%0], %1, 0x989680; @P1 bra.uni WD%=; bra.uni WL%=; WD%=: }" \
                     :: "r"(ba), "r"(ph) : "memory"); } } while(0)

#define LDTM32(rr, addr) \
    asm volatile("tcgen05.ld.sync.aligned.32x32b.x32.b32 " \
        "{%0,%1,%2,%3,%4,%5,%6,%7,%8,%9,%10,%11,%12,%13,%14,%15," \
        "%16,%17,%18,%19,%20,%21,%22,%23,%24,%25,%26,%27,%28,%29,%30,%31}, [%32];" \
        : "=r"(rr[0]), "=r"(rr[1]), "=r"(rr[2]), "=r"(rr[3]), \
          "=r"(rr[4]), "=r"(rr[5]), "=r"(rr[6]), "=r"(rr[7]), \
          "=r"(rr[8]), "=r"(rr[9]), "=r"(rr[10]), "=r"(rr[11]), \
          "=r"(rr[12]), "=r"(rr[13]), "=r"(rr[14]), "=r"(rr[15]), \
          "=r"(rr[16]), "=r"(rr[17]), "=r"(rr[18]), "=r"(rr[19]), \
          "=r"(rr[20]), "=r"(rr[21]), "=r"(rr[22]), "=r"(rr[23]), \
          "=r"(rr[24]), "=r"(rr[25]), "=r"(rr[26]), "=r"(rr[27]), \
          "=r"(rr[28]), "=r"(rr[29]), "=r"(rr[30]), "=r"(rr[31]) \
        : "r"(addr))

#define TMA2D(dst, tmap, cx, cy, mbar) \
    asm volatile("cp.async.bulk.tensor.2d.shared::cta.global.tile.mbarrier::complete_tx::bytes " \
                 "[%0], [%1, {%2, %3}], [%4];" \
                 :: "r"(dst), "l"(tmap), "r"(cx), "r"(cy), "r"(mbar) : "memory")

#define TMA2D_MC(dst, tmap, cx, cy, mbar, mask) \
    asm volatile("cp.async.bulk.tensor.2d.shared::cluster.global.tile.mbarrier::complete_tx::bytes.multicast::cluster " \
                 "[%0], [%1, {%2, %3}], [%4], %5;" \
                 :: "r"(dst), "l"(tmap), "r"(cx), "r"(cy), "r"(mbar), "h"((unsigned short)(mask)) : "memory")

#define EXPECT_TX(mbar, n) \
    asm volatile("mbarrier.arrive.expect_tx.shared.b64 _, [%0], %1;" \
                 :: "r"(mbar), "r"(n) : "memory")

#define MMA8(tmem, a0, a1, bd, IDESC, en) do { \
    asm volatile("{ .reg .pred p; setp.ne.u32 p, %5, 0; " \
        "tcgen05.mma.cta_group::1.kind::f16 [%0], %1, %2, %3, {%4,%4,%4,%4}, p; }" \
        :: "r"(tmem), "l"(a0), "l"(bd), "r"(IDESC), "r"(0u), "r"(en) : "memory"); \
    asm volatile("{ .reg .pred p; setp.ne.u32 p, %5, 0; " \
        "tcgen05.mma.cta_group::1.kind::f16 [%0], %1, %2, %3, {%4,%4,%4,%4}, p; }" \
        :: "r"((tmem) + 256), "l"(a1), "l"(bd), "r"(IDESC), "r"(0u), "r"(en) : "memory"); \
} while(0)

__device__ __forceinline__ u32 sm2u32(const void* p) {
    u32 a;
    asm("{ .reg .u64 t; cvta.to.shared.u64 t, %1; cvt.u32.u64 %0, t; }" : "=r"(a) : "l"(p));
    return a;
}

extern "C" __global__ void initt() {
    u64 i = (u64)blockIdx.x * 256 + threadIdx.x;
    const u16 T[9] = {0xBC00,0xBA00,0xB800,0xB400,0,0x3400,0x3800,0x3A00,0x3C00};
    if (i < 33554432ull) {
        u32 m = (u32)(i >> 12), k = (u32)(i & 4095);
        GX[i] = T[(k*131u + m*7u) % 9u];
    }
    if (i < 16777216ull) {
        u32 n = (u32)(i >> 12), k = (u32)(i & 4095);
        GW[i] = T[(k*17u + n*3u) % 7u + 1u];
    }
}

extern "C" __global__ void wtinit() {
    u64 i = (u64)blockIdx.x * 256 + threadIdx.x;
    if (i < 8388608ull) GTQW[i] = (int)((i * 37ull) & 255ull);
    if (i < 262144ull) {
        GTAM[i] = (float)((u32)(i * 13ull) % 31u + 1u) * 0.03125f;
        u32 o = (u32)(i >> 6), r = (u32)(i & 63);
        float lb = (float)((int)((o*3u + r*7u) % 17u) - 8) * 0.015625f;
        float la = (float)((int)((o*5u + r*11u) % 19u) - 9) * 0.015625f;
        u16 hb, ha;
        asm("cvt.rn.f16.f32 %0, %1;" : "=h"(hb) : "f"(lb));
        asm("cvt.rn.f16.f32 %0, %1;" : "=h"(ha) : "f"(la));
        GLB[i] = hb;
        GLAT[i] = ha;
    }
}

__device__ __forceinline__ void ld_sub(u32 dst, const char* src, int tid, int iters) {
#pragma unroll
    for (int r = 0; r < 8; r++) {
        if (r >= iters) break;
        int i = tid + r * 256; int row = i >> 3, c = i & 7;
        u32 off = (u32)(row * 128 + ((c * 16) ^ ((row & 7) << 4)));
        asm volatile("cp.async.cg.shared.global.L2::256B [%0], [%1], 16;"
                     :: "r"(dst + off), "l"(src + (u64)row * 8192 + c * 16));
    }
}

// ---------------- gemm5 (single M-tile backstop) ----------------
__device__ __forceinline__ void ld_stage(u32 sA, u32 sB, const char* xb,
                                         const char* wb, int tid) {
#pragma unroll
    for (int r = 0; r < 4; r++) {
        int i = tid + r * 256; int row = i >> 3, c = i & 7;
        u32 off = (u32)(row * 128 + ((c * 16) ^ ((row & 7) << 4)));
        asm volatile("cp.async.cg.shared.global.L2::256B [%0], [%1], 16;"
                     :: "r"(sA + off), "l"(xb + (u64)row * 8192 + c * 16));
    }
#pragma unroll
    for (int r = 0; r < 8; r++) {
        int i = tid + r * 256; int row = i >> 3, c = i & 7;
        u32 off = (u32)(row * 128 + ((c * 16) ^ ((row & 7) << 4)));
        asm volatile("cp.async.cg.shared.global.L2::256B [%0], [%1], 16;"
                     :: "r"(sB + off), "l"(wb + (u64)row * 8192 + c * 16));
    }
}

extern "C" __global__ void __launch_bounds__(256, 1)
gemm5(const char* __restrict__ X, const char* __restrict__ W,
      float* __restrict__ out) {
    extern __shared__ char sm[];
    u32 base = (sm2u32(sm) + 1023) & ~1023u;
    const u32 tptr = base;
    const u32 mb = base + 16;
    const u32 st0 = base + 1024;
    const int tid = threadIdx.x, wid = tid >> 5, lid = tid & 31;

    if (wid == 0)
        asm volatile("tcgen05.alloc.cta_group::1.sync.aligned.shared::cta.b32 [%0], %1;"
                     :: "r"(tptr), "r"(256u) : "memory");
    if (tid == 0) {
#pragma unroll
        for (int s = 0; s < 4; s++)
            asm volatile("mbarrier.init.shared.b64 [%0], %1;"
                         :: "r"(mb + s * 8), "r"(1u) : "memory");
    }
    __syncthreads();
    u32 tmem; asm volatile("ld.shared.b32 %0,[%1];" : "=r"(tmem) : "r"(tptr));

    const u64 DBASE = (2ull << 61) | (1ull << 46) | (64ull << 32) | (1ull << 16);
    const u32 IDESC = (1u << 4) | (32u << 17) | (8u << 24);

#pragma unroll 1
    for (int t = blockIdx.x; t < 1024; t += gridDim.x) {
        const int mBase = (t >> 4) * 128, nBase = (t & 15) * 256;
        const char* xt = X + (u64)mBase * 8192;
        const char* wt = W + (u64)nBase * 8192;

#pragma unroll
        for (int p = 0; p < 4; p++) {
            u32 sA = st0 + p * 49152;
            ld_stage(sA, sA + 16384, xt + p * 128, wt + p * 128, tid);
            asm volatile("cp.async.commit_group;" ::: "memory");
        }

#pragma unroll 1
        for (int kt = 0; kt < 64; kt++) {
            const int s = kt & 3;
            const u32 sA = st0 + s * 49152, sB = sA + 16384;
            asm volatile("cp.async.wait_group 3;" ::: "memory");
            __syncthreads();

            if (wid == 0) {
                u32 ep;
                asm volatile("{ .reg .pred p; elect.sync _|p, 0xFFFFFFFF; selp.b32 %0,1,0,p; }"
                             : "=r"(ep));
                if (ep) {
                    asm volatile("fence.proxy.async.shared::cta;" ::: "memory");
                    u64 ad = DBASE | ((u64)(sA >> 4) & 0x3FFF);
                    u64 bd = DBASE | ((u64)(sB >> 4) & 0x3FFF);
#pragma unroll
                    for (int q = 0; q < 4; q++) {
                        u32 en = (kt > 0 || q > 0) ? 1u : 0u;
                        asm volatile("{ .reg .pred p; setp.ne.u32 p, %5, 0; "
                            "tcgen05.mma.cta_group::1.kind::f16 [%0], %1, %2, %3, {%4,%4,%4,%4}, p; }"
                            :: "r"(tmem), "l"(ad + q * 2), "l"(bd + q * 2),
                               "r"(IDESC), "r"(0u), "r"(en) : "memory");
                    }
                    asm volatile("tcgen05.commit.cta_group::1.mbarrier::arrive::one.shared::cluster.b64 [%0];"
                                 :: "r"(mb + s * 8) : "memory");
                }
            }

            if (kt + 4 < 64) {
                u32 ph = (u32)((kt >> 2) & 1);
                MWAIT(mb + s * 8, ph);
                ld_stage(sA, sB, xt + (kt + 4) * 128, wt + (kt + 4) * 128, tid);
            }
            asm volatile("cp.async.commit_group;" ::: "memory");
        }

        MWAIT(mb + 24, 1u);
        asm volatile("tcgen05.fence::after_thread_sync;" ::: "memory");

        if (wid < 4) {
            float* dst = out + (u64)(mBase + wid * 32 + lid) * 4096 + nBase;
#pragma unroll
            for (int ch = 0; ch < 8; ch++) {
                u32 rr[32];
                LDTM32(rr, tmem + ch * 32);
                asm volatile("tcgen05.wait::ld.sync.aligned;" ::: "memory");
#pragma unroll
                for (int j = 0; j < 8; j++)
                    asm volatile("st.global.cs.v4.b32 [%0], {%1,%2,%3,%4};"
                                 :: "l"(dst + ch * 32 + j * 4),
                                    "r"(rr[4 * j]), "r"(rr[4 * j + 1]),
                                    "r"(rr[4 * j + 2]), "r"(rr[4 * j + 3]) : "memory");
            }
            asm volatile("tcgen05.fence::before_thread_sync;" ::: "memory");
        }
        __syncthreads();
    }

    __syncthreads();
    if (wid == 0) {
        asm volatile("tcgen05.relinquish_alloc_permit.cta_group::1.sync.aligned;");
        asm volatile("tcgen05.dealloc.cta_group::1.sync.aligned.b32 %0, %1;"
                     :: "r"(tmem), "r"(256u));
    }
}

// ---------------- gemm5c: 2 M-tiles, decoupled cp.async pipeline ----------------
extern "C" __global__ void __launch_bounds__(256, 1)
gemm5c(const char* __restrict__ X, const char* __restrict__ W,
       float* __restrict__ out) {
    extern __shared__ char sm[];
    u32 base = (sm2u32(sm) + 1023) & ~1023u;
    const u32 tptr = base;
    const u32 mb = base + 16;
    const u32 st0 = base + 1024;
    const int tid = threadIdx.x, wid = tid >> 5, lid = tid & 31;

    if (wid == 0)
        asm volatile("tcgen05.alloc.cta_group::1.sync.aligned.shared::cta.b32 [%0], %1;"
                     :: "r"(tptr), "r"(512u) : "memory");
    if (tid == 0) {
#pragma unroll
        for (int s = 0; s < 3; s++)
            asm volatile("mbarrier.init.shared.b64 [%0], %1;"
                         :: "r"(mb + s * 8), "r"(1u) : "memory");
    }
    __syncthreads();
    u32 tmem; asm volatile("ld.shared.b32 %0,[%1];" : "=r"(tmem) : "r"(tptr));

    const u64 DBASE = (2ull << 61) | (1ull << 46) | (64ull << 32) | (1ull << 16);
    const u32 IDESC = (1u << 4) | (32u << 17) | (8u << 24);

    int bp1 = 0, bp2 = 0;

#pragma unroll 1
    for (int t = blockIdx.x; t < 512; t += gridDim.x) {
        const int mBase = (t >> 4) * 256, nBase = (t & 15) * 256;
        const char* x0 = X + (u64)mBase * 8192;
        const char* x1 = x0 + 1048576;
        const char* wt = W + (u64)nBase * 8192;

#pragma unroll
        for (int p = 0; p < 2; p++) {
            u32 sA0 = st0 + p * 65536;
            ld_sub(sA0,         x0 + p * 128, tid, 4);
            ld_sub(sA0 + 16384, x1 + p * 128, tid, 4);
            ld_sub(sA0 + 32768, wt + p * 128, tid, 8);
            asm volatile("cp.async.commit_group;" ::: "memory");
        }

#pragma unroll 1
        for (int kt = 0; kt < 64; kt++) {
            const int kdiv = kt / 3;
            const int s = kt - kdiv * 3;
            const u32 sA0 = st0 + s * 65536, sA1 = sA0 + 16384, sB = sA0 + 32768;
            asm volatile("cp.async.wait_group 1;" ::: "memory");
            __syncthreads();

            if (wid == 0) {
                u32 ep;
                asm volatile("{ .reg .pred p; elect.sync _|p, 0xFFFFFFFF; selp.b32 %0,1,0,p; }"
                             : "=r"(ep));
                if (ep) {
                    asm volatile("fence.proxy.async.shared::cta;" ::: "memory");
                    u64 a0 = DBASE | ((u64)(sA0 >> 4) & 0x3FFF);
                    u64 a1 = DBASE | ((u64)(sA1 >> 4) & 0x3FFF);
                    u64 bd = DBASE | ((u64)(sB >> 4) & 0x3FFF);
#pragma unroll
                    for (int q = 0; q < 4; q++) {
                        u32 en = (kt > 0 || q > 0) ? 1u : 0u;
                        MMA8(tmem, a0 + q * 2, a1 + q * 2, bd + q * 2, IDESC, en);
                    }
                    asm volatile("tcgen05.commit.cta_group::1.mbarrier::arrive::one.shared::cluster.b64 [%0];"
                                 :: "r"(mb + s * 8) : "memory");
                }
            }

            if (kt + 2 < 64) {
                const int sd = (kt + 2) - ((kt + 2) / 3) * 3;
                const u32 dA0 = st0 + sd * 65536;
                if (kt >= 1) {
                    const int kp = kt - 1;
                    const int kdv = kp / 3;
                    const int sp = kp - kdv * 3;
                    int bps = (sp == 0) ? 0 : ((sp == 1) ? bp1 : bp2);
                    u32 ph = (u32)(bps ^ (kdv & 1));
                    MWAIT(mb + sp * 8, ph);
                }
                ld_sub(dA0,         x0 + (kt + 2) * 128, tid, 4);
                ld_sub(dA0 + 16384, x1 + (kt + 2) * 128, tid, 4);
                ld_sub(dA0 + 32768, wt + (kt + 2) * 128, tid, 8);
            }
            asm volatile("cp.async.commit_group;" ::: "memory");
        }

        MWAIT(mb, 1u);
        asm volatile("tcgen05.fence::after_thread_sync;" ::: "memory");

        {
            const int half = wid >> 2, wr = wid & 3;
            float* dst = out + (u64)(mBase + half * 128 + wr * 32 + lid) * 4096 + nBase;
            const u32 tm = tmem + half * 256;
#pragma unroll
            for (int ch = 0; ch < 8; ch++) {
                u32 rr[32];
                LDTM32(rr, tm + ch * 32);
                asm volatile("tcgen05.wait::ld.sync.aligned;" ::: "memory");
#pragma unroll
                for (int j = 0; j < 8; j++)
                    asm volatile("st.global.cs.v4.b32 [%0], {%1,%2,%3,%4};"
                                 :: "l"(dst + ch * 32 + j * 4),
                                    "r"(rr[4 * j]), "r"(rr[4 * j + 1]),
                                    "r"(rr[4 * j + 2]), "r"(rr[4 * j + 3]) : "memory");
            }
            asm volatile("tcgen05.fence::before_thread_sync;" ::: "memory");
        }
        __syncthreads();
        bp1 ^= 1; bp2 ^= 1;
    }

    __syncthreads();
    if (wid == 0) {
        asm volatile("tcgen05.relinquish_alloc_permit.cta_group::1.sync.aligned;");
        asm volatile("tcgen05.dealloc.cta_group::1.sync.aligned.b32 %0, %1;"
                     :: "r"(tmem), "r"(512u));
    }
}

// ---------------- gemm5d: TMA + single-thread producer/consumer ----------------
extern "C" __global__ void __launch_bounds__(256, 1)
gemm5d(const void* __restrict__ tmx, const void* __restrict__ tmw,
       float* __restrict__ out) {
    extern __shared__ char sm[];
    u32 base = (sm2u32(sm) + 1023) & ~1023u;
    const u32 tptr = base;
    const u32 mbc = base + 16;
    const u32 mbf = base + 48;
    const u32 st0 = base + 1024;
    const int tid = threadIdx.x, wid = tid >> 5, lid = tid & 31;

    if (wid == 0)
        asm volatile("tcgen05.alloc.cta_group::1.sync.aligned.shared::cta.b32 [%0], %1;"
                     :: "r"(tptr), "r"(512u) : "memory");
    if (tid == 0) {
#pragma unroll
        for (int s = 0; s < 3; s++) {
            asm volatile("mbarrier.init.shared.b64 [%0], %1;"
                         :: "r"(mbc + s * 8), "r"(1u) : "memory");
            asm volatile("mbarrier.init.shared.b64 [%0], %1;"
                         :: "r"(mbf + s * 8), "r"(1u) : "memory");
        }
        asm volatile("prefetch.tensormap [%0];" :: "l"(tmx));
        asm volatile("prefetch.tensormap [%0];" :: "l"(tmw));
    }
    __syncthreads();
    u32 tmem; asm volatile("ld.shared.b32 %0,[%1];" : "=r"(tmem) : "r"(tptr));

    const u64 DBASE = (2ull << 61) | (1ull << 46) | (64ull << 32) | (1ull << 16);
    const u32 IDESC = (1u << 4) | (32u << 17) | (8u << 24);

    int bp1 = 0, bp2 = 0;
    int pf0 = 0, pf1 = 0, pf2 = 0;

#pragma unroll 1
    for (int t = blockIdx.x; t < 512; t += gridDim.x) {
        const int mBase = (t >> 4) * 256, nBase = (t & 15) * 256;

        if (wid == 0) {
            u32 ep;
            asm volatile("{ .reg .pred p; elect.sync _|p, 0xFFFFFFFF; selp.b32 %0,1,0,p; }"
                         : "=r"(ep));
            if (ep) {
#pragma unroll
                for (int p = 0; p < 2; p++) {
                    u32 sl = st0 + p * 65536;
                    EXPECT_TX(mbf + p * 8, 65536u);
                    TMA2D(sl,         tmx, p * 128, mBase,       mbf + p * 8);
                    TMA2D(sl + 16384, tmx, p * 128, mBase + 128, mbf + p * 8);
                    TMA2D(sl + 32768, tmw, p * 128, nBase,       mbf + p * 8);
                }
#pragma unroll 1
                for (int kt = 0; kt < 64; kt++) {
                    const int kdiv = kt / 3;
                    const int s = kt - kdiv * 3;
                    const u32 sA0 = st0 + s * 65536, sA1 = sA0 + 16384, sB = sA0 + 32768;
                    u32 ph;
                    if (s == 0) { ph = (u32)pf0; pf0 ^= 1; }
                    else if (s == 1) { ph = (u32)pf1; pf1 ^= 1; }
                    else { ph = (u32)pf2; pf2 ^= 1; }
                    MWAIT(mbf + s * 8, ph);

                    u64 a0 = DBASE | ((u64)(sA0 >> 4) & 0x3FFF);
                    u64 a1 = DBASE | ((u64)(sA1 >> 4) & 0x3FFF);
                    u64 bd = DBASE | ((u64)(sB >> 4) & 0x3FFF);
#pragma unroll
                    for (int q = 0; q < 4; q++) {
                        u32 en = (kt > 0 || q > 0) ? 1u : 0u;
                        MMA8(tmem, a0 + q * 2, a1 + q * 2, bd + q * 2, IDESC, en);
                    }
                    asm volatile("tcgen05.commit.cta_group::1.mbarrier::arrive::one.shared::cluster.b64 [%0];"
                                 :: "r"(mbc + s * 8) : "memory");

                    if (kt + 2 < 64) {
                        const int sd = (kt + 2) - ((kt + 2) / 3) * 3;
                        const u32 dA0 = st0 + sd * 65536;
                        if (kt >= 1) {
                            const int kp = kt - 1;
                            const int kdv = kp / 3;
                            const int sp = kp - kdv * 3;
                            int bps = (sp == 0) ? 0 : ((sp == 1) ? bp1 : bp2);
                            u32 p2 = (u32)(bps ^ (kdv & 1));
                            MWAIT(mbc + sp * 8, p2);
                        }
                        EXPECT_TX(mbf + sd * 8, 65536u);
                        TMA2D(dA0,         tmx, (kt + 2) * 128, mBase,       mbf + sd * 8);
                        TMA2D(dA0 + 16384, tmx, (kt + 2) * 128, mBase + 128, mbf + sd * 8);
                        TMA2D(dA0 + 32768, tmw, (kt + 2) * 128, nBase,       mbf + sd * 8);
                    }
                }
            }
        }

        MWAIT(mbc, 1u);
        asm volatile("tcgen05.fence::after_thread_sync;" ::: "memory");

        {
            const int half = wid >> 2, wr = wid & 3;
            float* dst = out + (u64)(mBase + half * 128 + wr * 32 + lid) * 4096 + nBase;
            const u32 tm = tmem + half * 256;
#pragma unroll
            for (int ch = 0; ch < 8; ch++) {
                u32 rr[32];
                LDTM32(rr, tm + ch * 32);
                asm volatile("tcgen05.wait::ld.sync.aligned;" ::: "memory");
#pragma unroll
                for (int j = 0; j < 8; j++)
                    asm volatile("st.global.cs.v4.b32 [%0], {%1,%2,%3,%4};"
                                 :: "l"(dst + ch * 32 + j * 4),
                                    "r"(rr[4 * j]), "r"(rr[4 * j + 1]),
                                    "r"(rr[4 * j + 2]), "r"(rr[4 * j + 3]) : "memory");
            }
            asm volatile("tcgen05.fence::before_thread_sync;" ::: "memory");
        }
        __syncthreads();
        bp1 ^= 1; bp2 ^= 1;
    }

    __syncthreads();
    if (wid == 0) {
        asm volatile("tcgen05.relinquish_alloc_permit.cta_group::1.sync.aligned;");
        asm volatile("tcgen05.dealloc.cta_group::1.sync.aligned.b32 %0, %1;"
                     :: "r"(tmem), "r"(512u));
    }
}

// ---------------- gemm6: cluster-2, B-tile TMA multicast ----------------
// Pair = 2 CTAs, same n-tile, adjacent m-supers. Each rank loads its 128-row
// half of B and multicasts; both CTAs receive the full 256-row B tile.
// Per-CTA L2 traffic drops from 64KB to 48KB per ktile.
extern "C" __global__ void __launch_bounds__(256, 1)
gemm6(const void* __restrict__ tmx, const void* __restrict__ tmw2,
      float* __restrict__ out) {
    extern __shared__ char sm[];
    u32 base = (sm2u32(sm) + 1023) & ~1023u;
    const u32 tptr = base;
    const u32 mbc = base + 16;    // commit barriers x3 (count 1)
    const u32 mbf = base + 48;    // TMA full barriers x3 (count 1, tx)
    const u32 mbb = base + 80;    // slot-free barriers x3 (count 2)
    const u32 st0 = base + 1024;
    const int tid = threadIdx.x, wid = tid >> 5, lid = tid & 31;

    u32 rank; asm("mov.u32 %0, %%cluster_ctarank;" : "=r"(rank));
    const u32 peer = rank ^ 1u;
    const int cid = blockIdx.x >> 1;

    if (wid == 0)
        asm volatile("tcgen05.alloc.cta_group::1.sync.aligned.shared::cta.b32 [%0], %1;"
                     :: "r"(tptr), "r"(512u) : "memory");
    if (tid == 0) {
#pragma unroll
        for (int s = 0; s < 3; s++) {
            asm volatile("mbarrier.init.shared.b64 [%0], %1;"
                         :: "r"(mbc + s * 8), "r"(1u) : "memory");
            asm volatile("mbarrier.init.shared.b64 [%0], %1;"
                         :: "r"(mbf + s * 8), "r"(1u) : "memory");
            asm volatile("mbarrier.init.shared.b64 [%0], %1;"
                         :: "r"(mbb + s * 8), "r"(2u) : "memory");
        }
        asm volatile("prefetch.tensormap [%0];" :: "l"(tmx));
        asm volatile("prefetch.tensormap [%0];" :: "l"(tmw2));
    }
    __syncthreads();
    asm volatile("barrier.cluster.arrive.aligned;" ::: "memory");
    asm volatile("barrier.cluster.wait.aligned;" ::: "memory");
    u32 tmem; asm volatile("ld.shared.b32 %0,[%1];" : "=r"(tmem) : "r"(tptr));

    const u64 DBASE = (2ull << 61) | (1ull << 46) | (64ull << 32) | (1ull << 16);
    const u32 IDESC = (1u << 4) | (32u << 17) | (8u << 24);

    int bp1 = 0, bp2 = 0;
    int pf0 = 0, pf1 = 0, pf2 = 0;
    int bf0 = 0, bf1 = 0, bf2 = 0;

#pragma unroll 1
    for (int p = cid; p < 256; p += 74) {
        const int mBase = ((p >> 4) * 2 + (int)rank) * 256;
        const int nBase = (p & 15) * 256;

        // all CTAs of the pair: previous tile fully drained before the peer
        // may multicast into our smem slots
        asm volatile("barrier.cluster.arrive.aligned;" ::: "memory");
        asm volatile("barrier.cluster.wait.aligned;" ::: "memory");

        if (wid == 0) {
            u32 ep;
            asm volatile("{ .reg .pred p; elect.sync _|p, 0xFFFFFFFF; selp.b32 %0,1,0,p; }"
                         : "=r"(ep));
            if (ep) {
#pragma unroll
                for (int pi = 0; pi < 2; pi++) {
                    u32 sl = st0 + pi * 65536;
                    EXPECT_TX(mbf + pi * 8, 65536u);
                    TMA2D(sl,         tmx, pi * 128, mBase,       mbf + pi * 8);
                    TMA2D(sl + 16384, tmx, pi * 128, mBase + 128, mbf + pi * 8);
                    TMA2D_MC(sl + 32768 + rank * 16384, tmw2,
                             pi * 128, nBase + (int)rank * 128, mbf + pi * 8, 3);
                }
#pragma unroll 1
                for (int kt = 0; kt < 64; kt++) {
                    const int kdiv = kt / 3;
                    const int s = kt - kdiv * 3;
                    const u32 sA0 = st0 + s * 65536, sA1 = sA0 + 16384, sB = sA0 + 32768;
                    u32 ph;
                    if (s == 0) { ph = (u32)pf0; pf0 ^= 1; }
                    else if (s == 1) { ph = (u32)pf1; pf1 ^= 1; }
                    else { ph = (u32)pf2; pf2 ^= 1; }
                    MWAIT(mbf + s * 8, ph);

                    u64 a0 = DBASE | ((u64)(sA0 >> 4) & 0x3FFF);
                    u64 a1 = DBASE | ((u64)(sA1 >> 4) & 0x3FFF);
                    u64 bd = DBASE | ((u64)(sB >> 4) & 0x3FFF);
#pragma unroll
                    for (int q = 0; q < 4; q++) {
                        u32 en = (kt > 0 || q > 0) ? 1u : 0u;
                        MMA8(tmem, a0 + q * 2, a1 + q * 2, bd + q * 2, IDESC, en);
                    }
                    asm volatile("tcgen05.commit.cta_group::1.mbarrier::arrive::one.shared::cluster.b64 [%0];"
                                 :: "r"(mbc + s * 8) : "memory");

                    if (kt + 2 < 64) {
                        const int sd = (kt + 2) - ((kt + 2) / 3) * 3;
                        const u32 dA0 = st0 + sd * 65536;
                        if (kt >= 1) {
                            const int kp = kt - 1;
                            const int kdv = kp / 3;
                            const int sp = kp - kdv * 3;   // == sd
                            int bps = (sp == 0) ? 0 : ((sp == 1) ? bp1 : bp2);
                            u32 p2 = (u32)(bps ^ (kdv & 1));
                            MWAIT(mbc + sp * 8, p2);
                            // announce slot free: arrive locally + on peer
                            asm volatile("mbarrier.arrive.shared.b64 _, [%0];"
                                         :: "r"(mbb + sp * 8) : "memory");
                            asm volatile("{ .reg .b32 ra; mapa.shared::cluster.u32 ra, %0, %1; "
                                         "mbarrier.arrive.shared::cluster.b64 _, [ra]; }"
                                         :: "r"(mbb + sp * 8), "r"(peer) : "memory");
                            u32 bph;
                            if (sp == 0) { bph = (u32)bf0; bf0 ^= 1; }
                            else if (sp == 1) { bph = (u32)bf1; bf1 ^= 1; }
                            else { bph = (u32)bf2; bf2 ^= 1; }
                            MWAIT(mbb + sp * 8, bph);
                        }
                        EXPECT_TX(mbf + sd * 8, 65536u);
                        TMA2D(dA0,         tmx, (kt + 2) * 128, mBase,       mbf + sd * 8);
                        TMA2D(dA0 + 16384, tmx, (kt + 2) * 128, mBase + 128, mbf + sd * 8);
                        TMA2D_MC(dA0 + 32768 + rank * 16384, tmw2,
                                 (kt + 2) * 128, nBase + (int)rank * 128, mbf + sd * 8, 3);
                    }
                }
            }
        }

        MWAIT(mbc, 1u);
        asm volatile("tcgen05.fence::after_thread_sync;" ::: "memory");

        {
            const int half = wid >> 2, wr = wid & 3;
            float* dst = out + (u64)(mBase + half * 128 + wr * 32 + lid) * 4096 + nBase;
            const u32 tm = tmem + half * 256;
#pragma unroll
            for (int ch = 0; ch < 8; ch++) {
                u32 rr[32];
                LDTM32(rr, tm + ch * 32);
                asm volatile("tcgen05.wait::ld.sync.aligned;" ::: "memory");
#pragma unroll
                for (int j = 0; j < 8; j++)
                    asm volatile("st.global.cs.v4.b32 [%0], {%1,%2,%3,%4};"
                                 :: "l"(dst + ch * 32 + j * 4),
                                    "r"(rr[4 * j]), "r"(rr[4 * j + 1]),
                                    "r"(rr[4 * j + 2]), "r"(rr[4 * j + 3]) : "memory");
            }
            asm volatile("tcgen05.fence::before_thread_sync;" ::: "memory");
        }
        __syncthreads();
        bp1 ^= 1; bp2 ^= 1;
    }

    __syncthreads();
    if (wid == 0) {
        asm volatile("tcgen05.relinquish_alloc_permit.cta_group::1.sync.aligned;");
        asm volatile("tcgen05.dealloc.cta_group::1.sync.aligned.b32 %0, %1;"
                     :: "r"(tmem), "r"(512u));
    }
    asm volatile("barrier.cluster.arrive.aligned;" ::: "memory");
    asm volatile("barrier.cluster.wait.aligned;" ::: "memory");
}

// ---------------- wbuild: fused LoRA GEMM + NF4 dequant ----------------
extern "C" __global__ void __launch_bounds__(256, 1)
wbuild(const int* __restrict__ qw, const float* __restrict__ am,
       const u16* __restrict__ lb, const u16* __restrict__ lat,
       u16* __restrict__ w) {
    extern __shared__ char sm[];
    u32 base = (sm2u32(sm) + 1023) & ~1023u;
    const u32 tptr = base;
    const u32 mb = base + 16;
    const u32 sa = base + 1024;
    const u32 sb = sa + 16384;
    const int tid = threadIdx.x, wid = tid >> 5, lid = tid & 31;
    const int ti = blockIdx.x;
    const int o0 = (ti >> 4) * 128, i0 = (ti & 15) * 256;

    if (wid == 0)
        asm volatile("tcgen05.alloc.cta_group::1.sync.aligned.shared::cta.b32 [%0], %1;"
                     :: "r"(tptr), "r"(256u) : "memory");
    if (tid == 0)
        asm volatile("mbarrier.init.shared.b64 [%0], %1;" :: "r"(mb), "r"(1u) : "memory");
    __syncthreads();
    u32 tmem; asm volatile("ld.shared.b32 %0,[%1];" : "=r"(tmem) : "r"(tptr));

#pragma unroll
    for (int r = 0; r < 4; r++) {
        int i = tid + r * 256; int row = i >> 3, c = i & 7;
        u32 off = (u32)(row * 128 + ((c * 16) ^ ((row & 7) << 4)));
        asm volatile("cp.async.cg.shared.global [%0], [%1], 16;"
                     :: "r"(sa + off), "l"((const char*)lb + (u64)(o0 + row) * 128 + c * 16));
    }
#pragma unroll
    for (int r = 0; r < 8; r++) {
        int i = tid + r * 256; int row = i >> 3, c = i & 7;
        u32 off = (u32)(row * 128 + ((c * 16) ^ ((row & 7) << 4)));
        asm volatile("cp.async.cg.shared.global [%0], [%1], 16;"
                     :: "r"(sb + off), "l"((const char*)lat + (u64)(i0 + row) * 128 + c * 16));
    }
    asm volatile("cp.async.commit_group;" ::: "memory");
    asm volatile("cp.async.wait_group 0;" ::: "memory");
    __syncthreads();

    const u64 DBASE = (2ull << 61) | (1ull << 46) | (64ull << 32) | (1ull << 16);
    const u32 IDESC = (1u << 4) | (32u << 17) | (8u << 24);

    if (wid == 0) {
        u32 ep;
        asm volatile("{ .reg .pred p; elect.sync _|p, 0xFFFFFFFF; selp.b32 %0,1,0,p; }"
                     : "=r"(ep));
        if (ep) {
            asm volatile("fence.proxy.async.shared::cta;" ::: "memory");
            u64 ad = DBASE | ((u64)(sa >> 4) & 0x3FFF);
            u64 bd = DBASE | ((u64)(sb >> 4) & 0x3FFF);
#pragma unroll
            for (int q = 0; q < 4; q++) {
                u32 en = (q > 0) ? 1u : 0u;
                asm volatile("{ .reg .pred p; setp.ne.u32 p, %5, 0; "
                    "tcgen05.mma.cta_group::1.kind::f16 [%0], %1, %2, %3, {%4,%4,%4,%4}, p; }"
                    :: "r"(tmem), "l"(ad + q * 2), "l"(bd + q * 2),
                       "r"(IDESC), "r"(0u), "r"(en) : "memory");
            }
            asm volatile("tcgen05.commit.cta_group::1.mbarrier::arrive::one.shared::cluster.b64 [%0];"
                         :: "r"(mb) : "memory");
        }
    }
    __syncthreads();
    MWAIT(mb, 0u);
    asm volatile("tcgen05.fence::after_thread_sync;" ::: "memory");

    const int half = wid >> 2, wr = wid & 3;
    const int o = o0 + wr * 32 + lid;
#pragma unroll
    for (int c4 = 0; c4 < 4; c4++) {
        u32 rr[32];
        LDTM32(rr, tmem + half * 128 + c4 * 32);
        asm volatile("tcgen05.wait::ld.sync.aligned;" ::: "memory");
        const u64 k = (u64)o * 4096 + (u64)(i0 + half * 128 + c4 * 32);
        const float a = am[k >> 6];
        const int4* qp = (const int4*)qw + (k >> 3);
        u32 ov[16];
#pragma unroll
        for (int u = 0; u < 4; u++) {
            int4 qv = qp[u];
            int e[8] = {qv.x & 15, (qv.x >> 4) & 15, qv.y & 15, (qv.y >> 4) & 15,
                        qv.z & 15, (qv.z >> 4) & 15, qv.w & 15, (qv.w >> 4) & 15};
#pragma unroll
            for (int j = 0; j < 4; j++) {
                union { u32 u_; float f_; } c0, c1;
                c0.u_ = rr[u * 8 + 2 * j];
                c1.u_ = rr[u * 8 + 2 * j + 1];
                float w0 = NF4D[e[2 * j]] * a + c0.f_;
                float w1 = NF4D[e[2 * j + 1]] * a + c1.f_;
                asm("cvt.rn.f16x2.f32 %0, %1, %2;" : "=r"(ov[u * 4 + j]) : "f"(w1), "f"(w0));
            }
        }
        char* wp = (char*)w + k * 2;
#pragma unroll
        for (int j = 0; j < 4; j++)
            asm volatile("st.global.cs.v4.b32 [%0], {%1,%2,%3,%4};"
                         :: "l"(wp + j * 16), "r"(ov[4 * j]), "r"(ov[4 * j + 1]),
                            "r"(ov[4 * j + 2]), "r"(ov[4 * j + 3]) : "memory");
    }
    asm volatile("tcgen05.fence::before_thread_sync;" ::: "memory");
    __syncthreads();
    if (wid == 0) {
        asm volatile("tcgen05.relinquish_alloc_permit.cta_group::1.sync.aligned;");
        asm volatile("tcgen05.dealloc.cta_group::1.sync.aligned.b32 %0, %1;"
                     :: "r"(tmem), "r"(256u));
    }
}
)NVSRC";

// --- driver/nvrtc plumbing ---
typedef int (*nvrtcCreateProgram_t)(void**, const char*, const char*, int,
                                    const char* const*, const char* const*);
typedef int (*nvrtcCompileProgram_t)(void*, int, const char* const*);
typedef int (*nvrtcGetCUBINSize_t)(void*, size_t*);
typedef int (*nvrtcGetCUBIN_t)(void*, char*);
typedef int (*cuInit_t)(unsigned);
typedef int (*cuDevicePrimaryCtxRetain_t)(void**, int);
typedef int (*cuCtxSetCurrent_t)(void*);
typedef int (*cuModuleLoadDataEx_t)(void**, const void*, unsigned, int*, void**);
typedef int (*cuModuleGetFunction_t)(void**, void*, const char*);
typedef int (*cuModuleGetGlobal_t)(unsigned long long*, size_t*, void*, const char*);
typedef int (*cuFuncSetAttribute_t)(void*, int, int);
typedef int (*cuLaunchKernel_t)(void*, unsigned, unsigned, unsigned,
                                unsigned, unsigned, unsigned,
                                unsigned, void*, void**, void**);
typedef int (*cuCtxSynchronize_t)(void);
typedef int (*cuMemcpyDtoH_t)(void*, unsigned long long, size_t);
typedef int (*cuMemcpyHtoD_t)(unsigned long long, const void*, size_t);
typedef int (*cuTensorMapEncodeTiled_t)(void*, int, unsigned, void*,
                                        const unsigned long long*,
                                        const unsigned long long*,
                                        const unsigned*, const unsigned*,
                                        int, int, int, int);

// mirror of CUlaunchConfig / CUlaunchAttribute
struct DrvLaunchAttr { int id; int pad; unsigned long long v[8]; };
struct DrvLaunchCfg {
    unsigned gx, gy, gz, bx, by, bz, smem;
    void* stream;
    DrvLaunchAttr* attrs;
    unsigned numAttrs;
};
typedef int (*cuLaunchKernelEx_t)(const DrvLaunchCfg*, void*, void**, void**);

#if defined(CUDA_API_PER_THREAD_DEFAULT_STREAM) || defined(__CUDA_API_PER_THREAD_DEFAULT_STREAM)
#define DRV_STREAM ((void*)0x2)
#else
#define DRV_STREAM ((void*)0x1)
#endif

static bool g_ok_gemm = false, g_ok_wb = false;
static int g_mode = 0;  // 1 = ptr(5c/5), 2 = tma(5d), 3 = cluster(6)
static cuLaunchKernel_t p_cuLaunchKernel = nullptr;
static cuLaunchKernelEx_t p_cuLaunchEx = nullptr;
static void* g_fn_gemm = nullptr;
static void* g_fn_wbuild = nullptr;
static unsigned long long g_gx = 0, g_gw = 0, g_glb = 0, g_glat = 0;
static unsigned long long g_tmx = 0, g_tmw = 0, g_tmw2 = 0;
constexpr int SMEM5 = 198656;
constexpr int SMEMW = 51200;

static float h2f(uint16_t h) {
    uint32_t s = (h >> 15) & 1, e = (h >> 10) & 31, m = h & 1023;
    uint32_t f;
    if (e == 0) {
        if (m == 0) f = s << 31;
        else {
            e = 127 - 15 + 1;
            while (!(m & 1024)) { m <<= 1; e--; }
            m &= 1023;
            f = (s << 31) | (e << 23) | (m << 13);
        }
    } else if (e == 31) f = (s << 31) | 0x7F800000 | (m << 13);
    else f = (s << 31) | ((e - 15 + 127) << 23) | (m << 13);
    float r; memcpy(&r, &f, 4); return r;
}

static int launch_cluster(void* fn, void** args, unsigned smem) {
    static DrvLaunchAttr attr;
    memset(&attr, 0, sizeof(attr));
    attr.id = 4;  // CU_LAUNCH_ATTRIBUTE_CLUSTER_DIMENSION
    unsigned* cd = (unsigned*)attr.v;
    cd[0] = 2; cd[1] = 1; cd[2] = 1;
    DrvLaunchCfg cfg;
    cfg.gx = 148; cfg.gy = 1; cfg.gz = 1;
    cfg.bx = 256; cfg.by = 1; cfg.bz = 1;
    cfg.smem = smem;
    cfg.stream = DRV_STREAM;
    cfg.attrs = &attr;
    cfg.numAttrs = 1;
    return p_cuLaunchEx(&cfg, fn, args, nullptr);
}

static bool try_init_tcgen05() {
    void* hcu = dlopen("libcuda.so.1", RTLD_NOW | RTLD_GLOBAL);
    if (!hcu) hcu = dlopen("libcuda.so", RTLD_NOW | RTLD_GLOBAL);
    if (!hcu) return false;
    void* hnv = dlopen("libnvrtc.so.13", RTLD_NOW | RTLD_GLOBAL);
    if (!hnv) hnv = dlopen("libnvrtc.so", RTLD_NOW | RTLD_GLOBAL);
    if (!hnv) hnv = dlopen("libnvrtc.so.12", RTLD_NOW | RTLD_GLOBAL);
    if (!hnv) return false;

    auto nCreate  = (nvrtcCreateProgram_t)dlsym(hnv, "nvrtcCreateProgram");
    auto nCompile = (nvrtcCompileProgram_t)dlsym(hnv, "nvrtcCompileProgram");
    auto nCbSize  = (nvrtcGetCUBINSize_t)dlsym(hnv, "nvrtcGetCUBINSize");
    auto nCb      = (nvrtcGetCUBIN_t)dlsym(hnv, "nvrtcGetCUBIN");
    auto cInit    = (cuInit_t)dlsym(hcu, "cuInit");
    auto cRetain  = (cuDevicePrimaryCtxRetain_t)dlsym(hcu, "cuDevicePrimaryCtxRetain");
    auto cSetCur  = (cuCtxSetCurrent_t)dlsym(hcu, "cuCtxSetCurrent");
    auto cModLoad = (cuModuleLoadDataEx_t)dlsym(hcu, "cuModuleLoadDataEx");
    auto cGetFn   = (cuModuleGetFunction_t)dlsym(hcu, "cuModuleGetFunction");
    auto cGetGlb  = (cuModuleGetGlobal_t)dlsym(hcu, "cuModuleGetGlobal_v2");
    auto cSetAttr = (cuFuncSetAttribute_t)dlsym(hcu, "cuFuncSetAttribute");
    auto cLaunch  = (cuLaunchKernel_t)dlsym(hcu, "cuLaunchKernel");
    auto cSync    = (cuCtxSynchronize_t)dlsym(hcu, "cuCtxSynchronize");
    auto cD2H     = (cuMemcpyDtoH_t)dlsym(hcu, "cuMemcpyDtoH_v2");
    auto cH2D     = (cuMemcpyHtoD_t)dlsym(hcu, "cuMemcpyHtoD_v2");
    auto cTmEnc   = (cuTensorMapEncodeTiled_t)dlsym(hcu, "cuTensorMapEncodeTiled");
    auto cLEx     = (cuLaunchKernelEx_t)dlsym(hcu, "cuLaunchKernelEx");
    if (!nCreate || !nCompile || !nCbSize || !nCb || !cInit || !cRetain ||
        !cSetCur || !cModLoad || !cGetFn || !cGetGlb || !cSetAttr ||
        !cLaunch || !cSync || !cD2H)
        return false;

    if (cInit(0)) return false;
    void* ctx = nullptr;
    if (cRetain(&ctx, 0)) return false;
    if (cSetCur(ctx)) return false;

    void* prog = nullptr;
    if (nCreate(&prog, NVRTC_SRC, "gemm6.cu", 0, nullptr, nullptr)) return false;
    const char* opts[] = {"--gpu-architecture=sm_103a"};
    if (nCompile(prog, 1, opts)) return false;
    size_t cbsz = 0;
    if (nCbSize(prog, &cbsz) || cbsz == 0) return false;
    static char* cubin = new char[cbsz];
    if (nCb(prog, cubin)) return false;

    void* mod = nullptr;
    if (cModLoad(&mod, cubin, 0, nullptr, nullptr)) return false;
    void *fG5 = nullptr, *fG5c = nullptr, *fG5d = nullptr, *fG6 = nullptr;
    void *fInit = nullptr, *fWb = nullptr, *fWti = nullptr;
    if (cGetFn(&fG5, mod, "gemm5")) return false;
    if (cGetFn(&fG5c, mod, "gemm5c")) return false;
    if (cGetFn(&fG5d, mod, "gemm5d")) return false;
    if (cGetFn(&fG6, mod, "gemm6")) return false;
    if (cGetFn(&fInit, mod, "initt")) return false;
    if (cGetFn(&fWb, mod, "wbuild")) return false;
    if (cGetFn(&fWti, mod, "wtinit")) return false;
    unsigned long long gx = 0, gw = 0, gout = 0, glb = 0, glat = 0,
                       gtqw = 0, gtam = 0, tmxd = 0, tmwd = 0, tmw2d = 0;
    size_t sz;
    if (cGetGlb(&gx, &sz, mod, "GX")) return false;
    if (cGetGlb(&gw, &sz, mod, "GW")) return false;
    if (cGetGlb(&gout, &sz, mod, "GOUT")) return false;
    if (cGetGlb(&glb, &sz, mod, "GLB")) return false;
    if (cGetGlb(&glat, &sz, mod, "GLAT")) return false;
    if (cGetGlb(&gtqw, &sz, mod, "GTQW")) return false;
    if (cGetGlb(&gtam, &sz, mod, "GTAM")) return false;
    if (cGetGlb(&tmxd, &sz, mod, "TMXD")) return false;
    if (cGetGlb(&tmwd, &sz, mod, "TMWD")) return false;
    if (cGetGlb(&tmw2d, &sz, mod, "TMW2D")) return false;
    if (cSetAttr(fG5, 8, SMEM5)) return false;
    if (cSetAttr(fG5c, 8, SMEM5)) return false;
    if (cSetAttr(fG5d, 8, SMEM5)) return false;
    if (cSetAttr(fG6, 8, SMEM5)) return false;
    if (cSetAttr(fWb, 8, SMEMW)) return false;

    p_cuLaunchKernel = cLaunch;
    p_cuLaunchEx = cLEx;
    g_gx = gx; g_gw = gw; g_glb = glb; g_glat = glat;
    g_tmx = tmxd; g_tmw = tmwd; g_tmw2 = tmw2d;

    // ---- encode tensormaps (uint8, SW128) ----
    bool tma_ready = false;
    if (cTmEnc && cH2D) {
        struct { alignas(64) unsigned char b[128]; } tm;
        unsigned long long dimsX[2] = {8192ull, 8192ull};
        unsigned long long dimsW[2] = {8192ull, 4096ull};
        unsigned long long strides[1] = {8192ull};
        unsigned boxA[2] = {128u, 128u};
        unsigned boxB[2] = {128u, 256u};
        unsigned es[2] = {1u, 1u};
        do {
            memset(&tm, 0, sizeof(tm));
            if (cTmEnc(&tm, 0, 2, (void*)(uintptr_t)gx, dimsX, strides, boxA, es,
                       0, 3, 2, 0)) break;
            if (cH2D(tmxd, &tm, 128)) break;
            memset(&tm, 0, sizeof(tm));
            if (cTmEnc(&tm, 0, 2, (void*)(uintptr_t)gw, dimsW, strides, boxB, es,
                       0, 3, 2, 0)) break;
            if (cH2D(tmwd, &tm, 128)) break;
            memset(&tm, 0, sizeof(tm));
            if (cTmEnc(&tm, 0, 2, (void*)(uintptr_t)gw, dimsW, strides, boxA, es,
                       0, 3, 2, 0)) break;
            if (cH2D(tmw2d, &tm, 128)) break;
            tma_ready = true;
        } while (0);
    }

    // ---- gemm self-tests (exact integer grid) ----
    if (cLaunch(fInit, 131072, 1, 1, 256, 1, 1, 0, DRV_STREAM, nullptr, nullptr))
        return false;
    static float row[OUT_F];
    const int ms[4] = {0, 97, 4095, 8191};
    auto check_out = [&](unsigned long long gout_) -> bool {
        for (int ri = 0; ri < 4; ri++) {
            int m = ms[ri];
            if (cD2H(row, gout_ + (unsigned long long)m * OUT_F * 4, OUT_F * 4))
                return false;
            for (int n = 0; n < OUT_F; n++) {
                float ref = 0.0f;
                for (int k = 0; k < IN_F; k++) {
                    int av = (k * 131 + m * 7) % 9 - 4;
                    int bv = (k * 17 + n * 3) % 7 - 3;
                    ref += (av * 0.25f) * (bv * 0.25f);
                }
                if (fabsf(row[n] - ref) > 0.01f) return false;
            }
        }
        return true;
    };
    // gemm6 (cluster)
    if (tma_ready && p_cuLaunchEx) {
        unsigned long long px = tmxd, pw = tmw2d, po = gout;
        void* args[3] = {&px, &pw, &po};
        if (launch_cluster(fG6, args, SMEM5) == 0 && cSync() == 0 && check_out(gout)) {
            g_fn_gemm = fG6; g_ok_gemm = true; g_mode = 3;
        }
    }
    // gemm5d (TMA, no cluster)
    if (!g_ok_gemm && tma_ready) {
        unsigned long long px = tmxd, pw = tmwd, po = gout;
        void* args[3] = {&px, &pw, &po};
        if (cLaunch(fG5d, 148, 1, 1, 256, 1, 1, SMEM5, DRV_STREAM, args, nullptr) == 0 &&
            cSync() == 0 && check_out(gout)) {
            g_fn_gemm = fG5d; g_ok_gemm = true; g_mode = 2;
        }
    }
    // gemm5c / gemm5 (cp.async)
    if (!g_ok_gemm) {
        unsigned long long px = gx, pw = gw, po = gout;
        void* args[3] = {&px, &pw, &po};
        if (cLaunch(fG5c, 148, 1, 1, 256, 1, 1, SMEM5, DRV_STREAM, args, nullptr) == 0 &&
            cSync() == 0 && check_out(gout)) {
            g_fn_gemm = fG5c; g_ok_gemm = true; g_mode = 1;
        }
    }
    if (!g_ok_gemm) {
        unsigned long long px = gx, pw = gw, po = gout;
        void* args[3] = {&px, &pw, &po};
        if (cLaunch(fG5, 148, 1, 1, 256, 1, 1, SMEM5, DRV_STREAM, args, nullptr) == 0 &&
            cSync() == 0 && check_out(gout)) {
            g_fn_gemm = fG5; g_ok_gemm = true; g_mode = 1;
        }
    }
    if (!g_ok_gemm) return false;

    // ---- wbuild self-test ----
    do {
        if (cLaunch(fWti, 32768, 1, 1, 256, 1, 1, 0, DRV_STREAM, nullptr, nullptr))
            break;
        unsigned long long pq = gtqw, pa = gtam, pl = glb, pt = glat, pw2 = gw;
        void* args[5] = {&pq, &pa, &pl, &pt, &pw2};
        if (cLaunch(fWb, 512, 1, 1, 256, 1, 1, SMEMW, DRV_STREAM, args, nullptr))
            break;
        if (cSync()) break;
        static uint16_t wrow[IN_F];
        const int os[4] = {0, 1, 255, 4095};
        bool ok = true;
        for (int oi = 0; oi < 4 && ok; oi++) {
            int o = os[oi];
            if (cD2H(wrow, gw + (unsigned long long)o * IN_F * 2, IN_F * 2)) { ok = false; break; }
            for (int i = 0; i < IN_F; i++) {
                uint64_t k = (uint64_t)o * 4096 + i;
                uint64_t t = k >> 1;
                int qv = (int)((t * 37ull) & 255ull);
                int nib = (k & 1) ? (qv >> 4) & 15 : qv & 15;
                float a = (float)(((uint32_t)((k >> 6) * 13ull)) % 31u + 1u) * 0.03125f;
                float lora = 0.0f;
                for (int r = 0; r < 64; r++) {
                    float lb = (float)((int)(((uint32_t)o * 3u + r * 7u) % 17u) - 8) * 0.015625f;
                    float la = (float)((int)(((uint32_t)i * 5u + r * 11u) % 19u) - 9) * 0.015625f;
                    lora += lb * la;
                }
                float ref = NF4H[nib] * a + lora;
                if (fabsf(h2f(wrow[i]) - ref) > 0.01f) { ok = false; break; }
            }
        }
        // re-run GEMM test after wbuild clobbered GW
        if (cLaunch(fInit, 131072, 1, 1, 256, 1, 1, 0, DRV_STREAM, nullptr, nullptr))
            { g_ok_wb = false; break; }
        if (cSync()) { g_ok_wb = false; break; }
        if (ok) { g_fn_wbuild = fWb; g_ok_wb = true; }
    } while (0);

    return true;
}

__attribute__((constructor))
static void _init_drv() {
    try_init_tcgen05();
}

// ---------------------------------------------------------------------------
extern "C" void kernel_launch(void* const* d_in, const int* in_sizes, int n_in,
                              void* d_out, int out_size) {
    const float* x  = (const float*)d_in[0];
    const int*   qw = (const int*)d_in[1];
    const float* am = (const float*)d_in[2];
    const float* lA = (const float*)d_in[3];
    const float* lB = (const float*)d_in[4];
    float*       out = (float*)d_out;

    (void)in_sizes; (void)n_in; (void)out_size;

    if (g_ok_gemm) {
        __half* xh = (__half*)(uintptr_t)g_gx;
        __half* wh = (__half*)(uintptr_t)g_gw;

        convert_x_kernel<<<(M_ROWS * IN_F / 8) / 256, 256>>>(x, xh);

        if (g_ok_wb) {
            cvt_lb_kernel<<<256, 256>>>(lB, (__half*)(uintptr_t)g_glb);
            cvt_lat_kernel<<<64, 256>>>(lA, (__half*)(uintptr_t)g_glat);
            unsigned long long pq = (unsigned long long)(uintptr_t)qw;
            unsigned long long pa = (unsigned long long)(uintptr_t)am;
            unsigned long long pl = g_glb, pt = g_glat, pw = g_gw;
            void* args[5] = {&pq, &pa, &pl, &pt, &pw};
            p_cuLaunchKernel(g_fn_wbuild, 512, 1, 1, 256, 1, 1, SMEMW,
                             DRV_STREAM, args, nullptr);
        } else {
            build_weff_kernel<<<dim3(IN_F / 128, OUT_F / 64), 256>>>(qw, am, lA, lB, wh);
        }

        void* po = (void*)out;
        if (g_mode == 3) {
            unsigned long long ptx = g_tmx, ptw = g_tmw2;
            void* args[3] = {&ptx, &ptw, &po};
            launch_cluster(g_fn_gemm, args, SMEM5);
        } else if (g_mode == 2) {
            unsigned long long ptx = g_tmx, ptw = g_tmw;
            void* args[3] = {&ptx, &ptw, &po};
            p_cuLaunchKernel(g_fn_gemm, 148, 1, 1, 256, 1, 1, SMEM5,
                             DRV_STREAM, args, nullptr);
        } else {
            unsigned long long px = g_gx, pw2 = g_gw;
            void* args[3] = {&px, &pw2, &po};
            p_cuLaunchKernel(g_fn_gemm, 148, 1, 1, 256, 1, 1, SMEM5,
                             DRV_STREAM, args, nullptr);
        }
    } else {
        __half* xh; __half* wh;
        cudaGetSymbolAddress((void**)&xh, g_Xh);
        cudaGetSymbolAddress((void**)&wh, g_Wh);
        convert_x_kernel<<<(M_ROWS * IN_F / 8) / 256, 256>>>(x, xh);
        build_weff_kernel<<<dim3(IN_F / 128, OUT_F / 64), 256>>>(qw, am, lA, lB, wh);
        cudaFuncSetAttribute(gemm_f16_kernel,
                             cudaFuncAttributeMaxDynamicSharedMemorySize, SMEM_TOTAL);
        gemm_f16_kernel<<<148, 512, SMEM_TOTAL>>>(xh, wh, out);
    }
}

// round 12
// speedup vs baseline: 1.0098x; 1.0038x over previous
#include <cuda_runtime.h>
#include <cuda_fp16.h>
#include <cstdint>
#include <cstdio>
#include <cstring>
#include <cmath>
#include <dlfcn.h>

#define IN_F   4096
#define OUT_F  4096
#define M_ROWS 8192

// Host-module fp16 scratch (used by the host fallback path).
__device__ __half g_Xh[(size_t)M_ROWS * IN_F];
__device__ __half g_Wh[(size_t)OUT_F * IN_F];

__constant__ float NF4[16] = {
    -1.0f, -0.6961928009986877f, -0.5250730514526367f, -0.39491748809814453f,
    -0.28444138169288635f, -0.18477343022823334f, -0.09105003625154495f, 0.0f,
    0.07958029955625534f, 0.16093020141124725f, 0.24611230194568634f,
    0.33791524171829224f, 0.4407098889350891f, 0.5626170039176941f,
    0.7229568362236023f, 1.0f
};

static const float NF4H[16] = {
    -1.0f, -0.6961928009986877f, -0.5250730514526367f, -0.39491748809814453f,
    -0.28444138169288635f, -0.18477343022823334f, -0.09105003625154495f, 0.0f,
    0.07958029955625534f, 0.16093020141124725f, 0.24611230194568634f,
    0.33791524171829224f, 0.4407098889350891f, 0.5626170039176941f,
    0.7229568362236023f, 1.0f
};

__device__ __forceinline__ uint32_t smem_u32(const void* p) {
    uint32_t a;
    asm("{ .reg .u64 t; cvta.to.shared.u64 t, %1; cvt.u32.u64 %0, t; }" : "=r"(a) : "l"(p));
    return a;
}

// ---------------------------------------------------------------------------
// Kernel A: convert x (fp32) -> dst (fp16) row-major. 8 elems/thread.
// ---------------------------------------------------------------------------
__global__ void convert_x_kernel(const float* __restrict__ x, __half* __restrict__ dst) {
    size_t i = ((size_t)blockIdx.x * 256 + threadIdx.x) * 8;
    float4 v0 = *(const float4*)(x + i);
    float4 v1 = *(const float4*)(x + i + 4);
    __half2 h0 = __floats2half2_rn(v0.x, v0.y);
    __half2 h1 = __floats2half2_rn(v0.z, v0.w);
    __half2 h2 = __floats2half2_rn(v1.x, v1.y);
    __half2 h3 = __floats2half2_rn(v1.z, v1.w);
    uint4 o;
    o.x = *(uint32_t*)&h0; o.y = *(uint32_t*)&h1;
    o.z = *(uint32_t*)&h2; o.w = *(uint32_t*)&h3;
    *(uint4*)&dst[i] = o;
}

// Kernel A': convert x -> TILED layout: tile (m>>7, k>>6) contiguous 16KB SW128.
__global__ void convert_x_tiled_kernel(const float* __restrict__ x, char* __restrict__ dst) {
    size_t i = ((size_t)blockIdx.x * 256 + threadIdx.x) * 8;
    float4 v0 = *(const float4*)(x + i);
    float4 v1 = *(const float4*)(x + i + 4);
    __half2 h0 = __floats2half2_rn(v0.x, v0.y);
    __half2 h1 = __floats2half2_rn(v0.z, v0.w);
    __half2 h2 = __floats2half2_rn(v1.x, v1.y);
    __half2 h3 = __floats2half2_rn(v1.z, v1.w);
    uint4 o;
    o.x = *(uint32_t*)&h0; o.y = *(uint32_t*)&h1;
    o.z = *(uint32_t*)&h2; o.w = *(uint32_t*)&h3;
    const uint32_t m = (uint32_t)(i >> 12), k = (uint32_t)(i & 4095);
    uint32_t off = (m & 127) * 128 + (k & 63) * 2;
    off = off ^ ((off >> 3) & 0x70);
    const size_t boff = ((size_t)((m >> 7) * 64 + (k >> 6))) * 16384 + off;
    *(uint4*)(dst + boff) = o;
}

// lora_B [4096][64] fp32 -> fp16 same layout
__global__ void cvt_lb_kernel(const float* __restrict__ lB, __half* __restrict__ lb) {
    size_t i = ((size_t)blockIdx.x * 256 + threadIdx.x) * 4;
    float4 v = *(const float4*)(lB + i);
    __half h[4] = {__float2half_rn(v.x), __float2half_rn(v.y),
                   __float2half_rn(v.z), __float2half_rn(v.w)};
    *(uint2*)&lb[i] = *(uint2*)h;
}

// lora_A [64][4096] fp32 -> lat [4096][64] fp16 (transpose)
__global__ void cvt_lat_kernel(const float* __restrict__ lA, __half* __restrict__ lat) {
    __shared__ float s[64][65];
    const int tid = threadIdx.x;
    const int i0 = blockIdx.x * 64;
    for (int idx = tid; idx < 4096; idx += 256) {
        int r = idx >> 6, ii = idx & 63;
        s[r][ii] = lA[r * IN_F + i0 + ii];
    }
    __syncthreads();
    int ii = tid >> 2, rs = (tid & 3) * 16;
    __half h[16];
#pragma unroll
    for (int j = 0; j < 16; j++) h[j] = __float2half_rn(s[rs + j][ii]);
    uint4* dst = (uint4*)&lat[(size_t)(i0 + ii) * 64 + rs];
    dst[0] = *(uint4*)&h[0];
    dst[1] = *(uint4*)&h[8];
}

// ---------------------------------------------------------------------------
// Host fallback: W_eff = NF4 dequant * absmax + lora_B @ lora_A  (fp16, row-major)
// ---------------------------------------------------------------------------
__global__ void build_weff_kernel(const int* __restrict__ qweight,
                                  const float* __restrict__ absmax,
                                  const float* __restrict__ lA,
                                  const float* __restrict__ lB,
                                  __half* __restrict__ dst) {
    __shared__ float Bsh[64][64];
    __shared__ float Ash[64][128];

    const int tid = threadIdx.x;
    const int o0 = blockIdx.y * 64;
    const int i0 = blockIdx.x * 128;

    for (int t = tid; t < 64 * 64; t += 256) {
        int o = t >> 6, r = t & 63;
        Bsh[r][o] = lB[(o0 + o) * 64 + r];
    }
    for (int t = tid; t < 64 * 128; t += 256) {
        int r = t >> 7, c = t & 127;
        Ash[r][c] = lA[r * IN_F + i0 + c];
    }
    __syncthreads();

    const int oo0 = (tid >> 4) * 4;
    const int ii0 = (tid & 15) * 8;

    float acc[4][8];
#pragma unroll
    for (int a = 0; a < 4; a++)
#pragma unroll
        for (int b = 0; b < 8; b++) acc[a][b] = 0.0f;

#pragma unroll 4
    for (int r = 0; r < 64; r++) {
        float4 a0 = *(const float4*)&Ash[r][ii0];
        float4 a1 = *(const float4*)&Ash[r][ii0 + 4];
#pragma unroll
        for (int oo = 0; oo < 4; oo++) {
            float bv = Bsh[r][oo0 + oo];
            acc[oo][0] += bv * a0.x; acc[oo][1] += bv * a0.y;
            acc[oo][2] += bv * a0.z; acc[oo][3] += bv * a0.w;
            acc[oo][4] += bv * a1.x; acc[oo][5] += bv * a1.y;
            acc[oo][6] += bv * a1.z; acc[oo][7] += bv * a1.w;
        }
    }

#pragma unroll
    for (int oo = 0; oo < 4; oo++) {
        const int o = o0 + oo0 + oo;
        const size_t k = (size_t)o * IN_F + i0 + ii0;
        const int4 qv = ((const int4*)qweight)[k >> 3];
        const float am = absmax[k >> 6];

        float w[8];
        w[0] = NF4[qv.x & 15];  w[1] = NF4[(qv.x >> 4) & 15];
        w[2] = NF4[qv.y & 15];  w[3] = NF4[(qv.y >> 4) & 15];
        w[4] = NF4[qv.z & 15];  w[5] = NF4[(qv.z >> 4) & 15];
        w[6] = NF4[qv.w & 15];  w[7] = NF4[(qv.w >> 4) & 15];

        __half2 h0 = __floats2half2_rn(w[0] * am + acc[oo][0], w[1] * am + acc[oo][1]);
        __half2 h1 = __floats2half2_rn(w[2] * am + acc[oo][2], w[3] * am + acc[oo][3]);
        __half2 h2 = __floats2half2_rn(w[4] * am + acc[oo][4], w[5] * am + acc[oo][5]);
        __half2 h3 = __floats2half2_rn(w[6] * am + acc[oo][6], w[7] * am + acc[oo][7]);
        uint4 pk;
        pk.x = *(uint32_t*)&h0; pk.y = *(uint32_t*)&h1;
        pk.z = *(uint32_t*)&h2; pk.w = *(uint32_t*)&h3;
        *(uint4*)&dst[k] = pk;
    }
}

// ---------------------------------------------------------------------------
// Host fallback GEMM (proven 778us): fp16 mma.sync, 512 thr, 4-stage.
// ---------------------------------------------------------------------------
constexpr int BM = 128, BN = 256, BK = 64, S = 4;
constexpr int NT = IN_F / BK;
constexpr int A_BYTES = BM * 128;
constexpr int B_BYTES = BN * 128;
constexpr int STAGE = A_BYTES + B_BYTES;
constexpr int SMEM_TOTAL = 1024 + S * STAGE;
constexpr int TOTAL_TILES = (M_ROWS / BM) * (OUT_F / BN);

__device__ __forceinline__ void mma_f16(float c[4], const uint32_t a[4],
                                        uint32_t b0, uint32_t b1) {
    asm volatile(
        "mma.sync.aligned.m16n8k16.row.col.f32.f16.f16.f32 "
        "{%0,%1,%2,%3}, {%4,%5,%6,%7}, {%8,%9}, {%0,%1,%2,%3};"
        : "+f"(c[0]), "+f"(c[1]), "+f"(c[2]), "+f"(c[3])
        : "r"(a[0]), "r"(a[1]), "r"(a[2]), "r"(a[3]), "r"(b0), "r"(b1));
}

__device__ __forceinline__ void ldsm4(uint32_t& r0, uint32_t& r1,
                                      uint32_t& r2, uint32_t& r3, uint32_t addr) {
    asm volatile("ldmatrix.sync.aligned.m8n8.x4.shared.b16 {%0,%1,%2,%3}, [%4];"
                 : "=r"(r0), "=r"(r1), "=r"(r2), "=r"(r3) : "r"(addr));
}

__device__ __forceinline__ void st_cs_f2(float* p, float a, float b) {
    asm volatile("st.global.cs.v2.f32 [%0], {%1,%2};" :: "l"(p), "f"(a), "f"(b)
                 : "memory");
}

__device__ __forceinline__ void issue_stage(uint32_t sA, uint32_t sB,
                                            const __half* xb, const __half* wb,
                                            int tid) {
#pragma unroll
    for (int r = 0; r < 2; r++) {
        int i = tid + r * 512;
        int row = i >> 3, c = i & 7;
        uint32_t off = (uint32_t)(row * 128 + ((c * 16) ^ ((row & 7) << 4)));
        const __half* src = xb + (size_t)row * IN_F + c * 8;
        asm volatile("cp.async.cg.shared.global.L2::256B [%0], [%1], 16;\n"
                     :: "r"(sA + off), "l"(src));
    }
#pragma unroll
    for (int r = 0; r < 4; r++) {
        int i = tid + r * 512;
        int row = i >> 3, c = i & 7;
        uint32_t off = (uint32_t)(row * 128 + ((c * 16) ^ ((row & 7) << 4)));
        const __half* src = wb + (size_t)row * IN_F + c * 8;
        asm volatile("cp.async.cg.shared.global.L2::256B [%0], [%1], 16;\n"
                     :: "r"(sB + off), "l"(src));
    }
}

__global__ void __launch_bounds__(512, 1)
gemm_f16_kernel(const __half* __restrict__ Xh, const __half* __restrict__ Wh,
                float* __restrict__ out) {
    extern __shared__ char sm[];
    const uint32_t stage0 = (smem_u32(sm) + 1023) & ~1023u;

    const int tid = threadIdx.x;
    const int wid = tid >> 5;
    const int lane = tid & 31;
    const int warp_m = wid & 3;
    const int warp_n = wid >> 2;
    const int g = lane >> 3;
    const int r = lane & 7;

    uint32_t a_rowoff[2], a_xr[2];
    const uint32_t a_kc = (uint32_t)((g >> 1) * 16);
#pragma unroll
    for (int mf = 0; mf < 2; mf++) {
        int row = warp_m * 32 + mf * 16 + (g & 1) * 8 + r;
        a_rowoff[mf] = row * 128;
        a_xr[mf] = (row & 7) << 4;
    }
    uint32_t b_rowoff[4], b_xr[4];
    const uint32_t b_kc = (uint32_t)((g & 1) * 16);
#pragma unroll
    for (int p = 0; p < 4; p++) {
        int row = warp_n * 64 + p * 16 + (g >> 1) * 8 + r;
        b_rowoff[p] = row * 128;
        b_xr[p] = (row & 7) << 4;
    }

    for (int t = blockIdx.x; t < TOTAL_TILES; t += gridDim.x) {
        const int mBase = (t >> 4) * BM;
        const int nBase = (t & 15) * BN;
        const __half* xt = Xh + (size_t)mBase * IN_F;
        const __half* wt = Wh + (size_t)nBase * IN_F;

        float acc[2][8][4];
#pragma unroll
        for (int i = 0; i < 2; i++)
#pragma unroll
            for (int j = 0; j < 8; j++)
#pragma unroll
                for (int l = 0; l < 4; l++) acc[i][j][l] = 0.0f;

#pragma unroll
        for (int p = 0; p < S - 1; p++) {
            uint32_t sA = stage0 + p * STAGE;
            issue_stage(sA, sA + A_BYTES, xt + p * BK, wt + p * BK, tid);
            asm volatile("cp.async.commit_group;\n" ::: "memory");
        }

        for (int kt = 0; kt < NT; kt++) {
            asm volatile("cp.async.wait_group %0;\n" :: "n"(S - 2) : "memory");
            __syncthreads();

            if (kt + S - 1 < NT) {
                const int s2 = (kt + S - 1) % S;
                uint32_t sA = stage0 + s2 * STAGE;
                issue_stage(sA, sA + A_BYTES,
                            xt + (kt + S - 1) * BK, wt + (kt + S - 1) * BK, tid);
            }
            asm volatile("cp.async.commit_group;\n" ::: "memory");

            const uint32_t sA = stage0 + (kt % S) * STAGE;
            const uint32_t sB = sA + A_BYTES;

#pragma unroll
            for (int q = 0; q < 4; q++) {
                uint32_t a[2][4];
#pragma unroll
                for (int mf = 0; mf < 2; mf++)
                    ldsm4(a[mf][0], a[mf][1], a[mf][2], a[mf][3],
                          sA + a_rowoff[mf] + (((q * 32) + a_kc) ^ a_xr[mf]));
                uint32_t b[8][2];
#pragma unroll
                for (int p = 0; p < 4; p++)
                    ldsm4(b[2 * p][0], b[2 * p][1], b[2 * p + 1][0], b[2 * p + 1][1],
                          sB + b_rowoff[p] + (((q * 32) + b_kc) ^ b_xr[p]));
#pragma unroll
                for (int mf = 0; mf < 2; mf++)
#pragma unroll
                    for (int nf = 0; nf < 8; nf++)
                        mma_f16(acc[mf][nf], a[mf], b[nf][0], b[nf][1]);
            }
        }
        asm volatile("cp.async.wait_group 0;\n" ::: "memory");

#pragma unroll
        for (int mf = 0; mf < 2; mf++) {
#pragma unroll
            for (int nf = 0; nf < 8; nf++) {
                const int row = mBase + warp_m * 32 + mf * 16 + (lane >> 2);
                const int col = nBase + warp_n * 64 + nf * 8 + (lane & 3) * 2;
                st_cs_f2(&out[(size_t)row * OUT_F + col],
                         acc[mf][nf][0], acc[mf][nf][1]);
                st_cs_f2(&out[(size_t)(row + 8) * OUT_F + col],
                         acc[mf][nf][2], acc[mf][nf][3]);
            }
        }
        __syncthreads();
    }
}

// ===========================================================================
// NVRTC module: gemm7 (bulk-copy, tiled operands), gemm5c/gemm5 (backstops),
// wbuild (row-major or tiled output), init kernels.
// ===========================================================================
static const char* NVRTC_SRC = R"NVSRC(
typedef unsigned int u32;
typedef unsigned long long u64;
typedef unsigned short u16;

__device__ __align__(128) u16 GX[33554432];  // X fp16 (row-major OR tiled)
__device__ __align__(128) u16 GW[16777216];  // W fp16 (row-major OR tiled)
__device__ float GOUT[33554432];             // gemm self-test output
__device__ u16 GLB[262144];                  // lora_B fp16 [4096][64]
__device__ u16 GLAT[262144];                 // lora_A^T fp16 [4096][64]
__device__ int GTQW[8388608];                // wbuild self-test qweight
__device__ float GTAM[262144];               // wbuild self-test absmax

__constant__ float NF4D[16] = {
    -1.0f, -0.6961928009986877f, -0.5250730514526367f, -0.39491748809814453f,
    -0.28444138169288635f, -0.18477343022823334f, -0.09105003625154495f, 0.0f,
    0.07958029955625534f, 0.16093020141124725f, 0.24611230194568634f,
    0.33791524171829224f, 0.4407098889350891f, 0.5626170039176941f,
    0.7229568362236023f, 1.0f
};

#define MWAIT(ba, ph) do { u32 _d; \
    asm volatile("{ .reg .pred p; mbarrier.try_wait.parity.acquire.cta.shared::cta.b64 p, [%1], %2; selp.b32 %0,1,0,p; }" \
                 : "=r"(_d) : "r"(ba), "r"(ph) : "memory"); \
    if (!_d) { \
        asm volatile("{ .reg .pred P1; WL%=: mbarrier.try_wait.parity.acquire.cta.shared::cta.b64 P1, [%0], %1, 0x989680; @P1 bra.uni WD%=; bra.uni WL%=; WD%=: }" \
                     :: "r"(ba), "r"(ph) : "memory"); } } while(0)

#define LDTM32(rr, addr) \
    asm volatile("tcgen05.ld.sync.aligned.32x32b.x32.b32 " \
        "{%0,%1,%2,%3,%4,%5,%6,%7,%8,%9,%10,%11,%12,%13,%14,%15," \
        "%16,%17,%18,%19,%20,%21,%22,%23,%24,%25,%26,%27,%28,%29,%30,%31}, [%32];" \
        : "=r"(rr[0]), "=r"(rr[1]), "=r"(rr[2]), "=r"(rr[3]), \
          "=r"(rr[4]), "=r"(rr[5]), "=r"(rr[6]), "=r"(rr[7]), \
          "=r"(rr[8]), "=r"(rr[9]), "=r"(rr[10]), "=r"(rr[11]), \
          "=r"(rr[12]), "=r"(rr[13]), "=r"(rr[14]), "=r"(rr[15]), \
          "=r"(rr[16]), "=r"(rr[17]), "=r"(rr[18]), "=r"(rr[19]), \
          "=r"(rr[20]), "=r"(rr[21]), "=r"(rr[22]), "=r"(rr[23]), \
          "=r"(rr[24]), "=r"(rr[25]), "=r"(rr[26]), "=r"(rr[27]), \
          "=r"(rr[28]), "=r"(rr[29]), "=r"(rr[30]), "=r"(rr[31]) \
        : "r"(addr))

#define BULK(dst, src, sz, mbar) \
    asm volatile("cp.async.bulk.shared::cta.global.mbarrier::complete_tx::bytes " \
                 "[%0], [%1], %2, [%3];" \
                 :: "r"(dst), "l"(src), "r"(sz), "r"(mbar) : "memory")

#define EXPECT_TX(mbar, n) \
    asm volatile("mbarrier.arrive.expect_tx.shared.b64 _, [%0], %1;" \
                 :: "r"(mbar), "r"(n) : "memory")

#define MMA8(tmem, a0, a1, bd, IDESC, en) do { \
    asm volatile("{ .reg .pred p; setp.ne.u32 p, %5, 0; " \
        "tcgen05.mma.cta_group::1.kind::f16 [%0], %1, %2, %3, {%4,%4,%4,%4}, p; }" \
        :: "r"(tmem), "l"(a0), "l"(bd), "r"(IDESC), "r"(0u), "r"(en) : "memory"); \
    asm volatile("{ .reg .pred p; setp.ne.u32 p, %5, 0; " \
        "tcgen05.mma.cta_group::1.kind::f16 [%0], %1, %2, %3, {%4,%4,%4,%4}, p; }" \
        :: "r"((tmem) + 256), "l"(a1), "l"(bd), "r"(IDESC), "r"(0u), "r"(en) : "memory"); \
} while(0)

__device__ __forceinline__ u32 sm2u32(const void* p) {
    u32 a;
    asm("{ .reg .u64 t; cvta.to.shared.u64 t, %1; cvt.u32.u64 %0, t; }" : "=r"(a) : "l"(p));
    return a;
}

__device__ __forceinline__ u32 swz(u32 off) { return off ^ ((off >> 3) & 0x70); }

// row-major test init
extern "C" __global__ void initt() {
    u64 i = (u64)blockIdx.x * 256 + threadIdx.x;
    const u16 T[9] = {0xBC00,0xBA00,0xB800,0xB400,0,0x3400,0x3800,0x3A00,0x3C00};
    if (i < 33554432ull) {
        u32 m = (u32)(i >> 12), k = (u32)(i & 4095);
        GX[i] = T[(k*131u + m*7u) % 9u];
    }
    if (i < 16777216ull) {
        u32 n = (u32)(i >> 12), k = (u32)(i & 4095);
        GW[i] = T[(k*17u + n*3u) % 7u + 1u];
    }
}

// tiled test init: same logical values, (tile,ktile)-major SW128 layout
extern "C" __global__ void init7() {
    u64 i = (u64)blockIdx.x * 256 + threadIdx.x;
    const u16 T[9] = {0xBC00,0xBA00,0xB800,0xB400,0,0x3400,0x3800,0x3A00,0x3C00};
    if (i < 33554432ull) {
        u32 m = (u32)(i >> 12), k = (u32)(i & 4095);
        u64 boff = ((u64)((m >> 7) * 64u + (k >> 6))) * 16384ull
                 + (u64)swz((m & 127u) * 128u + (k & 63u) * 2u);
        GX[boff >> 1] = T[(k*131u + m*7u) % 9u];
    }
    if (i < 16777216ull) {
        u32 n = (u32)(i >> 12), k = (u32)(i & 4095);
        u64 boff = ((u64)((n >> 7) * 64u + (k >> 6))) * 16384ull
                 + (u64)swz((n & 127u) * 128u + (k & 63u) * 2u);
        GW[boff >> 1] = T[(k*17u + n*3u) % 7u + 1u];
    }
}

extern "C" __global__ void wtinit() {
    u64 i = (u64)blockIdx.x * 256 + threadIdx.x;
    if (i < 8388608ull) GTQW[i] = (int)((i * 37ull) & 255ull);
    if (i < 262144ull) {
        GTAM[i] = (float)((u32)(i * 13ull) % 31u + 1u) * 0.03125f;
        u32 o = (u32)(i >> 6), r = (u32)(i & 63);
        float lb = (float)((int)((o*3u + r*7u) % 17u) - 8) * 0.015625f;
        float la = (float)((int)((o*5u + r*11u) % 19u) - 9) * 0.015625f;
        u16 hb, ha;
        asm("cvt.rn.f16.f32 %0, %1;" : "=h"(hb) : "f"(lb));
        asm("cvt.rn.f16.f32 %0, %1;" : "=h"(ha) : "f"(la));
        GLB[i] = hb;
        GLAT[i] = ha;
    }
}

__device__ __forceinline__ void ld_sub(u32 dst, const char* src, int tid, int iters) {
#pragma unroll
    for (int r = 0; r < 8; r++) {
        if (r >= iters) break;
        int i = tid + r * 256; int row = i >> 3, c = i & 7;
        u32 off = (u32)(row * 128 + ((c * 16) ^ ((row & 7) << 4)));
        asm volatile("cp.async.cg.shared.global.L2::256B [%0], [%1], 16;"
                     :: "r"(dst + off), "l"(src + (u64)row * 8192 + c * 16));
    }
}

// ---------------- gemm5 (single M-tile backstop, row-major operands) ----------------
__device__ __forceinline__ void ld_stage(u32 sA, u32 sB, const char* xb,
                                         const char* wb, int tid) {
#pragma unroll
    for (int r = 0; r < 4; r++) {
        int i = tid + r * 256; int row = i >> 3, c = i & 7;
        u32 off = (u32)(row * 128 + ((c * 16) ^ ((row & 7) << 4)));
        asm volatile("cp.async.cg.shared.global.L2::256B [%0], [%1], 16;"
                     :: "r"(sA + off), "l"(xb + (u64)row * 8192 + c * 16));
    }
#pragma unroll
    for (int r = 0; r < 8; r++) {
        int i = tid + r * 256; int row = i >> 3, c = i & 7;
        u32 off = (u32)(row * 128 + ((c * 16) ^ ((row & 7) << 4)));
        asm volatile("cp.async.cg.shared.global.L2::256B [%0], [%1], 16;"
                     :: "r"(sB + off), "l"(wb + (u64)row * 8192 + c * 16));
    }
}

extern "C" __global__ void __launch_bounds__(256, 1)
gemm5(const char* __restrict__ X, const char* __restrict__ W,
      float* __restrict__ out) {
    extern __shared__ char sm[];
    u32 base = (sm2u32(sm) + 1023) & ~1023u;
    const u32 tptr = base;
    const u32 mb = base + 16;
    const u32 st0 = base + 1024;
    const int tid = threadIdx.x, wid = tid >> 5, lid = tid & 31;

    if (wid == 0)
        asm volatile("tcgen05.alloc.cta_group::1.sync.aligned.shared::cta.b32 [%0], %1;"
                     :: "r"(tptr), "r"(256u) : "memory");
    if (tid == 0) {
#pragma unroll
        for (int s = 0; s < 4; s++)
            asm volatile("mbarrier.init.shared.b64 [%0], %1;"
                         :: "r"(mb + s * 8), "r"(1u) : "memory");
    }
    __syncthreads();
    u32 tmem; asm volatile("ld.shared.b32 %0,[%1];" : "=r"(tmem) : "r"(tptr));

    const u64 DBASE = (2ull << 61) | (1ull << 46) | (64ull << 32) | (1ull << 16);
    const u32 IDESC = (1u << 4) | (32u << 17) | (8u << 24);

#pragma unroll 1
    for (int t = blockIdx.x; t < 1024; t += gridDim.x) {
        const int mBase = (t >> 4) * 128, nBase = (t & 15) * 256;
        const char* xt = X + (u64)mBase * 8192;
        const char* wt = W + (u64)nBase * 8192;

#pragma unroll
        for (int p = 0; p < 4; p++) {
            u32 sA = st0 + p * 49152;
            ld_stage(sA, sA + 16384, xt + p * 128, wt + p * 128, tid);
            asm volatile("cp.async.commit_group;" ::: "memory");
        }

#pragma unroll 1
        for (int kt = 0; kt < 64; kt++) {
            const int s = kt & 3;
            const u32 sA = st0 + s * 49152, sB = sA + 16384;
            asm volatile("cp.async.wait_group 3;" ::: "memory");
            __syncthreads();

            if (wid == 0) {
                u32 ep;
                asm volatile("{ .reg .pred p; elect.sync _|p, 0xFFFFFFFF; selp.b32 %0,1,0,p; }"
                             : "=r"(ep));
                if (ep) {
                    asm volatile("fence.proxy.async.shared::cta;" ::: "memory");
                    u64 ad = DBASE | ((u64)(sA >> 4) & 0x3FFF);
                    u64 bd = DBASE | ((u64)(sB >> 4) & 0x3FFF);
#pragma unroll
                    for (int q = 0; q < 4; q++) {
                        u32 en = (kt > 0 || q > 0) ? 1u : 0u;
                        asm volatile("{ .reg .pred p; setp.ne.u32 p, %5, 0; "
                            "tcgen05.mma.cta_group::1.kind::f16 [%0], %1, %2, %3, {%4,%4,%4,%4}, p; }"
                            :: "r"(tmem), "l"(ad + q * 2), "l"(bd + q * 2),
                               "r"(IDESC), "r"(0u), "r"(en) : "memory");
                    }
                    asm volatile("tcgen05.commit.cta_group::1.mbarrier::arrive::one.shared::cluster.b64 [%0];"
                                 :: "r"(mb + s * 8) : "memory");
                }
            }

            if (kt + 4 < 64) {
                u32 ph = (u32)((kt >> 2) & 1);
                MWAIT(mb + s * 8, ph);
                ld_stage(sA, sB, xt + (kt + 4) * 128, wt + (kt + 4) * 128, tid);
            }
            asm volatile("cp.async.commit_group;" ::: "memory");
        }

        MWAIT(mb + 24, 1u);
        asm volatile("tcgen05.fence::after_thread_sync;" ::: "memory");

        if (wid < 4) {
            float* dst = out + (u64)(mBase + wid * 32 + lid) * 4096 + nBase;
#pragma unroll
            for (int ch = 0; ch < 8; ch++) {
                u32 rr[32];
                LDTM32(rr, tmem + ch * 32);
                asm volatile("tcgen05.wait::ld.sync.aligned;" ::: "memory");
#pragma unroll
                for (int j = 0; j < 8; j++)
                    asm volatile("st.global.cs.v4.b32 [%0], {%1,%2,%3,%4};"
                                 :: "l"(dst + ch * 32 + j * 4),
                                    "r"(rr[4 * j]), "r"(rr[4 * j + 1]),
                                    "r"(rr[4 * j + 2]), "r"(rr[4 * j + 3]) : "memory");
            }
            asm volatile("tcgen05.fence::before_thread_sync;" ::: "memory");
        }
        __syncthreads();
    }

    __syncthreads();
    if (wid == 0) {
        asm volatile("tcgen05.relinquish_alloc_permit.cta_group::1.sync.aligned;");
        asm volatile("tcgen05.dealloc.cta_group::1.sync.aligned.b32 %0, %1;"
                     :: "r"(tmem), "r"(256u));
    }
}

// ---------------- gemm5c: 2 M-tiles, decoupled cp.async (row-major) ----------------
extern "C" __global__ void __launch_bounds__(256, 1)
gemm5c(const char* __restrict__ X, const char* __restrict__ W,
       float* __restrict__ out) {
    extern __shared__ char sm[];
    u32 base = (sm2u32(sm) + 1023) & ~1023u;
    const u32 tptr = base;
    const u32 mb = base + 16;
    const u32 st0 = base + 1024;
    const int tid = threadIdx.x, wid = tid >> 5, lid = tid & 31;

    if (wid == 0)
        asm volatile("tcgen05.alloc.cta_group::1.sync.aligned.shared::cta.b32 [%0], %1;"
                     :: "r"(tptr), "r"(512u) : "memory");
    if (tid == 0) {
#pragma unroll
        for (int s = 0; s < 3; s++)
            asm volatile("mbarrier.init.shared.b64 [%0], %1;"
                         :: "r"(mb + s * 8), "r"(1u) : "memory");
    }
    __syncthreads();
    u32 tmem; asm volatile("ld.shared.b32 %0,[%1];" : "=r"(tmem) : "r"(tptr));

    const u64 DBASE = (2ull << 61) | (1ull << 46) | (64ull << 32) | (1ull << 16);
    const u32 IDESC = (1u << 4) | (32u << 17) | (8u << 24);

    int bp1 = 0, bp2 = 0;

#pragma unroll 1
    for (int t = blockIdx.x; t < 512; t += gridDim.x) {
        const int mBase = (t >> 4) * 256, nBase = (t & 15) * 256;
        const char* x0 = X + (u64)mBase * 8192;
        const char* x1 = x0 + 1048576;
        const char* wt = W + (u64)nBase * 8192;

#pragma unroll
        for (int p = 0; p < 2; p++) {
            u32 sA0 = st0 + p * 65536;
            ld_sub(sA0,         x0 + p * 128, tid, 4);
            ld_sub(sA0 + 16384, x1 + p * 128, tid, 4);
            ld_sub(sA0 + 32768, wt + p * 128, tid, 8);
            asm volatile("cp.async.commit_group;" ::: "memory");
        }

#pragma unroll 1
        for (int kt = 0; kt < 64; kt++) {
            const int kdiv = kt / 3;
            const int s = kt - kdiv * 3;
            const u32 sA0 = st0 + s * 65536, sA1 = sA0 + 16384, sB = sA0 + 32768;
            asm volatile("cp.async.wait_group 1;" ::: "memory");
            __syncthreads();

            if (wid == 0) {
                u32 ep;
                asm volatile("{ .reg .pred p; elect.sync _|p, 0xFFFFFFFF; selp.b32 %0,1,0,p; }"
                             : "=r"(ep));
                if (ep) {
                    asm volatile("fence.proxy.async.shared::cta;" ::: "memory");
                    u64 a0 = DBASE | ((u64)(sA0 >> 4) & 0x3FFF);
                    u64 a1 = DBASE | ((u64)(sA1 >> 4) & 0x3FFF);
                    u64 bd = DBASE | ((u64)(sB >> 4) & 0x3FFF);
#pragma unroll
                    for (int q = 0; q < 4; q++) {
                        u32 en = (kt > 0 || q > 0) ? 1u : 0u;
                        MMA8(tmem, a0 + q * 2, a1 + q * 2, bd + q * 2, IDESC, en);
                    }
                    asm volatile("tcgen05.commit.cta_group::1.mbarrier::arrive::one.shared::cluster.b64 [%0];"
                                 :: "r"(mb + s * 8) : "memory");
                }
            }

            if (kt + 2 < 64) {
                const int sd = (kt + 2) - ((kt + 2) / 3) * 3;
                const u32 dA0 = st0 + sd * 65536;
                if (kt >= 1) {
                    const int kp = kt - 1;
                    const int kdv = kp / 3;
                    const int sp = kp - kdv * 3;
                    int bps = (sp == 0) ? 0 : ((sp == 1) ? bp1 : bp2);
                    u32 ph = (u32)(bps ^ (kdv & 1));
                    MWAIT(mb + sp * 8, ph);
                }
                ld_sub(dA0,         x0 + (kt + 2) * 128, tid, 4);
                ld_sub(dA0 + 16384, x1 + (kt + 2) * 128, tid, 4);
                ld_sub(dA0 + 32768, wt + (kt + 2) * 128, tid, 8);
            }
            asm volatile("cp.async.commit_group;" ::: "memory");
        }

        MWAIT(mb, 1u);
        asm volatile("tcgen05.fence::after_thread_sync;" ::: "memory");

        {
            const int half = wid >> 2, wr = wid & 3;
            float* dst = out + (u64)(mBase + half * 128 + wr * 32 + lid) * 4096 + nBase;
            const u32 tm = tmem + half * 256;
#pragma unroll
            for (int ch = 0; ch < 8; ch++) {
                u32 rr[32];
                LDTM32(rr, tm + ch * 32);
                asm volatile("tcgen05.wait::ld.sync.aligned;" ::: "memory");
#pragma unroll
                for (int j = 0; j < 8; j++)
                    asm volatile("st.global.cs.v4.b32 [%0], {%1,%2,%3,%4};"
                                 :: "l"(dst + ch * 32 + j * 4),
                                    "r"(rr[4 * j]), "r"(rr[4 * j + 1]),
                                    "r"(rr[4 * j + 2]), "r"(rr[4 * j + 3]) : "memory");
            }
            asm volatile("tcgen05.fence::before_thread_sync;" ::: "memory");
        }
        __syncthreads();
        bp1 ^= 1; bp2 ^= 1;
    }

    __syncthreads();
    if (wid == 0) {
        asm volatile("tcgen05.relinquish_alloc_permit.cta_group::1.sync.aligned;");
        asm volatile("tcgen05.dealloc.cta_group::1.sync.aligned.b32 %0, %1;"
                     :: "r"(tmem), "r"(512u));
    }
}

// ---------------- gemm7: bulk-copy pipeline, TILED operands ----------------
// X tiled: block (mtile, kt) = 16KB SW128 at offset ((mtile*64)+kt)*16384.
// W tiled likewise with 128-row n-tiles. 4 bulk copies of 16KB per k-iter,
// issued by one elected thread; same mbarrier/parity scheme as gemm5c.
extern "C" __global__ void __launch_bounds__(256, 1)
gemm7(const char* __restrict__ X, const char* __restrict__ W,
      float* __restrict__ out) {
    extern __shared__ char sm[];
    u32 base = (sm2u32(sm) + 1023) & ~1023u;
    const u32 tptr = base;
    const u32 mbc = base + 16;
    const u32 mbf = base + 48;
    const u32 st0 = base + 1024;
    const int tid = threadIdx.x, wid = tid >> 5, lid = tid & 31;

    if (wid == 0)
        asm volatile("tcgen05.alloc.cta_group::1.sync.aligned.shared::cta.b32 [%0], %1;"
                     :: "r"(tptr), "r"(512u) : "memory");
    if (tid == 0) {
#pragma unroll
        for (int s = 0; s < 3; s++) {
            asm volatile("mbarrier.init.shared.b64 [%0], %1;"
                         :: "r"(mbc + s * 8), "r"(1u) : "memory");
            asm volatile("mbarrier.init.shared.b64 [%0], %1;"
                         :: "r"(mbf + s * 8), "r"(1u) : "memory");
        }
    }
    __syncthreads();
    u32 tmem; asm volatile("ld.shared.b32 %0,[%1];" : "=r"(tmem) : "r"(tptr));

    const u64 DBASE = (2ull << 61) | (1ull << 46) | (64ull << 32) | (1ull << 16);
    const u32 IDESC = (1u << 4) | (32u << 17) | (8u << 24);

    int bp1 = 0, bp2 = 0;
    int pf0 = 0, pf1 = 0, pf2 = 0;

#pragma unroll 1
    for (int t = blockIdx.x; t < 512; t += gridDim.x) {
        const int mBase = (t >> 4) * 256, nBase = (t & 15) * 256;
        const u64 mt0 = (u64)((t >> 4) * 2) * 64;       // X tile-row index base *64
        const u64 nt0 = (u64)((t & 15) * 2) * 64;       // W tile-row index base *64

        if (wid == 0) {
            u32 ep;
            asm volatile("{ .reg .pred p; elect.sync _|p, 0xFFFFFFFF; selp.b32 %0,1,0,p; }"
                         : "=r"(ep));
            if (ep) {
#pragma unroll
                for (int p = 0; p < 2; p++) {
                    u32 sl = st0 + p * 65536;
                    EXPECT_TX(mbf + p * 8, 65536u);
                    BULK(sl,          X + (mt0 + p) * 16384ull,        16384u, mbf + p * 8);
                    BULK(sl + 16384,  X + (mt0 + 64 + p) * 16384ull,   16384u, mbf + p * 8);
                    BULK(sl + 32768,  W + (nt0 + p) * 16384ull,        16384u, mbf + p * 8);
                    BULK(sl + 49152,  W + (nt0 + 64 + p) * 16384ull,   16384u, mbf + p * 8);
                }
#pragma unroll 1
                for (int kt = 0; kt < 64; kt++) {
                    const int kdiv = kt / 3;
                    const int s = kt - kdiv * 3;
                    const u32 sA0 = st0 + s * 65536, sA1 = sA0 + 16384, sB = sA0 + 32768;
                    u32 ph;
                    if (s == 0) { ph = (u32)pf0; pf0 ^= 1; }
                    else if (s == 1) { ph = (u32)pf1; pf1 ^= 1; }
                    else { ph = (u32)pf2; pf2 ^= 1; }
                    MWAIT(mbf + s * 8, ph);

                    u64 a0 = DBASE | ((u64)(sA0 >> 4) & 0x3FFF);
                    u64 a1 = DBASE | ((u64)(sA1 >> 4) & 0x3FFF);
                    u64 bd = DBASE | ((u64)(sB >> 4) & 0x3FFF);
#pragma unroll
                    for (int q = 0; q < 4; q++) {
                        u32 en = (kt > 0 || q > 0) ? 1u : 0u;
                        MMA8(tmem, a0 + q * 2, a1 + q * 2, bd + q * 2, IDESC, en);
                    }
                    asm volatile("tcgen05.commit.cta_group::1.mbarrier::arrive::one.shared::cluster.b64 [%0];"
                                 :: "r"(mbc + s * 8) : "memory");

                    if (kt + 2 < 64) {
                        const int sd = (kt + 2) - ((kt + 2) / 3) * 3;
                        const u32 dA0 = st0 + sd * 65536;
                        if (kt >= 1) {
                            const int kp = kt - 1;
                            const int kdv = kp / 3;
                            const int sp = kp - kdv * 3;   // == sd
                            int bps = (sp == 0) ? 0 : ((sp == 1) ? bp1 : bp2);
                            u32 p2 = (u32)(bps ^ (kdv & 1));
                            MWAIT(mbc + sp * 8, p2);
                        }
                        const u64 kk = (u64)(kt + 2);
                        EXPECT_TX(mbf + sd * 8, 65536u);
                        BULK(dA0,          X + (mt0 + kk) * 16384ull,      16384u, mbf + sd * 8);
                        BULK(dA0 + 16384,  X + (mt0 + 64 + kk) * 16384ull, 16384u, mbf + sd * 8);
                        BULK(dA0 + 32768,  W + (nt0 + kk) * 16384ull,      16384u, mbf + sd * 8);
                        BULK(dA0 + 49152,  W + (nt0 + 64 + kk) * 16384ull, 16384u, mbf + sd * 8);
                    }
                }
            }
        }

        MWAIT(mbc, 1u);
        asm volatile("tcgen05.fence::after_thread_sync;" ::: "memory");

        {
            const int half = wid >> 2, wr = wid & 3;
            float* dst = out + (u64)(mBase + half * 128 + wr * 32 + lid) * 4096 + nBase;
            const u32 tm = tmem + half * 256;
#pragma unroll
            for (int ch = 0; ch < 8; ch++) {
                u32 rr[32];
                LDTM32(rr, tm + ch * 32);
                asm volatile("tcgen05.wait::ld.sync.aligned;" ::: "memory");
#pragma unroll
                for (int j = 0; j < 8; j++)
                    asm volatile("st.global.cs.v4.b32 [%0], {%1,%2,%3,%4};"
                                 :: "l"(dst + ch * 32 + j * 4),
                                    "r"(rr[4 * j]), "r"(rr[4 * j + 1]),
                                    "r"(rr[4 * j + 2]), "r"(rr[4 * j + 3]) : "memory");
            }
            asm volatile("tcgen05.fence::before_thread_sync;" ::: "memory");
        }
        __syncthreads();
        bp1 ^= 1; bp2 ^= 1;
    }

    __syncthreads();
    if (wid == 0) {
        asm volatile("tcgen05.relinquish_alloc_permit.cta_group::1.sync.aligned;");
        asm volatile("tcgen05.dealloc.cta_group::1.sync.aligned.b32 %0, %1;"
                     :: "r"(tmem), "r"(512u));
    }
}

// ---------------- wbuild: fused LoRA GEMM + NF4 dequant (row-major or tiled) ------
extern "C" __global__ void __launch_bounds__(256, 1)
wbuild(const int* __restrict__ qw, const float* __restrict__ am,
       const u16* __restrict__ lb, const u16* __restrict__ lat,
       u16* __restrict__ w, int tiled) {
    extern __shared__ char sm[];
    u32 base = (sm2u32(sm) + 1023) & ~1023u;
    const u32 tptr = base;
    const u32 mb = base + 16;
    const u32 sa = base + 1024;
    const u32 sb = sa + 16384;
    const int tid = threadIdx.x, wid = tid >> 5, lid = tid & 31;
    const int ti = blockIdx.x;
    const int o0 = (ti >> 4) * 128, i0 = (ti & 15) * 256;

    if (wid == 0)
        asm volatile("tcgen05.alloc.cta_group::1.sync.aligned.shared::cta.b32 [%0], %1;"
                     :: "r"(tptr), "r"(256u) : "memory");
    if (tid == 0)
        asm volatile("mbarrier.init.shared.b64 [%0], %1;" :: "r"(mb), "r"(1u) : "memory");
    __syncthreads();
    u32 tmem; asm volatile("ld.shared.b32 %0,[%1];" : "=r"(tmem) : "r"(tptr));

#pragma unroll
    for (int r = 0; r < 4; r++) {
        int i = tid + r * 256; int row = i >> 3, c = i & 7;
        u32 off = (u32)(row * 128 + ((c * 16) ^ ((row & 7) << 4)));
        asm volatile("cp.async.cg.shared.global [%0], [%1], 16;"
                     :: "r"(sa + off), "l"((const char*)lb + (u64)(o0 + row) * 128 + c * 16));
    }
#pragma unroll
    for (int r = 0; r < 8; r++) {
        int i = tid + r * 256; int row = i >> 3, c = i & 7;
        u32 off = (u32)(row * 128 + ((c * 16) ^ ((row & 7) << 4)));
        asm volatile("cp.async.cg.shared.global [%0], [%1], 16;"
                     :: "r"(sb + off), "l"((const char*)lat + (u64)(i0 + row) * 128 + c * 16));
    }
    asm volatile("cp.async.commit_group;" ::: "memory");
    asm volatile("cp.async.wait_group 0;" ::: "memory");
    __syncthreads();

    const u64 DBASE = (2ull << 61) | (1ull << 46) | (64ull << 32) | (1ull << 16);
    const u32 IDESC = (1u << 4) | (32u << 17) | (8u << 24);

    if (wid == 0) {
        u32 ep;
        asm volatile("{ .reg .pred p; elect.sync _|p, 0xFFFFFFFF; selp.b32 %0,1,0,p; }"
                     : "=r"(ep));
        if (ep) {
            asm volatile("fence.proxy.async.shared::cta;" ::: "memory");
            u64 ad = DBASE | ((u64)(sa >> 4) & 0x3FFF);
            u64 bd = DBASE | ((u64)(sb >> 4) & 0x3FFF);
#pragma unroll
            for (int q = 0; q < 4; q++) {
                u32 en = (q > 0) ? 1u : 0u;
                asm volatile("{ .reg .pred p; setp.ne.u32 p, %5, 0; "
                    "tcgen05.mma.cta_group::1.kind::f16 [%0], %1, %2, %3, {%4,%4,%4,%4}, p; }"
                    :: "r"(tmem), "l"(ad + q * 2), "l"(bd + q * 2),
                       "r"(IDESC), "r"(0u), "r"(en) : "memory");
            }
            asm volatile("tcgen05.commit.cta_group::1.mbarrier::arrive::one.shared::cluster.b64 [%0];"
                         :: "r"(mb) : "memory");
        }
    }
    __syncthreads();
    MWAIT(mb, 0u);
    asm volatile("tcgen05.fence::after_thread_sync;" ::: "memory");

    const int half = wid >> 2, wr = wid & 3;
    const int o = o0 + wr * 32 + lid;
#pragma unroll
    for (int c4 = 0; c4 < 4; c4++) {
        u32 rr[32];
        LDTM32(rr, tmem + half * 128 + c4 * 32);
        asm volatile("tcgen05.wait::ld.sync.aligned;" ::: "memory");
        const int ib = i0 + half * 128 + c4 * 32;
        const u64 k = (u64)o * 4096 + (u64)ib;
        const float a = am[k >> 6];
        const int4* qp = (const int4*)qw + (k >> 3);
        u32 ov[16];
#pragma unroll
        for (int u = 0; u < 4; u++) {
            int4 qv = qp[u];
            int e[8] = {qv.x & 15, (qv.x >> 4) & 15, qv.y & 15, (qv.y >> 4) & 15,
                        qv.z & 15, (qv.z >> 4) & 15, qv.w & 15, (qv.w >> 4) & 15};
#pragma unroll
            for (int j = 0; j < 4; j++) {
                union { u32 u_; float f_; } c0, c1;
                c0.u_ = rr[u * 8 + 2 * j];
                c1.u_ = rr[u * 8 + 2 * j + 1];
                float w0 = NF4D[e[2 * j]] * a + c0.f_;
                float w1 = NF4D[e[2 * j + 1]] * a + c1.f_;
                asm("cvt.rn.f16x2.f32 %0, %1, %2;" : "=r"(ov[u * 4 + j]) : "f"(w1), "f"(w0));
            }
        }
        if (!tiled) {
            char* wp = (char*)w + k * 2;
#pragma unroll
            for (int j = 0; j < 4; j++)
                asm volatile("st.global.cs.v4.b32 [%0], {%1,%2,%3,%4};"
                             :: "l"(wp + j * 16), "r"(ov[4 * j]), "r"(ov[4 * j + 1]),
                                "r"(ov[4 * j + 2]), "r"(ov[4 * j + 3]) : "memory");
        } else {
            // tiled: tile (o>>7, ib>>6), row o&127, cols (ib&63)+j*8
            const u64 tbase = ((u64)((o >> 7) * 64 + (ib >> 6))) * 16384ull;
            const u32 rowoff = (u32)((o & 127) * 128 + (ib & 63) * 2);
#pragma unroll
            for (int j = 0; j < 4; j++) {
                u32 off = rowoff + (u32)(j * 16);
                off = off ^ ((off >> 3) & 0x70);
                asm volatile("st.global.cs.v4.b32 [%0], {%1,%2,%3,%4};"
                             :: "l"((char*)w + tbase + off),
                                "r"(ov[4 * j]), "r"(ov[4 * j + 1]),
                                "r"(ov[4 * j + 2]), "r"(ov[4 * j + 3]) : "memory");
            }
        }
    }
    asm volatile("tcgen05.fence::before_thread_sync;" ::: "memory");
    __syncthreads();
    if (wid == 0) {
        asm volatile("tcgen05.relinquish_alloc_permit.cta_group::1.sync.aligned;");
        asm volatile("tcgen05.dealloc.cta_group::1.sync.aligned.b32 %0, %1;"
                     :: "r"(tmem), "r"(256u));
    }
}
)NVSRC";

// --- driver/nvrtc plumbing ---
typedef int (*nvrtcCreateProgram_t)(void**, const char*, const char*, int,
                                    const char* const*, const char* const*);
typedef int (*nvrtcCompileProgram_t)(void*, int, const char* const*);
typedef int (*nvrtcGetCUBINSize_t)(void*, size_t*);
typedef int (*nvrtcGetCUBIN_t)(void*, char*);
typedef int (*cuInit_t)(unsigned);
typedef int (*cuDevicePrimaryCtxRetain_t)(void**, int);
typedef int (*cuCtxSetCurrent_t)(void*);
typedef int (*cuModuleLoadDataEx_t)(void**, const void*, unsigned, int*, void**);
typedef int (*cuModuleGetFunction_t)(void**, void*, const char*);
typedef int (*cuModuleGetGlobal_t)(unsigned long long*, size_t*, void*, const char*);
typedef int (*cuFuncSetAttribute_t)(void*, int, int);
typedef int (*cuLaunchKernel_t)(void*, unsigned, unsigned, unsigned,
                                unsigned, unsigned, unsigned,
                                unsigned, void*, void**, void**);
typedef int (*cuCtxSynchronize_t)(void);
typedef int (*cuMemcpyDtoH_t)(void*, unsigned long long, size_t);

#if defined(CUDA_API_PER_THREAD_DEFAULT_STREAM) || defined(__CUDA_API_PER_THREAD_DEFAULT_STREAM)
#define DRV_STREAM ((void*)0x2)
#else
#define DRV_STREAM ((void*)0x1)
#endif

static bool g_ok_gemm = false, g_ok_wb = false;
static int g_mode = 0;  // 4 = tiled bulk (gemm7), 1 = row-major (5c/5), 0 = host
static cuLaunchKernel_t p_cuLaunchKernel = nullptr;
static void* g_fn_gemm = nullptr;
static void* g_fn_wbuild = nullptr;
static unsigned long long g_gx = 0, g_gw = 0, g_glb = 0, g_glat = 0;
constexpr int SMEM5 = 198656;
constexpr int SMEMW = 51200;

static float h2f(uint16_t h) {
    uint32_t s = (h >> 15) & 1, e = (h >> 10) & 31, m = h & 1023;
    uint32_t f;
    if (e == 0) {
        if (m == 0) f = s << 31;
        else {
            e = 127 - 15 + 1;
            while (!(m & 1024)) { m <<= 1; e--; }
            m &= 1023;
            f = (s << 31) | (e << 23) | (m << 13);
        }
    } else if (e == 31) f = (s << 31) | 0x7F800000 | (m << 13);
    else f = (s << 31) | ((e - 15 + 127) << 23) | (m << 13);
    float r; memcpy(&r, &f, 4); return r;
}

static bool try_init_tcgen05() {
    void* hcu = dlopen("libcuda.so.1", RTLD_NOW | RTLD_GLOBAL);
    if (!hcu) hcu = dlopen("libcuda.so", RTLD_NOW | RTLD_GLOBAL);
    if (!hcu) return false;
    void* hnv = dlopen("libnvrtc.so.13", RTLD_NOW | RTLD_GLOBAL);
    if (!hnv) hnv = dlopen("libnvrtc.so", RTLD_NOW | RTLD_GLOBAL);
    if (!hnv) hnv = dlopen("libnvrtc.so.12", RTLD_NOW | RTLD_GLOBAL);
    if (!hnv) return false;

    auto nCreate  = (nvrtcCreateProgram_t)dlsym(hnv, "nvrtcCreateProgram");
    auto nCompile = (nvrtcCompileProgram_t)dlsym(hnv, "nvrtcCompileProgram");
    auto nCbSize  = (nvrtcGetCUBINSize_t)dlsym(hnv, "nvrtcGetCUBINSize");
    auto nCb      = (nvrtcGetCUBIN_t)dlsym(hnv, "nvrtcGetCUBIN");
    auto cInit    = (cuInit_t)dlsym(hcu, "cuInit");
    auto cRetain  = (cuDevicePrimaryCtxRetain_t)dlsym(hcu, "cuDevicePrimaryCtxRetain");
    auto cSetCur  = (cuCtxSetCurrent_t)dlsym(hcu, "cuCtxSetCurrent");
    auto cModLoad = (cuModuleLoadDataEx_t)dlsym(hcu, "cuModuleLoadDataEx");
    auto cGetFn   = (cuModuleGetFunction_t)dlsym(hcu, "cuModuleGetFunction");
    auto cGetGlb  = (cuModuleGetGlobal_t)dlsym(hcu, "cuModuleGetGlobal_v2");
    auto cSetAttr = (cuFuncSetAttribute_t)dlsym(hcu, "cuFuncSetAttribute");
    auto cLaunch  = (cuLaunchKernel_t)dlsym(hcu, "cuLaunchKernel");
    auto cSync    = (cuCtxSynchronize_t)dlsym(hcu, "cuCtxSynchronize");
    auto cD2H     = (cuMemcpyDtoH_t)dlsym(hcu, "cuMemcpyDtoH_v2");
    if (!nCreate || !nCompile || !nCbSize || !nCb || !cInit || !cRetain ||
        !cSetCur || !cModLoad || !cGetFn || !cGetGlb || !cSetAttr ||
        !cLaunch || !cSync || !cD2H)
        return false;

    if (cInit(0)) return false;
    void* ctx = nullptr;
    if (cRetain(&ctx, 0)) return false;
    if (cSetCur(ctx)) return false;

    void* prog = nullptr;
    if (nCreate(&prog, NVRTC_SRC, "gemm7.cu", 0, nullptr, nullptr)) return false;
    const char* opts[] = {"--gpu-architecture=sm_103a"};
    if (nCompile(prog, 1, opts)) return false;
    size_t cbsz = 0;
    if (nCbSize(prog, &cbsz) || cbsz == 0) return false;
    static char* cubin = new char[cbsz];
    if (nCb(prog, cubin)) return false;

    void* mod = nullptr;
    if (cModLoad(&mod, cubin, 0, nullptr, nullptr)) return false;
    void *fG5 = nullptr, *fG5c = nullptr, *fG7 = nullptr;
    void *fInit = nullptr, *fInit7 = nullptr, *fWb = nullptr, *fWti = nullptr;
    if (cGetFn(&fG5, mod, "gemm5")) return false;
    if (cGetFn(&fG5c, mod, "gemm5c")) return false;
    if (cGetFn(&fG7, mod, "gemm7")) return false;
    if (cGetFn(&fInit, mod, "initt")) return false;
    if (cGetFn(&fInit7, mod, "init7")) return false;
    if (cGetFn(&fWb, mod, "wbuild")) return false;
    if (cGetFn(&fWti, mod, "wtinit")) return false;
    unsigned long long gx = 0, gw = 0, gout = 0, glb = 0, glat = 0,
                       gtqw = 0, gtam = 0;
    size_t sz;
    if (cGetGlb(&gx, &sz, mod, "GX")) return false;
    if (cGetGlb(&gw, &sz, mod, "GW")) return false;
    if (cGetGlb(&gout, &sz, mod, "GOUT")) return false;
    if (cGetGlb(&glb, &sz, mod, "GLB")) return false;
    if (cGetGlb(&glat, &sz, mod, "GLAT")) return false;
    if (cGetGlb(&gtqw, &sz, mod, "GTQW")) return false;
    if (cGetGlb(&gtam, &sz, mod, "GTAM")) return false;
    if (cSetAttr(fG5, 8, SMEM5)) return false;
    if (cSetAttr(fG5c, 8, SMEM5)) return false;
    if (cSetAttr(fG7, 8, SMEM5)) return false;
    if (cSetAttr(fWb, 8, SMEMW)) return false;

    p_cuLaunchKernel = cLaunch;
    g_gx = gx; g_gw = gw; g_glb = glb; g_glat = glat;

    static float row[OUT_F];
    const int ms[4] = {0, 97, 4095, 8191};
    auto check_out = [&](unsigned long long gout_) -> bool {
        for (int ri = 0; ri < 4; ri++) {
            int m = ms[ri];
            if (cD2H(row, gout_ + (unsigned long long)m * OUT_F * 4, OUT_F * 4))
                return false;
            for (int n = 0; n < OUT_F; n++) {
                float ref = 0.0f;
                for (int k = 0; k < IN_F; k++) {
                    int av = (k * 131 + m * 7) % 9 - 4;
                    int bv = (k * 17 + n * 3) % 7 - 3;
                    ref += (av * 0.25f) * (bv * 0.25f);
                }
                if (fabsf(row[n] - ref) > 0.01f) return false;
            }
        }
        return true;
    };

    // ---- wbuild math + layout self-tests ----
    bool wb_math_ok = false, wb_tiled_ok = false;
    {
        if (cLaunch(fWti, 32768, 1, 1, 256, 1, 1, 0, DRV_STREAM, nullptr, nullptr))
            return false;
        if (cSync()) return false;
        static uint16_t* hw = new uint16_t[16777216];
        const int os[4] = {0, 1, 255, 4095};
        auto wref = [&](int o, int i) -> float {
            uint64_t k = (uint64_t)o * 4096 + i;
            int qv = (int)(((k >> 1) * 37ull) & 255ull);
            int nib = (k & 1) ? (qv >> 4) & 15 : qv & 15;
            float a = (float)(((uint32_t)((k >> 6) * 13ull)) % 31u + 1u) * 0.03125f;
            float lora = 0.0f;
            for (int r = 0; r < 64; r++) {
                float lb = (float)((int)(((uint32_t)o * 3u + r * 7u) % 17u) - 8) * 0.015625f;
                float la = (float)((int)(((uint32_t)i * 5u + r * 11u) % 19u) - 9) * 0.015625f;
                lora += lb * la;
            }
            return NF4H[nib] * a + lora;
        };
        auto run_wb = [&](int tiled) -> bool {
            unsigned long long pq = gtqw, pa = gtam, pl = glb, pt = glat, pw2 = gw;
            int tf = tiled;
            void* args[6] = {&pq, &pa, &pl, &pt, &pw2, &tf};
            if (cLaunch(fWb, 512, 1, 1, 256, 1, 1, SMEMW, DRV_STREAM, args, nullptr))
                return false;
            return cSync() == 0;
        };
        // row-major check
        if (run_wb(0)) {
            bool ok = true;
            static uint16_t wrow[IN_F];
            for (int oi = 0; oi < 4 && ok; oi++) {
                int o = os[oi];
                if (cD2H(wrow, gw + (unsigned long long)o * IN_F * 2, IN_F * 2)) { ok = false; break; }
                for (int i = 0; i < IN_F; i++)
                    if (fabsf(h2f(wrow[i]) - wref(o, i)) > 0.01f) { ok = false; break; }
            }
            wb_math_ok = ok;
        }
        // tiled check (full readback, host swizzle formula)
        if (wb_math_ok && run_wb(1)) {
            if (cD2H(hw, gw, (size_t)16777216 * 2) == 0) {
                bool ok = true;
                for (int oi = 0; oi < 4 && ok; oi++) {
                    int o = os[oi];
                    for (int i = 0; i < IN_F; i++) {
                        uint32_t off = (uint32_t)((o & 127) * 128 + (i & 63) * 2);
                        off = off ^ ((off >> 3) & 0x70);
                        uint64_t boff = ((uint64_t)((o >> 7) * 64 + (i >> 6))) * 16384ull + off;
                        if (fabsf(h2f(hw[boff >> 1]) - wref(o, i)) > 0.01f) { ok = false; break; }
                    }
                }
                wb_tiled_ok = ok;
            }
        }
    }

    // ---- gemm7 self-test (tiled integer grid) ----
    if (wb_tiled_ok) {
        if (cLaunch(fInit7, 131072, 1, 1, 256, 1, 1, 0, DRV_STREAM, nullptr, nullptr) == 0 &&
            cSync() == 0) {
            unsigned long long px = gx, pw = gw, po = gout;
            void* args[3] = {&px, &pw, &po};
            if (cLaunch(fG7, 148, 1, 1, 256, 1, 1, SMEM5, DRV_STREAM, args, nullptr) == 0 &&
                cSync() == 0 && check_out(gout)) {
                g_fn_gemm = fG7; g_ok_gemm = true; g_mode = 4;
                g_fn_wbuild = fWb; g_ok_wb = true;
            }
        }
    }

    // ---- fallback: row-major gemm5c / gemm5 ----
    if (!g_ok_gemm) {
        if (cLaunch(fInit, 131072, 1, 1, 256, 1, 1, 0, DRV_STREAM, nullptr, nullptr) ||
            cSync())
            return false;
        unsigned long long px = gx, pw = gw, po = gout;
        void* args[3] = {&px, &pw, &po};
        if (cLaunch(fG5c, 148, 1, 1, 256, 1, 1, SMEM5, DRV_STREAM, args, nullptr) == 0 &&
            cSync() == 0 && check_out(gout)) {
            g_fn_gemm = fG5c; g_ok_gemm = true; g_mode = 1;
        } else if (cLaunch(fG5, 148, 1, 1, 256, 1, 1, SMEM5, DRV_STREAM, args, nullptr) == 0 &&
                   cSync() == 0 && check_out(gout)) {
            g_fn_gemm = fG5; g_ok_gemm = true; g_mode = 1;
        }
        if (g_ok_gemm && wb_math_ok) { g_fn_wbuild = fWb; g_ok_wb = true; }
    }

    return g_ok_gemm;
}

__attribute__((constructor))
static void _init_drv() {
    try_init_tcgen05();
}

// ---------------------------------------------------------------------------
extern "C" void kernel_launch(void* const* d_in, const int* in_sizes, int n_in,
                              void* d_out, int out_size) {
    const float* x  = (const float*)d_in[0];
    const int*   qw = (const int*)d_in[1];
    const float* am = (const float*)d_in[2];
    const float* lA = (const float*)d_in[3];
    const float* lB = (const float*)d_in[4];
    float*       out = (float*)d_out;

    (void)in_sizes; (void)n_in; (void)out_size;

    if (g_ok_gemm) {
        __half* xh = (__half*)(uintptr_t)g_gx;
        __half* wh = (__half*)(uintptr_t)g_gw;

        if (g_mode == 4)
            convert_x_tiled_kernel<<<(M_ROWS * IN_F / 8) / 256, 256>>>(x, (char*)xh);
        else
            convert_x_kernel<<<(M_ROWS * IN_F / 8) / 256, 256>>>(x, xh);

        if (g_ok_wb) {
            cvt_lb_kernel<<<256, 256>>>(lB, (__half*)(uintptr_t)g_glb);
            cvt_lat_kernel<<<64, 256>>>(lA, (__half*)(uintptr_t)g_glat);
            unsigned long long pq = (unsigned long long)(uintptr_t)qw;
            unsigned long long pa = (unsigned long long)(uintptr_t)am;
            unsigned long long pl = g_glb, pt = g_glat, pw = g_gw;
            int tf = (g_mode == 4) ? 1 : 0;
            void* args[6] = {&pq, &pa, &pl, &pt, &pw, &tf};
            p_cuLaunchKernel(g_fn_wbuild, 512, 1, 1, 256, 1, 1, SMEMW,
                             DRV_STREAM, args, nullptr);
        } else {
            build_weff_kernel<<<dim3(IN_F / 128, OUT_F / 64), 256>>>(qw, am, lA, lB, wh);
        }

        unsigned long long px = g_gx, pw2 = g_gw;
        void* po = (void*)out;
        void* args[3] = {&px, &pw2, &po};
        p_cuLaunchKernel(g_fn_gemm, 148, 1, 1, 256, 1, 1, SMEM5,
                         DRV_STREAM, args, nullptr);
    } else {
        __half* xh; __half* wh;
        cudaGetSymbolAddress((void**)&xh, g_Xh);
        cudaGetSymbolAddress((void**)&wh, g_Wh);
        convert_x_kernel<<<(M_ROWS * IN_F / 8) / 256, 256>>>(x, xh);
        build_weff_kernel<<<dim3(IN_F / 128, OUT_F / 64), 256>>>(qw, am, lA, lB, wh);
        cudaFuncSetAttribute(gemm_f16_kernel,
                             cudaFuncAttributeMaxDynamicSharedMemorySize, SMEM_TOTAL);
        gemm_f16_kernel<<<148, 512, SMEM_TOTAL>>>(xh, wh, out);
    }
}

// round 13
// speedup vs baseline: 1.0557x; 1.0455x over previous
#include <cuda_runtime.h>
#include <cuda_fp16.h>
#include <cstdint>
#include <cstdio>
#include <cstring>
#include <cmath>
#include <dlfcn.h>

#define IN_F   4096
#define OUT_F  4096
#define M_ROWS 8192

// Host-module fp16 scratch (used by the host fallback path).
__device__ __half g_Xh[(size_t)M_ROWS * IN_F];
__device__ __half g_Wh[(size_t)OUT_F * IN_F];

__constant__ float NF4[16] = {
    -1.0f, -0.6961928009986877f, -0.5250730514526367f, -0.39491748809814453f,
    -0.28444138169288635f, -0.18477343022823334f, -0.09105003625154495f, 0.0f,
    0.07958029955625534f, 0.16093020141124725f, 0.24611230194568634f,
    0.33791524171829224f, 0.4407098889350891f, 0.5626170039176941f,
    0.7229568362236023f, 1.0f
};

static const float NF4H[16] = {
    -1.0f, -0.6961928009986877f, -0.5250730514526367f, -0.39491748809814453f,
    -0.28444138169288635f, -0.18477343022823334f, -0.09105003625154495f, 0.0f,
    0.07958029955625534f, 0.16093020141124725f, 0.24611230194568634f,
    0.33791524171829224f, 0.4407098889350891f, 0.5626170039176941f,
    0.7229568362236023f, 1.0f
};

__device__ __forceinline__ uint32_t smem_u32(const void* p) {
    uint32_t a;
    asm("{ .reg .u64 t; cvta.to.shared.u64 t, %1; cvt.u32.u64 %0, t; }" : "=r"(a) : "l"(p));
    return a;
}

// ---------------------------------------------------------------------------
// Kernel A: convert x (fp32) -> dst (fp16) row-major. 8 elems/thread.
// ---------------------------------------------------------------------------
__global__ void convert_x_kernel(const float* __restrict__ x, __half* __restrict__ dst) {
    size_t i = ((size_t)blockIdx.x * 256 + threadIdx.x) * 8;
    float4 v0 = *(const float4*)(x + i);
    float4 v1 = *(const float4*)(x + i + 4);
    __half2 h0 = __floats2half2_rn(v0.x, v0.y);
    __half2 h1 = __floats2half2_rn(v0.z, v0.w);
    __half2 h2 = __floats2half2_rn(v1.x, v1.y);
    __half2 h3 = __floats2half2_rn(v1.z, v1.w);
    uint4 o;
    o.x = *(uint32_t*)&h0; o.y = *(uint32_t*)&h1;
    o.z = *(uint32_t*)&h2; o.w = *(uint32_t*)&h3;
    *(uint4*)&dst[i] = o;
}

// Kernel A': convert x -> TILED layout: tile (m>>7, k>>6) contiguous 16KB SW128.
__global__ void convert_x_tiled_kernel(const float* __restrict__ x, char* __restrict__ dst) {
    size_t i = ((size_t)blockIdx.x * 256 + threadIdx.x) * 8;
    float4 v0 = *(const float4*)(x + i);
    float4 v1 = *(const float4*)(x + i + 4);
    __half2 h0 = __floats2half2_rn(v0.x, v0.y);
    __half2 h1 = __floats2half2_rn(v0.z, v0.w);
    __half2 h2 = __floats2half2_rn(v1.x, v1.y);
    __half2 h3 = __floats2half2_rn(v1.z, v1.w);
    uint4 o;
    o.x = *(uint32_t*)&h0; o.y = *(uint32_t*)&h1;
    o.z = *(uint32_t*)&h2; o.w = *(uint32_t*)&h3;
    const uint32_t m = (uint32_t)(i >> 12), k = (uint32_t)(i & 4095);
    uint32_t off = (m & 127) * 128 + (k & 63) * 2;
    off = off ^ ((off >> 3) & 0x70);
    const size_t boff = ((size_t)((m >> 7) * 64 + (k >> 6))) * 16384 + off;
    *(uint4*)(dst + boff) = o;
}

// lora_B [4096][64] fp32 -> fp16 same layout
__global__ void cvt_lb_kernel(const float* __restrict__ lB, __half* __restrict__ lb) {
    size_t i = ((size_t)blockIdx.x * 256 + threadIdx.x) * 4;
    float4 v = *(const float4*)(lB + i);
    __half h[4] = {__float2half_rn(v.x), __float2half_rn(v.y),
                   __float2half_rn(v.z), __float2half_rn(v.w)};
    *(uint2*)&lb[i] = *(uint2*)h;
}

// lora_A [64][4096] fp32 -> lat [4096][64] fp16 (transpose)
__global__ void cvt_lat_kernel(const float* __restrict__ lA, __half* __restrict__ lat) {
    __shared__ float s[64][65];
    const int tid = threadIdx.x;
    const int i0 = blockIdx.x * 64;
    for (int idx = tid; idx < 4096; idx += 256) {
        int r = idx >> 6, ii = idx & 63;
        s[r][ii] = lA[r * IN_F + i0 + ii];
    }
    __syncthreads();
    int ii = tid >> 2, rs = (tid & 3) * 16;
    __half h[16];
#pragma unroll
    for (int j = 0; j < 16; j++) h[j] = __float2half_rn(s[rs + j][ii]);
    uint4* dst = (uint4*)&lat[(size_t)(i0 + ii) * 64 + rs];
    dst[0] = *(uint4*)&h[0];
    dst[1] = *(uint4*)&h[8];
}

// ---------------------------------------------------------------------------
// Host fallback: W_eff = NF4 dequant * absmax + lora_B @ lora_A  (fp16, row-major)
// ---------------------------------------------------------------------------
__global__ void build_weff_kernel(const int* __restrict__ qweight,
                                  const float* __restrict__ absmax,
                                  const float* __restrict__ lA,
                                  const float* __restrict__ lB,
                                  __half* __restrict__ dst) {
    __shared__ float Bsh[64][64];
    __shared__ float Ash[64][128];

    const int tid = threadIdx.x;
    const int o0 = blockIdx.y * 64;
    const int i0 = blockIdx.x * 128;

    for (int t = tid; t < 64 * 64; t += 256) {
        int o = t >> 6, r = t & 63;
        Bsh[r][o] = lB[(o0 + o) * 64 + r];
    }
    for (int t = tid; t < 64 * 128; t += 256) {
        int r = t >> 7, c = t & 127;
        Ash[r][c] = lA[r * IN_F + i0 + c];
    }
    __syncthreads();

    const int oo0 = (tid >> 4) * 4;
    const int ii0 = (tid & 15) * 8;

    float acc[4][8];
#pragma unroll
    for (int a = 0; a < 4; a++)
#pragma unroll
        for (int b = 0; b < 8; b++) acc[a][b] = 0.0f;

#pragma unroll 4
    for (int r = 0; r < 64; r++) {
        float4 a0 = *(const float4*)&Ash[r][ii0];
        float4 a1 = *(const float4*)&Ash[r][ii0 + 4];
#pragma unroll
        for (int oo = 0; oo < 4; oo++) {
            float bv = Bsh[r][oo0 + oo];
            acc[oo][0] += bv * a0.x; acc[oo][1] += bv * a0.y;
            acc[oo][2] += bv * a0.z; acc[oo][3] += bv * a0.w;
            acc[oo][4] += bv * a1.x; acc[oo][5] += bv * a1.y;
            acc[oo][6] += bv * a1.z; acc[oo][7] += bv * a1.w;
        }
    }

#pragma unroll
    for (int oo = 0; oo < 4; oo++) {
        const int o = o0 + oo0 + oo;
        const size_t k = (size_t)o * IN_F + i0 + ii0;
        const int4 qv = ((const int4*)qweight)[k >> 3];
        const float am = absmax[k >> 6];

        float w[8];
        w[0] = NF4[qv.x & 15];  w[1] = NF4[(qv.x >> 4) & 15];
        w[2] = NF4[qv.y & 15];  w[3] = NF4[(qv.y >> 4) & 15];
        w[4] = NF4[qv.z & 15];  w[5] = NF4[(qv.z >> 4) & 15];
        w[6] = NF4[qv.w & 15];  w[7] = NF4[(qv.w >> 4) & 15];

        __half2 h0 = __floats2half2_rn(w[0] * am + acc[oo][0], w[1] * am + acc[oo][1]);
        __half2 h1 = __floats2half2_rn(w[2] * am + acc[oo][2], w[3] * am + acc[oo][3]);
        __half2 h2 = __floats2half2_rn(w[4] * am + acc[oo][4], w[5] * am + acc[oo][5]);
        __half2 h3 = __floats2half2_rn(w[6] * am + acc[oo][6], w[7] * am + acc[oo][7]);
        uint4 pk;
        pk.x = *(uint32_t*)&h0; pk.y = *(uint32_t*)&h1;
        pk.z = *(uint32_t*)&h2; pk.w = *(uint32_t*)&h3;
        *(uint4*)&dst[k] = pk;
    }
}

// ---------------------------------------------------------------------------
// Host fallback GEMM (proven 778us): fp16 mma.sync, 512 thr, 4-stage.
// ---------------------------------------------------------------------------
constexpr int BM = 128, BN = 256, BK = 64, S = 4;
constexpr int NT = IN_F / BK;
constexpr int A_BYTES = BM * 128;
constexpr int B_BYTES = BN * 128;
constexpr int STAGE = A_BYTES + B_BYTES;
constexpr int SMEM_TOTAL = 1024 + S * STAGE;
constexpr int TOTAL_TILES = (M_ROWS / BM) * (OUT_F / BN);

__device__ __forceinline__ void mma_f16(float c[4], const uint32_t a[4],
                                        uint32_t b0, uint32_t b1) {
    asm volatile(
        "mma.sync.aligned.m16n8k16.row.col.f32.f16.f16.f32 "
        "{%0,%1,%2,%3}, {%4,%5,%6,%7}, {%8,%9}, {%0,%1,%2,%3};"
        : "+f"(c[0]), "+f"(c[1]), "+f"(c[2]), "+f"(c[3])
        : "r"(a[0]), "r"(a[1]), "r"(a[2]), "r"(a[3]), "r"(b0), "r"(b1));
}

__device__ __forceinline__ void ldsm4(uint32_t& r0, uint32_t& r1,
                                      uint32_t& r2, uint32_t& r3, uint32_t addr) {
    asm volatile("ldmatrix.sync.aligned.m8n8.x4.shared.b16 {%0,%1,%2,%3}, [%4];"
                 : "=r"(r0), "=r"(r1), "=r"(r2), "=r"(r3) : "r"(addr));
}

__device__ __forceinline__ void st_cs_f2(float* p, float a, float b) {
    asm volatile("st.global.cs.v2.f32 [%0], {%1,%2};" :: "l"(p), "f"(a), "f"(b)
                 : "memory");
}

__device__ __forceinline__ void issue_stage(uint32_t sA, uint32_t sB,
                                            const __half* xb, const __half* wb,
                                            int tid) {
#pragma unroll
    for (int r = 0; r < 2; r++) {
        int i = tid + r * 512;
        int row = i >> 3, c = i & 7;
        uint32_t off = (uint32_t)(row * 128 + ((c * 16) ^ ((row & 7) << 4)));
        const __half* src = xb + (size_t)row * IN_F + c * 8;
        asm volatile("cp.async.cg.shared.global.L2::256B [%0], [%1], 16;\n"
                     :: "r"(sA + off), "l"(src));
    }
#pragma unroll
    for (int r = 0; r < 4; r++) {
        int i = tid + r * 512;
        int row = i >> 3, c = i & 7;
        uint32_t off = (uint32_t)(row * 128 + ((c * 16) ^ ((row & 7) << 4)));
        const __half* src = wb + (size_t)row * IN_F + c * 8;
        asm volatile("cp.async.cg.shared.global.L2::256B [%0], [%1], 16;\n"
                     :: "r"(sB + off), "l"(src));
    }
}

__global__ void __launch_bounds__(512, 1)
gemm_f16_kernel(const __half* __restrict__ Xh, const __half* __restrict__ Wh,
                float* __restrict__ out) {
    extern __shared__ char sm[];
    const uint32_t stage0 = (smem_u32(sm) + 1023) & ~1023u;

    const int tid = threadIdx.x;
    const int wid = tid >> 5;
    const int lane = tid & 31;
    const int warp_m = wid & 3;
    const int warp_n = wid >> 2;
    const int g = lane >> 3;
    const int r = lane & 7;

    uint32_t a_rowoff[2], a_xr[2];
    const uint32_t a_kc = (uint32_t)((g >> 1) * 16);
#pragma unroll
    for (int mf = 0; mf < 2; mf++) {
        int row = warp_m * 32 + mf * 16 + (g & 1) * 8 + r;
        a_rowoff[mf] = row * 128;
        a_xr[mf] = (row & 7) << 4;
    }
    uint32_t b_rowoff[4], b_xr[4];
    const uint32_t b_kc = (uint32_t)((g & 1) * 16);
#pragma unroll
    for (int p = 0; p < 4; p++) {
        int row = warp_n * 64 + p * 16 + (g >> 1) * 8 + r;
        b_rowoff[p] = row * 128;
        b_xr[p] = (row & 7) << 4;
    }

    for (int t = blockIdx.x; t < TOTAL_TILES; t += gridDim.x) {
        const int mBase = (t >> 4) * BM;
        const int nBase = (t & 15) * BN;
        const __half* xt = Xh + (size_t)mBase * IN_F;
        const __half* wt = Wh + (size_t)nBase * IN_F;

        float acc[2][8][4];
#pragma unroll
        for (int i = 0; i < 2; i++)
#pragma unroll
            for (int j = 0; j < 8; j++)
#pragma unroll
                for (int l = 0; l < 4; l++) acc[i][j][l] = 0.0f;

#pragma unroll
        for (int p = 0; p < S - 1; p++) {
            uint32_t sA = stage0 + p * STAGE;
            issue_stage(sA, sA + A_BYTES, xt + p * BK, wt + p * BK, tid);
            asm volatile("cp.async.commit_group;\n" ::: "memory");
        }

        for (int kt = 0; kt < NT; kt++) {
            asm volatile("cp.async.wait_group %0;\n" :: "n"(S - 2) : "memory");
            __syncthreads();

            if (kt + S - 1 < NT) {
                const int s2 = (kt + S - 1) % S;
                uint32_t sA = stage0 + s2 * STAGE;
                issue_stage(sA, sA + A_BYTES,
                            xt + (kt + S - 1) * BK, wt + (kt + S - 1) * BK, tid);
            }
            asm volatile("cp.async.commit_group;\n" ::: "memory");

            const uint32_t sA = stage0 + (kt % S) * STAGE;
            const uint32_t sB = sA + A_BYTES;

#pragma unroll
            for (int q = 0; q < 4; q++) {
                uint32_t a[2][4];
#pragma unroll
                for (int mf = 0; mf < 2; mf++)
                    ldsm4(a[mf][0], a[mf][1], a[mf][2], a[mf][3],
                          sA + a_rowoff[mf] + (((q * 32) + a_kc) ^ a_xr[mf]));
                uint32_t b[8][2];
#pragma unroll
                for (int p = 0; p < 4; p++)
                    ldsm4(b[2 * p][0], b[2 * p][1], b[2 * p + 1][0], b[2 * p + 1][1],
                          sB + b_rowoff[p] + (((q * 32) + b_kc) ^ b_xr[p]));
#pragma unroll
                for (int mf = 0; mf < 2; mf++)
#pragma unroll
                    for (int nf = 0; nf < 8; nf++)
                        mma_f16(acc[mf][nf], a[mf], b[nf][0], b[nf][1]);
            }
        }
        asm volatile("cp.async.wait_group 0;\n" ::: "memory");

#pragma unroll
        for (int mf = 0; mf < 2; mf++) {
#pragma unroll
            for (int nf = 0; nf < 8; nf++) {
                const int row = mBase + warp_m * 32 + mf * 16 + (lane >> 2);
                const int col = nBase + warp_n * 64 + nf * 8 + (lane & 3) * 2;
                st_cs_f2(&out[(size_t)row * OUT_F + col],
                         acc[mf][nf][0], acc[mf][nf][1]);
                st_cs_f2(&out[(size_t)(row + 8) * OUT_F + col],
                         acc[mf][nf][2], acc[mf][nf][3]);
            }
        }
        __syncthreads();
    }
}

// ===========================================================================
// NVRTC module: gemm7 (bulk-copy, tiled, FIXED drain), gemm5c/gemm5 backstops,
// wbuild (row-major or tiled), init kernels.
// ===========================================================================
static const char* NVRTC_SRC = R"NVSRC(
typedef unsigned int u32;
typedef unsigned long long u64;
typedef unsigned short u16;

__device__ __align__(128) u16 GX[33554432];  // X fp16 (row-major OR tiled)
__device__ __align__(128) u16 GW[16777216];  // W fp16 (row-major OR tiled)
__device__ float GOUT[33554432];             // gemm self-test output
__device__ u16 GLB[262144];                  // lora_B fp16 [4096][64]
__device__ u16 GLAT[262144];                 // lora_A^T fp16 [4096][64]
__device__ int GTQW[8388608];                // wbuild self-test qweight
__device__ float GTAM[262144];               // wbuild self-test absmax

__constant__ float NF4D[16] = {
    -1.0f, -0.6961928009986877f, -0.5250730514526367f, -0.39491748809814453f,
    -0.28444138169288635f, -0.18477343022823334f, -0.09105003625154495f, 0.0f,
    0.07958029955625534f, 0.16093020141124725f, 0.24611230194568634f,
    0.33791524171829224f, 0.4407098889350891f, 0.5626170039176941f,
    0.7229568362236023f, 1.0f
};

#define MWAIT(ba, ph) do { u32 _d; \
    asm volatile("{ .reg .pred p; mbarrier.try_wait.parity.acquire.cta.shared::cta.b64 p, [%1], %2; selp.b32 %0,1,0,p; }" \
                 : "=r"(_d) : "r"(ba), "r"(ph) : "memory"); \
    if (!_d) { \
        asm volatile("{ .reg .pred P1; WL%=: mbarrier.try_wait.parity.acquire.cta.shared::cta.b64 P1, [%0], %1, 0x989680; @P1 bra.uni WD%=; bra.uni WL%=; WD%=: }" \
                     :: "r"(ba), "r"(ph) : "memory"); } } while(0)

#define LDTM32(rr, addr) \
    asm volatile("tcgen05.ld.sync.aligned.32x32b.x32.b32 " \
        "{%0,%1,%2,%3,%4,%5,%6,%7,%8,%9,%10,%11,%12,%13,%14,%15," \
        "%16,%17,%18,%19,%20,%21,%22,%23,%24,%25,%26,%27,%28,%29,%30,%31}, [%32];" \
        : "=r"(rr[0]), "=r"(rr[1]), "=r"(rr[2]), "=r"(rr[3]), \
          "=r"(rr[4]), "=r"(rr[5]), "=r"(rr[6]), "=r"(rr[7]), \
          "=r"(rr[8]), "=r"(rr[9]), "=r"(rr[10]), "=r"(rr[11]), \
          "=r"(rr[12]), "=r"(rr[13]), "=r"(rr[14]), "=r"(rr[15]), \
          "=r"(rr[16]), "=r"(rr[17]), "=r"(rr[18]), "=r"(rr[19]), \
          "=r"(rr[20]), "=r"(rr[21]), "=r"(rr[22]), "=r"(rr[23]), \
          "=r"(rr[24]), "=r"(rr[25]), "=r"(rr[26]), "=r"(rr[27]), \
          "=r"(rr[28]), "=r"(rr[29]), "=r"(rr[30]), "=r"(rr[31]) \
        : "r"(addr))

#define BULK(dst, src, sz, mbar) \
    asm volatile("cp.async.bulk.shared::cta.global.mbarrier::complete_tx::bytes " \
                 "[%0], [%1], %2, [%3];" \
                 :: "r"(dst), "l"(src), "r"(sz), "r"(mbar) : "memory")

#define EXPECT_TX(mbar, n) \
    asm volatile("mbarrier.arrive.expect_tx.shared.b64 _, [%0], %1;" \
                 :: "r"(mbar), "r"(n) : "memory")

#define MMA8(tmem, a0, a1, bd, IDESC, en) do { \
    asm volatile("{ .reg .pred p; setp.ne.u32 p, %5, 0; " \
        "tcgen05.mma.cta_group::1.kind::f16 [%0], %1, %2, %3, {%4,%4,%4,%4}, p; }" \
        :: "r"(tmem), "l"(a0), "l"(bd), "r"(IDESC), "r"(0u), "r"(en) : "memory"); \
    asm volatile("{ .reg .pred p; setp.ne.u32 p, %5, 0; " \
        "tcgen05.mma.cta_group::1.kind::f16 [%0], %1, %2, %3, {%4,%4,%4,%4}, p; }" \
        :: "r"((tmem) + 256), "l"(a1), "l"(bd), "r"(IDESC), "r"(0u), "r"(en) : "memory"); \
} while(0)

__device__ __forceinline__ u32 sm2u32(const void* p) {
    u32 a;
    asm("{ .reg .u64 t; cvta.to.shared.u64 t, %1; cvt.u32.u64 %0, t; }" : "=r"(a) : "l"(p));
    return a;
}

__device__ __forceinline__ u32 swz(u32 off) { return off ^ ((off >> 3) & 0x70); }

extern "C" __global__ void initt() {
    u64 i = (u64)blockIdx.x * 256 + threadIdx.x;
    const u16 T[9] = {0xBC00,0xBA00,0xB800,0xB400,0,0x3400,0x3800,0x3A00,0x3C00};
    if (i < 33554432ull) {
        u32 m = (u32)(i >> 12), k = (u32)(i & 4095);
        GX[i] = T[(k*131u + m*7u) % 9u];
    }
    if (i < 16777216ull) {
        u32 n = (u32)(i >> 12), k = (u32)(i & 4095);
        GW[i] = T[(k*17u + n*3u) % 7u + 1u];
    }
}

extern "C" __global__ void init7() {
    u64 i = (u64)blockIdx.x * 256 + threadIdx.x;
    const u16 T[9] = {0xBC00,0xBA00,0xB800,0xB400,0,0x3400,0x3800,0x3A00,0x3C00};
    if (i < 33554432ull) {
        u32 m = (u32)(i >> 12), k = (u32)(i & 4095);
        u64 boff = ((u64)((m >> 7) * 64u + (k >> 6))) * 16384ull
                 + (u64)swz((m & 127u) * 128u + (k & 63u) * 2u);
        GX[boff >> 1] = T[(k*131u + m*7u) % 9u];
    }
    if (i < 16777216ull) {
        u32 n = (u32)(i >> 12), k = (u32)(i & 4095);
        u64 boff = ((u64)((n >> 7) * 64u + (k >> 6))) * 16384ull
                 + (u64)swz((n & 127u) * 128u + (k & 63u) * 2u);
        GW[boff >> 1] = T[(k*17u + n*3u) % 7u + 1u];
    }
}

extern "C" __global__ void wtinit() {
    u64 i = (u64)blockIdx.x * 256 + threadIdx.x;
    if (i < 8388608ull) GTQW[i] = (int)((i * 37ull) & 255ull);
    if (i < 262144ull) {
        GTAM[i] = (float)((u32)(i * 13ull) % 31u + 1u) * 0.03125f;
        u32 o = (u32)(i >> 6), r = (u32)(i & 63);
        float lb = (float)((int)((o*3u + r*7u) % 17u) - 8) * 0.015625f;
        float la = (float)((int)((o*5u + r*11u) % 19u) - 9) * 0.015625f;
        u16 hb, ha;
        asm("cvt.rn.f16.f32 %0, %1;" : "=h"(hb) : "f"(lb));
        asm("cvt.rn.f16.f32 %0, %1;" : "=h"(ha) : "f"(la));
        GLB[i] = hb;
        GLAT[i] = ha;
    }
}

__device__ __forceinline__ void ld_sub(u32 dst, const char* src, int tid, int iters) {
#pragma unroll
    for (int r = 0; r < 8; r++) {
        if (r >= iters) break;
        int i = tid + r * 256; int row = i >> 3, c = i & 7;
        u32 off = (u32)(row * 128 + ((c * 16) ^ ((row & 7) << 4)));
        asm volatile("cp.async.cg.shared.global.L2::256B [%0], [%1], 16;"
                     :: "r"(dst + off), "l"(src + (u64)row * 8192 + c * 16));
    }
}

// ---------------- gemm5 (single M-tile backstop, row-major operands) ----------------
__device__ __forceinline__ void ld_stage(u32 sA, u32 sB, const char* xb,
                                         const char* wb, int tid) {
#pragma unroll
    for (int r = 0; r < 4; r++) {
        int i = tid + r * 256; int row = i >> 3, c = i & 7;
        u32 off = (u32)(row * 128 + ((c * 16) ^ ((row & 7) << 4)));
        asm volatile("cp.async.cg.shared.global.L2::256B [%0], [%1], 16;"
                     :: "r"(sA + off), "l"(xb + (u64)row * 8192 + c * 16));
    }
#pragma unroll
    for (int r = 0; r < 8; r++) {
        int i = tid + r * 256; int row = i >> 3, c = i & 7;
        u32 off = (u32)(row * 128 + ((c * 16) ^ ((row & 7) << 4)));
        asm volatile("cp.async.cg.shared.global.L2::256B [%0], [%1], 16;"
                     :: "r"(sB + off), "l"(wb + (u64)row * 8192 + c * 16));
    }
}

extern "C" __global__ void __launch_bounds__(256, 1)
gemm5(const char* __restrict__ X, const char* __restrict__ W,
      float* __restrict__ out) {
    extern __shared__ char sm[];
    u32 base = (sm2u32(sm) + 1023) & ~1023u;
    const u32 tptr = base;
    const u32 mb = base + 16;
    const u32 st0 = base + 1024;
    const int tid = threadIdx.x, wid = tid >> 5, lid = tid & 31;

    if (wid == 0)
        asm volatile("tcgen05.alloc.cta_group::1.sync.aligned.shared::cta.b32 [%0], %1;"
                     :: "r"(tptr), "r"(256u) : "memory");
    if (tid == 0) {
#pragma unroll
        for (int s = 0; s < 4; s++)
            asm volatile("mbarrier.init.shared.b64 [%0], %1;"
                         :: "r"(mb + s * 8), "r"(1u) : "memory");
    }
    __syncthreads();
    u32 tmem; asm volatile("ld.shared.b32 %0,[%1];" : "=r"(tmem) : "r"(tptr));

    const u64 DBASE = (2ull << 61) | (1ull << 46) | (64ull << 32) | (1ull << 16);
    const u32 IDESC = (1u << 4) | (32u << 17) | (8u << 24);

#pragma unroll 1
    for (int t = blockIdx.x; t < 1024; t += gridDim.x) {
        const int mBase = (t >> 4) * 128, nBase = (t & 15) * 256;
        const char* xt = X + (u64)mBase * 8192;
        const char* wt = W + (u64)nBase * 8192;

#pragma unroll
        for (int p = 0; p < 4; p++) {
            u32 sA = st0 + p * 49152;
            ld_stage(sA, sA + 16384, xt + p * 128, wt + p * 128, tid);
            asm volatile("cp.async.commit_group;" ::: "memory");
        }

#pragma unroll 1
        for (int kt = 0; kt < 64; kt++) {
            const int s = kt & 3;
            const u32 sA = st0 + s * 49152, sB = sA + 16384;
            asm volatile("cp.async.wait_group 3;" ::: "memory");
            __syncthreads();

            if (wid == 0) {
                u32 ep;
                asm volatile("{ .reg .pred p; elect.sync _|p, 0xFFFFFFFF; selp.b32 %0,1,0,p; }"
                             : "=r"(ep));
                if (ep) {
                    asm volatile("fence.proxy.async.shared::cta;" ::: "memory");
                    u64 ad = DBASE | ((u64)(sA >> 4) & 0x3FFF);
                    u64 bd = DBASE | ((u64)(sB >> 4) & 0x3FFF);
#pragma unroll
                    for (int q = 0; q < 4; q++) {
                        u32 en = (kt > 0 || q > 0) ? 1u : 0u;
                        asm volatile("{ .reg .pred p; setp.ne.u32 p, %5, 0; "
                            "tcgen05.mma.cta_group::1.kind::f16 [%0], %1, %2, %3, {%4,%4,%4,%4}, p; }"
                            :: "r"(tmem), "l"(ad + q * 2), "l"(bd + q * 2),
                               "r"(IDESC), "r"(0u), "r"(en) : "memory");
                    }
                    asm volatile("tcgen05.commit.cta_group::1.mbarrier::arrive::one.shared::cluster.b64 [%0];"
                                 :: "r"(mb + s * 8) : "memory");
                }
            }

            if (kt + 4 < 64) {
                u32 ph = (u32)((kt >> 2) & 1);
                MWAIT(mb + s * 8, ph);
                ld_stage(sA, sB, xt + (kt + 4) * 128, wt + (kt + 4) * 128, tid);
            }
            asm volatile("cp.async.commit_group;" ::: "memory");
        }

        MWAIT(mb + 24, 1u);
        asm volatile("tcgen05.fence::after_thread_sync;" ::: "memory");

        if (wid < 4) {
            float* dst = out + (u64)(mBase + wid * 32 + lid) * 4096 + nBase;
#pragma unroll
            for (int ch = 0; ch < 8; ch++) {
                u32 rr[32];
                LDTM32(rr, tmem + ch * 32);
                asm volatile("tcgen05.wait::ld.sync.aligned;" ::: "memory");
#pragma unroll
                for (int j = 0; j < 8; j++)
                    asm volatile("st.global.cs.v4.b32 [%0], {%1,%2,%3,%4};"
                                 :: "l"(dst + ch * 32 + j * 4),
                                    "r"(rr[4 * j]), "r"(rr[4 * j + 1]),
                                    "r"(rr[4 * j + 2]), "r"(rr[4 * j + 3]) : "memory");
            }
            asm volatile("tcgen05.fence::before_thread_sync;" ::: "memory");
        }
        __syncthreads();
    }

    __syncthreads();
    if (wid == 0) {
        asm volatile("tcgen05.relinquish_alloc_permit.cta_group::1.sync.aligned;");
        asm volatile("tcgen05.dealloc.cta_group::1.sync.aligned.b32 %0, %1;"
                     :: "r"(tmem), "r"(256u));
    }
}

// ---------------- gemm5c: 2 M-tiles, decoupled cp.async (row-major) ----------------
extern "C" __global__ void __launch_bounds__(256, 1)
gemm5c(const char* __restrict__ X, const char* __restrict__ W,
       float* __restrict__ out) {
    extern __shared__ char sm[];
    u32 base = (sm2u32(sm) + 1023) & ~1023u;
    const u32 tptr = base;
    const u32 mb = base + 16;
    const u32 st0 = base + 1024;
    const int tid = threadIdx.x, wid = tid >> 5, lid = tid & 31;

    if (wid == 0)
        asm volatile("tcgen05.alloc.cta_group::1.sync.aligned.shared::cta.b32 [%0], %1;"
                     :: "r"(tptr), "r"(512u) : "memory");
    if (tid == 0) {
#pragma unroll
        for (int s = 0; s < 3; s++)
            asm volatile("mbarrier.init.shared.b64 [%0], %1;"
                         :: "r"(mb + s * 8), "r"(1u) : "memory");
    }
    __syncthreads();
    u32 tmem; asm volatile("ld.shared.b32 %0,[%1];" : "=r"(tmem) : "r"(tptr));

    const u64 DBASE = (2ull << 61) | (1ull << 46) | (64ull << 32) | (1ull << 16);
    const u32 IDESC = (1u << 4) | (32u << 17) | (8u << 24);

    int bp1 = 0, bp2 = 0;

#pragma unroll 1
    for (int t = blockIdx.x; t < 512; t += gridDim.x) {
        const int mBase = (t >> 4) * 256, nBase = (t & 15) * 256;
        const char* x0 = X + (u64)mBase * 8192;
        const char* x1 = x0 + 1048576;
        const char* wt = W + (u64)nBase * 8192;

#pragma unroll
        for (int p = 0; p < 2; p++) {
            u32 sA0 = st0 + p * 65536;
            ld_sub(sA0,         x0 + p * 128, tid, 4);
            ld_sub(sA0 + 16384, x1 + p * 128, tid, 4);
            ld_sub(sA0 + 32768, wt + p * 128, tid, 8);
            asm volatile("cp.async.commit_group;" ::: "memory");
        }

#pragma unroll 1
        for (int kt = 0; kt < 64; kt++) {
            const int kdiv = kt / 3;
            const int s = kt - kdiv * 3;
            const u32 sA0 = st0 + s * 65536, sA1 = sA0 + 16384, sB = sA0 + 32768;
            asm volatile("cp.async.wait_group 1;" ::: "memory");
            __syncthreads();

            if (wid == 0) {
                u32 ep;
                asm volatile("{ .reg .pred p; elect.sync _|p, 0xFFFFFFFF; selp.b32 %0,1,0,p; }"
                             : "=r"(ep));
                if (ep) {
                    asm volatile("fence.proxy.async.shared::cta;" ::: "memory");
                    u64 a0 = DBASE | ((u64)(sA0 >> 4) & 0x3FFF);
                    u64 a1 = DBASE | ((u64)(sA1 >> 4) & 0x3FFF);
                    u64 bd = DBASE | ((u64)(sB >> 4) & 0x3FFF);
#pragma unroll
                    for (int q = 0; q < 4; q++) {
                        u32 en = (kt > 0 || q > 0) ? 1u : 0u;
                        MMA8(tmem, a0 + q * 2, a1 + q * 2, bd + q * 2, IDESC, en);
                    }
                    asm volatile("tcgen05.commit.cta_group::1.mbarrier::arrive::one.shared::cluster.b64 [%0];"
                                 :: "r"(mb + s * 8) : "memory");
                }
            }

            if (kt + 2 < 64) {
                const int sd = (kt + 2) - ((kt + 2) / 3) * 3;
                const u32 dA0 = st0 + sd * 65536;
                if (kt >= 1) {
                    const int kp = kt - 1;
                    const int kdv = kp / 3;
                    const int sp = kp - kdv * 3;
                    int bps = (sp == 0) ? 0 : ((sp == 1) ? bp1 : bp2);
                    u32 ph = (u32)(bps ^ (kdv & 1));
                    MWAIT(mb + sp * 8, ph);
                }
                ld_sub(dA0,         x0 + (kt + 2) * 128, tid, 4);
                ld_sub(dA0 + 16384, x1 + (kt + 2) * 128, tid, 4);
                ld_sub(dA0 + 32768, wt + (kt + 2) * 128, tid, 8);
            }
            asm volatile("cp.async.commit_group;" ::: "memory");
        }

        MWAIT(mb, 1u);
        asm volatile("tcgen05.fence::after_thread_sync;" ::: "memory");

        {
            const int half = wid >> 2, wr = wid & 3;
            float* dst = out + (u64)(mBase + half * 128 + wr * 32 + lid) * 4096 + nBase;
            const u32 tm = tmem + half * 256;
#pragma unroll
            for (int ch = 0; ch < 8; ch++) {
                u32 rr[32];
                LDTM32(rr, tm + ch * 32);
                asm volatile("tcgen05.wait::ld.sync.aligned;" ::: "memory");
#pragma unroll
                for (int j = 0; j < 8; j++)
                    asm volatile("st.global.cs.v4.b32 [%0], {%1,%2,%3,%4};"
                                 :: "l"(dst + ch * 32 + j * 4),
                                    "r"(rr[4 * j]), "r"(rr[4 * j + 1]),
                                    "r"(rr[4 * j + 2]), "r"(rr[4 * j + 3]) : "memory");
            }
            asm volatile("tcgen05.fence::before_thread_sync;" ::: "memory");
        }
        __syncthreads();
        bp1 ^= 1; bp2 ^= 1;
    }

    __syncthreads();
    if (wid == 0) {
        asm volatile("tcgen05.relinquish_alloc_permit.cta_group::1.sync.aligned;");
        asm volatile("tcgen05.dealloc.cta_group::1.sync.aligned.b32 %0, %1;"
                     :: "r"(tmem), "r"(512u));
    }
}

// ---------------- gemm7: bulk-copy pipeline, TILED operands, FIXED drain ----------
// The producer (one elected thread) consumes EVERY mbarrier phase with exact
// per-slot parity counters, then __syncthreads releases the consumers.
// (Previous bug: consumers waited parity-1 on a barrier that flips every
//  commit -> released after the 2nd commit instead of the 22nd.)
extern "C" __global__ void __launch_bounds__(256, 1)
gemm7(const char* __restrict__ X, const char* __restrict__ W,
      float* __restrict__ out) {
    extern __shared__ char sm[];
    u32 base = (sm2u32(sm) + 1023) & ~1023u;
    const u32 tptr = base;
    const u32 mbc = base + 16;
    const u32 mbf = base + 48;
    const u32 st0 = base + 1024;
    const int tid = threadIdx.x, wid = tid >> 5, lid = tid & 31;

    if (wid == 0)
        asm volatile("tcgen05.alloc.cta_group::1.sync.aligned.shared::cta.b32 [%0], %1;"
                     :: "r"(tptr), "r"(512u) : "memory");
    if (tid == 0) {
#pragma unroll
        for (int s = 0; s < 3; s++) {
            asm volatile("mbarrier.init.shared.b64 [%0], %1;"
                         :: "r"(mbc + s * 8), "r"(1u) : "memory");
            asm volatile("mbarrier.init.shared.b64 [%0], %1;"
                         :: "r"(mbf + s * 8), "r"(1u) : "memory");
        }
    }
    __syncthreads();
    u32 tmem; asm volatile("ld.shared.b32 %0,[%1];" : "=r"(tmem) : "r"(tptr));

    const u64 DBASE = (2ull << 61) | (1ull << 46) | (64ull << 32) | (1ull << 16);
    const u32 IDESC = (1u << 4) | (32u << 17) | (8u << 24);

    // producer-private parity trackers (live across tiles; counts stay exact)
    int pf0 = 0, pf1 = 0, pf2 = 0;   // TMA-full barriers
    int pc0 = 0, pc1 = 0, pc2 = 0;   // commit barriers

#pragma unroll 1
    for (int t = blockIdx.x; t < 512; t += gridDim.x) {
        const int mBase = (t >> 4) * 256, nBase = (t & 15) * 256;
        const u64 mt0 = (u64)((t >> 4) * 2) * 64;
        const u64 nt0 = (u64)((t & 15) * 2) * 64;

        if (wid == 0) {
            u32 ep;
            asm volatile("{ .reg .pred p; elect.sync _|p, 0xFFFFFFFF; selp.b32 %0,1,0,p; }"
                         : "=r"(ep));
            if (ep) {
#pragma unroll
                for (int p = 0; p < 2; p++) {
                    u32 sl = st0 + p * 65536;
                    EXPECT_TX(mbf + p * 8, 65536u);
                    BULK(sl,          X + (mt0 + p) * 16384ull,        16384u, mbf + p * 8);
                    BULK(sl + 16384,  X + (mt0 + 64 + p) * 16384ull,   16384u, mbf + p * 8);
                    BULK(sl + 32768,  W + (nt0 + p) * 16384ull,        16384u, mbf + p * 8);
                    BULK(sl + 49152,  W + (nt0 + 64 + p) * 16384ull,   16384u, mbf + p * 8);
                }
#pragma unroll 1
                for (int kt = 0; kt < 64; kt++) {
                    const int kdiv = kt / 3;
                    const int s = kt - kdiv * 3;
                    const u32 sA0 = st0 + s * 65536, sA1 = sA0 + 16384, sB = sA0 + 32768;
                    // wait TMA-full for this slot (toggle exact parity)
                    u32 ph;
                    if (s == 0) { ph = (u32)pf0; pf0 ^= 1; }
                    else if (s == 1) { ph = (u32)pf1; pf1 ^= 1; }
                    else { ph = (u32)pf2; pf2 ^= 1; }
                    MWAIT(mbf + s * 8, ph);

                    u64 a0 = DBASE | ((u64)(sA0 >> 4) & 0x3FFF);
                    u64 a1 = DBASE | ((u64)(sA1 >> 4) & 0x3FFF);
                    u64 bd = DBASE | ((u64)(sB >> 4) & 0x3FFF);
#pragma unroll
                    for (int q = 0; q < 4; q++) {
                        u32 en = (kt > 0 || q > 0) ? 1u : 0u;
                        MMA8(tmem, a0 + q * 2, a1 + q * 2, bd + q * 2, IDESC, en);
                    }
                    asm volatile("tcgen05.commit.cta_group::1.mbarrier::arrive::one.shared::cluster.b64 [%0];"
                                 :: "r"(mbc + s * 8) : "memory");

                    // unconditionally consume the commit phase of kt-1
                    if (kt >= 1) {
                        const int sp = (kt - 1) - ((kt - 1) / 3) * 3;
                        u32 p2;
                        if (sp == 0) { p2 = (u32)pc0; pc0 ^= 1; }
                        else if (sp == 1) { p2 = (u32)pc1; pc1 ^= 1; }
                        else { p2 = (u32)pc2; pc2 ^= 1; }
                        MWAIT(mbc + sp * 8, p2);
                    }

                    if (kt + 2 < 64) {
                        const int sd = (kt + 2) - ((kt + 2) / 3) * 3;
                        const u32 dA0 = st0 + sd * 65536;
                        const u64 kk = (u64)(kt + 2);
                        EXPECT_TX(mbf + sd * 8, 65536u);
                        BULK(dA0,          X + (mt0 + kk) * 16384ull,      16384u, mbf + sd * 8);
                        BULK(dA0 + 16384,  X + (mt0 + 64 + kk) * 16384ull, 16384u, mbf + sd * 8);
                        BULK(dA0 + 32768,  W + (nt0 + kk) * 16384ull,      16384u, mbf + sd * 8);
                        BULK(dA0 + 49152,  W + (nt0 + 64 + kk) * 16384ull, 16384u, mbf + sd * 8);
                    }
                }
                // final drain: consume the commit phase of kt=63 (slot 0)
                { u32 p2 = (u32)pc0; pc0 ^= 1; MWAIT(mbc, p2); }
            }
        }

        // producer has verified all MMAs complete; release everyone
        __syncthreads();
        asm volatile("tcgen05.fence::after_thread_sync;" ::: "memory");

        {
            const int half = wid >> 2, wr = wid & 3;
            float* dst = out + (u64)(mBase + half * 128 + wr * 32 + lid) * 4096 + nBase;
            const u32 tm = tmem + half * 256;
#pragma unroll
            for (int ch = 0; ch < 8; ch++) {
                u32 rr[32];
                LDTM32(rr, tm + ch * 32);
                asm volatile("tcgen05.wait::ld.sync.aligned;" ::: "memory");
#pragma unroll
                for (int j = 0; j < 8; j++)
                    asm volatile("st.global.cs.v4.b32 [%0], {%1,%2,%3,%4};"
                                 :: "l"(dst + ch * 32 + j * 4),
                                    "r"(rr[4 * j]), "r"(rr[4 * j + 1]),
                                    "r"(rr[4 * j + 2]), "r"(rr[4 * j + 3]) : "memory");
            }
            asm volatile("tcgen05.fence::before_thread_sync;" ::: "memory");
        }
        __syncthreads();   // epilogue done before next tile's MMAs write TMEM
    }

    __syncthreads();
    if (wid == 0) {
        asm volatile("tcgen05.relinquish_alloc_permit.cta_group::1.sync.aligned;");
        asm volatile("tcgen05.dealloc.cta_group::1.sync.aligned.b32 %0, %1;"
                     :: "r"(tmem), "r"(512u));
    }
}

// ---------------- wbuild: fused LoRA GEMM + NF4 dequant (row-major or tiled) ------
extern "C" __global__ void __launch_bounds__(256, 1)
wbuild(const int* __restrict__ qw, const float* __restrict__ am,
       const u16* __restrict__ lb, const u16* __restrict__ lat,
       u16* __restrict__ w, int tiled) {
    extern __shared__ char sm[];
    u32 base = (sm2u32(sm) + 1023) & ~1023u;
    const u32 tptr = base;
    const u32 mb = base + 16;
    const u32 sa = base + 1024;
    const u32 sb = sa + 16384;
    const int tid = threadIdx.x, wid = tid >> 5, lid = tid & 31;
    const int ti = blockIdx.x;
    const int o0 = (ti >> 4) * 128, i0 = (ti & 15) * 256;

    if (wid == 0)
        asm volatile("tcgen05.alloc.cta_group::1.sync.aligned.shared::cta.b32 [%0], %1;"
                     :: "r"(tptr), "r"(256u) : "memory");
    if (tid == 0)
        asm volatile("mbarrier.init.shared.b64 [%0], %1;" :: "r"(mb), "r"(1u) : "memory");
    __syncthreads();
    u32 tmem; asm volatile("ld.shared.b32 %0,[%1];" : "=r"(tmem) : "r"(tptr));

#pragma unroll
    for (int r = 0; r < 4; r++) {
        int i = tid + r * 256; int row = i >> 3, c = i & 7;
        u32 off = (u32)(row * 128 + ((c * 16) ^ ((row & 7) << 4)));
        asm volatile("cp.async.cg.shared.global [%0], [%1], 16;"
                     :: "r"(sa + off), "l"((const char*)lb + (u64)(o0 + row) * 128 + c * 16));
    }
#pragma unroll
    for (int r = 0; r < 8; r++) {
        int i = tid + r * 256; int row = i >> 3, c = i & 7;
        u32 off = (u32)(row * 128 + ((c * 16) ^ ((row & 7) << 4)));
        asm volatile("cp.async.cg.shared.global [%0], [%1], 16;"
                     :: "r"(sb + off), "l"((const char*)lat + (u64)(i0 + row) * 128 + c * 16));
    }
    asm volatile("cp.async.commit_group;" ::: "memory");
    asm volatile("cp.async.wait_group 0;" ::: "memory");
    __syncthreads();

    const u64 DBASE = (2ull << 61) | (1ull << 46) | (64ull << 32) | (1ull << 16);
    const u32 IDESC = (1u << 4) | (32u << 17) | (8u << 24);

    if (wid == 0) {
        u32 ep;
        asm volatile("{ .reg .pred p; elect.sync _|p, 0xFFFFFFFF; selp.b32 %0,1,0,p; }"
                     : "=r"(ep));
        if (ep) {
            asm volatile("fence.proxy.async.shared::cta;" ::: "memory");
            u64 ad = DBASE | ((u64)(sa >> 4) & 0x3FFF);
            u64 bd = DBASE | ((u64)(sb >> 4) & 0x3FFF);
#pragma unroll
            for (int q = 0; q < 4; q++) {
                u32 en = (q > 0) ? 1u : 0u;
                asm volatile("{ .reg .pred p; setp.ne.u32 p, %5, 0; "
                    "tcgen05.mma.cta_group::1.kind::f16 [%0], %1, %2, %3, {%4,%4,%4,%4}, p; }"
                    :: "r"(tmem), "l"(ad + q * 2), "l"(bd + q * 2),
                       "r"(IDESC), "r"(0u), "r"(en) : "memory");
            }
            asm volatile("tcgen05.commit.cta_group::1.mbarrier::arrive::one.shared::cluster.b64 [%0];"
                         :: "r"(mb) : "memory");
        }
    }
    __syncthreads();
    MWAIT(mb, 0u);
    asm volatile("tcgen05.fence::after_thread_sync;" ::: "memory");

    const int half = wid >> 2, wr = wid & 3;
    const int o = o0 + wr * 32 + lid;
#pragma unroll
    for (int c4 = 0; c4 < 4; c4++) {
        u32 rr[32];
        LDTM32(rr, tmem + half * 128 + c4 * 32);
        asm volatile("tcgen05.wait::ld.sync.aligned;" ::: "memory");
        const int ib = i0 + half * 128 + c4 * 32;
        const u64 k = (u64)o * 4096 + (u64)ib;
        const float a = am[k >> 6];
        const int4* qp = (const int4*)qw + (k >> 3);
        u32 ov[16];
#pragma unroll
        for (int u = 0; u < 4; u++) {
            int4 qv = qp[u];
            int e[8] = {qv.x & 15, (qv.x >> 4) & 15, qv.y & 15, (qv.y >> 4) & 15,
                        qv.z & 15, (qv.z >> 4) & 15, qv.w & 15, (qv.w >> 4) & 15};
#pragma unroll
            for (int j = 0; j < 4; j++) {
                union { u32 u_; float f_; } c0, c1;
                c0.u_ = rr[u * 8 + 2 * j];
                c1.u_ = rr[u * 8 + 2 * j + 1];
                float w0 = NF4D[e[2 * j]] * a + c0.f_;
                float w1 = NF4D[e[2 * j + 1]] * a + c1.f_;
                asm("cvt.rn.f16x2.f32 %0, %1, %2;" : "=r"(ov[u * 4 + j]) : "f"(w1), "f"(w0));
            }
        }
        if (!tiled) {
            char* wp = (char*)w + k * 2;
#pragma unroll
            for (int j = 0; j < 4; j++)
                asm volatile("st.global.cs.v4.b32 [%0], {%1,%2,%3,%4};"
                             :: "l"(wp + j * 16), "r"(ov[4 * j]), "r"(ov[4 * j + 1]),
                                "r"(ov[4 * j + 2]), "r"(ov[4 * j + 3]) : "memory");
        } else {
            const u64 tbase = ((u64)((o >> 7) * 64 + (ib >> 6))) * 16384ull;
            const u32 rowoff = (u32)((o & 127) * 128 + (ib & 63) * 2);
#pragma unroll
            for (int j = 0; j < 4; j++) {
                u32 off = rowoff + (u32)(j * 16);
                off = off ^ ((off >> 3) & 0x70);
                asm volatile("st.global.cs.v4.b32 [%0], {%1,%2,%3,%4};"
                             :: "l"((char*)w + tbase + off),
                                "r"(ov[4 * j]), "r"(ov[4 * j + 1]),
                                "r"(ov[4 * j + 2]), "r"(ov[4 * j + 3]) : "memory");
            }
        }
    }
    asm volatile("tcgen05.fence::before_thread_sync;" ::: "memory");
    __syncthreads();
    if (wid == 0) {
        asm volatile("tcgen05.relinquish_alloc_permit.cta_group::1.sync.aligned;");
        asm volatile("tcgen05.dealloc.cta_group::1.sync.aligned.b32 %0, %1;"
                     :: "r"(tmem), "r"(256u));
    }
}
)NVSRC";

// --- driver/nvrtc plumbing ---
typedef int (*nvrtcCreateProgram_t)(void**, const char*, const char*, int,
                                    const char* const*, const char* const*);
typedef int (*nvrtcCompileProgram_t)(void*, int, const char* const*);
typedef int (*nvrtcGetCUBINSize_t)(void*, size_t*);
typedef int (*nvrtcGetCUBIN_t)(void*, char*);
typedef int (*cuInit_t)(unsigned);
typedef int (*cuDevicePrimaryCtxRetain_t)(void**, int);
typedef int (*cuCtxSetCurrent_t)(void*);
typedef int (*cuModuleLoadDataEx_t)(void**, const void*, unsigned, int*, void**);
typedef int (*cuModuleGetFunction_t)(void**, void*, const char*);
typedef int (*cuModuleGetGlobal_t)(unsigned long long*, size_t*, void*, const char*);
typedef int (*cuFuncSetAttribute_t)(void*, int, int);
typedef int (*cuLaunchKernel_t)(void*, unsigned, unsigned, unsigned,
                                unsigned, unsigned, unsigned,
                                unsigned, void*, void**, void**);
typedef int (*cuCtxSynchronize_t)(void);
typedef int (*cuMemcpyDtoH_t)(void*, unsigned long long, size_t);

#if defined(CUDA_API_PER_THREAD_DEFAULT_STREAM) || defined(__CUDA_API_PER_THREAD_DEFAULT_STREAM)
#define DRV_STREAM ((void*)0x2)
#else
#define DRV_STREAM ((void*)0x1)
#endif

static bool g_ok_gemm = false, g_ok_wb = false;
static int g_mode = 0;  // 4 = tiled bulk (gemm7), 1 = row-major (5c/5), 0 = host
static cuLaunchKernel_t p_cuLaunchKernel = nullptr;
static void* g_fn_gemm = nullptr;
static void* g_fn_wbuild = nullptr;
static unsigned long long g_gx = 0, g_gw = 0, g_glb = 0, g_glat = 0;
constexpr int SMEM5 = 198656;
constexpr int SMEMW = 51200;

static float h2f(uint16_t h) {
    uint32_t s = (h >> 15) & 1, e = (h >> 10) & 31, m = h & 1023;
    uint32_t f;
    if (e == 0) {
        if (m == 0) f = s << 31;
        else {
            e = 127 - 15 + 1;
            while (!(m & 1024)) { m <<= 1; e--; }
            m &= 1023;
            f = (s << 31) | (e << 23) | (m << 13);
        }
    } else if (e == 31) f = (s << 31) | 0x7F800000 | (m << 13);
    else f = (s << 31) | ((e - 15 + 127) << 23) | (m << 13);
    float r; memcpy(&r, &f, 4); return r;
}

static bool try_init_tcgen05() {
    void* hcu = dlopen("libcuda.so.1", RTLD_NOW | RTLD_GLOBAL);
    if (!hcu) hcu = dlopen("libcuda.so", RTLD_NOW | RTLD_GLOBAL);
    if (!hcu) return false;
    void* hnv = dlopen("libnvrtc.so.13", RTLD_NOW | RTLD_GLOBAL);
    if (!hnv) hnv = dlopen("libnvrtc.so", RTLD_NOW | RTLD_GLOBAL);
    if (!hnv) hnv = dlopen("libnvrtc.so.12", RTLD_NOW | RTLD_GLOBAL);
    if (!hnv) return false;

    auto nCreate  = (nvrtcCreateProgram_t)dlsym(hnv, "nvrtcCreateProgram");
    auto nCompile = (nvrtcCompileProgram_t)dlsym(hnv, "nvrtcCompileProgram");
    auto nCbSize  = (nvrtcGetCUBINSize_t)dlsym(hnv, "nvrtcGetCUBINSize");
    auto nCb      = (nvrtcGetCUBIN_t)dlsym(hnv, "nvrtcGetCUBIN");
    auto cInit    = (cuInit_t)dlsym(hcu, "cuInit");
    auto cRetain  = (cuDevicePrimaryCtxRetain_t)dlsym(hcu, "cuDevicePrimaryCtxRetain");
    auto cSetCur  = (cuCtxSetCurrent_t)dlsym(hcu, "cuCtxSetCurrent");
    auto cModLoad = (cuModuleLoadDataEx_t)dlsym(hcu, "cuModuleLoadDataEx");
    auto cGetFn   = (cuModuleGetFunction_t)dlsym(hcu, "cuModuleGetFunction");
    auto cGetGlb  = (cuModuleGetGlobal_t)dlsym(hcu, "cuModuleGetGlobal_v2");
    auto cSetAttr = (cuFuncSetAttribute_t)dlsym(hcu, "cuFuncSetAttribute");
    auto cLaunch  = (cuLaunchKernel_t)dlsym(hcu, "cuLaunchKernel");
    auto cSync    = (cuCtxSynchronize_t)dlsym(hcu, "cuCtxSynchronize");
    auto cD2H     = (cuMemcpyDtoH_t)dlsym(hcu, "cuMemcpyDtoH_v2");
    if (!nCreate || !nCompile || !nCbSize || !nCb || !cInit || !cRetain ||
        !cSetCur || !cModLoad || !cGetFn || !cGetGlb || !cSetAttr ||
        !cLaunch || !cSync || !cD2H)
        return false;

    if (cInit(0)) return false;
    void* ctx = nullptr;
    if (cRetain(&ctx, 0)) return false;
    if (cSetCur(ctx)) return false;

    void* prog = nullptr;
    if (nCreate(&prog, NVRTC_SRC, "gemm7.cu", 0, nullptr, nullptr)) return false;
    const char* opts[] = {"--gpu-architecture=sm_103a"};
    if (nCompile(prog, 1, opts)) return false;
    size_t cbsz = 0;
    if (nCbSize(prog, &cbsz) || cbsz == 0) return false;
    static char* cubin = new char[cbsz];
    if (nCb(prog, cubin)) return false;

    void* mod = nullptr;
    if (cModLoad(&mod, cubin, 0, nullptr, nullptr)) return false;
    void *fG5 = nullptr, *fG5c = nullptr, *fG7 = nullptr;
    void *fInit = nullptr, *fInit7 = nullptr, *fWb = nullptr, *fWti = nullptr;
    if (cGetFn(&fG5, mod, "gemm5")) return false;
    if (cGetFn(&fG5c, mod, "gemm5c")) return false;
    if (cGetFn(&fG7, mod, "gemm7")) return false;
    if (cGetFn(&fInit, mod, "initt")) return false;
    if (cGetFn(&fInit7, mod, "init7")) return false;
    if (cGetFn(&fWb, mod, "wbuild")) return false;
    if (cGetFn(&fWti, mod, "wtinit")) return false;
    unsigned long long gx = 0, gw = 0, gout = 0, glb = 0, glat = 0,
                       gtqw = 0, gtam = 0;
    size_t sz;
    if (cGetGlb(&gx, &sz, mod, "GX")) return false;
    if (cGetGlb(&gw, &sz, mod, "GW")) return false;
    if (cGetGlb(&gout, &sz, mod, "GOUT")) return false;
    if (cGetGlb(&glb, &sz, mod, "GLB")) return false;
    if (cGetGlb(&glat, &sz, mod, "GLAT")) return false;
    if (cGetGlb(&gtqw, &sz, mod, "GTQW")) return false;
    if (cGetGlb(&gtam, &sz, mod, "GTAM")) return false;
    if (cSetAttr(fG5, 8, SMEM5)) return false;
    if (cSetAttr(fG5c, 8, SMEM5)) return false;
    if (cSetAttr(fG7, 8, SMEM5)) return false;
    if (cSetAttr(fWb, 8, SMEMW)) return false;

    p_cuLaunchKernel = cLaunch;
    g_gx = gx; g_gw = gw; g_glb = glb; g_glat = glat;

    static float row[OUT_F];
    const int ms[4] = {0, 97, 4095, 8191};
    auto check_out = [&](unsigned long long gout_) -> bool {
        for (int ri = 0; ri < 4; ri++) {
            int m = ms[ri];
            if (cD2H(row, gout_ + (unsigned long long)m * OUT_F * 4, OUT_F * 4))
                return false;
            for (int n = 0; n < OUT_F; n++) {
                float ref = 0.0f;
                for (int k = 0; k < IN_F; k++) {
                    int av = (k * 131 + m * 7) % 9 - 4;
                    int bv = (k * 17 + n * 3) % 7 - 3;
                    ref += (av * 0.25f) * (bv * 0.25f);
                }
                if (fabsf(row[n] - ref) > 0.01f) return false;
            }
        }
        return true;
    };

    // ---- TEST 1: gemm7 (tiled integer grid) — independent of wbuild ----
    bool g7ok = false;
    if (cLaunch(fInit7, 131072, 1, 1, 256, 1, 1, 0, DRV_STREAM, nullptr, nullptr) == 0 &&
        cSync() == 0) {
        unsigned long long px = gx, pw = gw, po = gout;
        void* args[3] = {&px, &pw, &po};
        if (cLaunch(fG7, 148, 1, 1, 256, 1, 1, SMEM5, DRV_STREAM, args, nullptr) == 0 &&
            cSync() == 0 && check_out(gout))
            g7ok = true;
    }

    // ---- TEST 2: wbuild math (row-major) + tiled layout ----
    bool wb_math_ok = false, wb_tiled_ok = false;
    {
        if (cLaunch(fWti, 32768, 1, 1, 256, 1, 1, 0, DRV_STREAM, nullptr, nullptr) == 0 &&
            cSync() == 0) {
            auto wref = [&](int o, int i) -> float {
                uint64_t k = (uint64_t)o * 4096 + i;
                int qv = (int)(((k >> 1) * 37ull) & 255ull);
                int nib = (k & 1) ? (qv >> 4) & 15 : qv & 15;
                float a = (float)(((uint32_t)((k >> 6) * 13ull)) % 31u + 1u) * 0.03125f;
                float lora = 0.0f;
                for (int r = 0; r < 64; r++) {
                    float lb = (float)((int)(((uint32_t)o * 3u + r * 7u) % 17u) - 8) * 0.015625f;
                    float la = (float)((int)(((uint32_t)i * 5u + r * 11u) % 19u) - 9) * 0.015625f;
                    lora += lb * la;
                }
                return NF4H[nib] * a + lora;
            };
            auto run_wb = [&](int tiled) -> bool {
                unsigned long long pq = gtqw, pa = gtam, pl = glb, pt = glat, pw2 = gw;
                int tf = tiled;
                void* args[6] = {&pq, &pa, &pl, &pt, &pw2, &tf};
                if (cLaunch(fWb, 512, 1, 1, 256, 1, 1, SMEMW, DRV_STREAM, args, nullptr))
                    return false;
                return cSync() == 0;
            };
            const int os[4] = {0, 1, 255, 4095};
            static uint16_t wrow[IN_F];
            if (run_wb(0)) {
                bool ok = true;
                for (int oi = 0; oi < 4 && ok; oi++) {
                    int o = os[oi];
                    if (cD2H(wrow, gw + (unsigned long long)o * IN_F * 2, IN_F * 2)) { ok = false; break; }
                    for (int i = 0; i < IN_F; i++)
                        if (fabsf(h2f(wrow[i]) - wref(o, i)) > 0.01f) { ok = false; break; }
                }
                wb_math_ok = ok;
            }
            if (wb_math_ok && g7ok && run_wb(1)) {
                static uint16_t* hw = new uint16_t[16777216];
                if (cD2H(hw, gw, (size_t)16777216 * 2) == 0) {
                    bool ok = true;
                    for (int oi = 0; oi < 4 && ok; oi++) {
                        int o = os[oi];
                        for (int i = 0; i < IN_F; i++) {
                            uint32_t off = (uint32_t)((o & 127) * 128 + (i & 63) * 2);
                            off = off ^ ((off >> 3) & 0x70);
                            uint64_t boff = ((uint64_t)((o >> 7) * 64 + (i >> 6))) * 16384ull + off;
                            if (fabsf(h2f(hw[boff >> 1]) - wref(o, i)) > 0.01f) { ok = false; break; }
                        }
                    }
                    wb_tiled_ok = ok;
                }
            }
        }
    }

    // ---- mode selection ----
    if (g7ok && wb_tiled_ok) {
        g_fn_gemm = fG7; g_ok_gemm = true; g_mode = 4;
        g_fn_wbuild = fWb; g_ok_wb = true;
        return true;
    }
    // row-major ladder
    if (cLaunch(fInit, 131072, 1, 1, 256, 1, 1, 0, DRV_STREAM, nullptr, nullptr) ||
        cSync())
        return false;
    {
        unsigned long long px = gx, pw = gw, po = gout;
        void* args[3] = {&px, &pw, &po};
        if (cLaunch(fG5c, 148, 1, 1, 256, 1, 1, SMEM5, DRV_STREAM, args, nullptr) == 0 &&
            cSync() == 0 && check_out(gout)) {
            g_fn_gemm = fG5c; g_ok_gemm = true; g_mode = 1;
        } else if (cLaunch(fG5, 148, 1, 1, 256, 1, 1, SMEM5, DRV_STREAM, args, nullptr) == 0 &&
                   cSync() == 0 && check_out(gout)) {
            g_fn_gemm = fG5; g_ok_gemm = true; g_mode = 1;
        }
    }
    if (g_ok_gemm && wb_math_ok) { g_fn_wbuild = fWb; g_ok_wb = true; }
    return g_ok_gemm;
}

__attribute__((constructor))
static void _init_drv() {
    try_init_tcgen05();
}

// ---------------------------------------------------------------------------
extern "C" void kernel_launch(void* const* d_in, const int* in_sizes, int n_in,
                              void* d_out, int out_size) {
    const float* x  = (const float*)d_in[0];
    const int*   qw = (const int*)d_in[1];
    const float* am = (const float*)d_in[2];
    const float* lA = (const float*)d_in[3];
    const float* lB = (const float*)d_in[4];
    float*       out = (float*)d_out;

    (void)in_sizes; (void)n_in; (void)out_size;

    if (g_ok_gemm) {
        __half* xh = (__half*)(uintptr_t)g_gx;
        __half* wh = (__half*)(uintptr_t)g_gw;

        if (g_mode == 4)
            convert_x_tiled_kernel<<<(M_ROWS * IN_F / 8) / 256, 256>>>(x, (char*)xh);
        else
            convert_x_kernel<<<(M_ROWS * IN_F / 8) / 256, 256>>>(x, xh);

        if (g_ok_wb) {
            cvt_lb_kernel<<<256, 256>>>(lB, (__half*)(uintptr_t)g_glb);
            cvt_lat_kernel<<<64, 256>>>(lA, (__half*)(uintptr_t)g_glat);
            unsigned long long pq = (unsigned long long)(uintptr_t)qw;
            unsigned long long pa = (unsigned long long)(uintptr_t)am;
            unsigned long long pl = g_glb, pt = g_glat, pw = g_gw;
            int tf = (g_mode == 4) ? 1 : 0;
            void* args[6] = {&pq, &pa, &pl, &pt, &pw, &tf};
            p_cuLaunchKernel(g_fn_wbuild, 512, 1, 1, 256, 1, 1, SMEMW,
                             DRV_STREAM, args, nullptr);
        } else {
            build_weff_kernel<<<dim3(IN_F / 128, OUT_F / 64), 256>>>(qw, am, lA, lB, wh);
        }

        unsigned long long px = g_gx, pw2 = g_gw;
        void* po = (void*)out;
        void* args[3] = {&px, &pw2, &po};
        p_cuLaunchKernel(g_fn_gemm, 148, 1, 1, 256, 1, 1, SMEM5,
                         DRV_STREAM, args, nullptr);
    } else {
        __half* xh; __half* wh;
        cudaGetSymbolAddress((void**)&xh, g_Xh);
        cudaGetSymbolAddress((void**)&wh, g_Wh);
        convert_x_kernel<<<(M_ROWS * IN_F / 8) / 256, 256>>>(x, xh);
        build_weff_kernel<<<dim3(IN_F / 128, OUT_F / 64), 256>>>(qw, am, lA, lB, wh);
        cudaFuncSetAttribute(gemm_f16_kernel,
                             cudaFuncAttributeMaxDynamicSharedMemorySize, SMEM_TOTAL);
        gemm_f16_kernel<<<148, 512, SMEM_TOTAL>>>(xh, wh, out);
    }
}